// round 2
// baseline (speedup 1.0000x reference)
#include <cuda_runtime.h>
#include <cuda_bf16.h>
#include <mma.h>
#include <math.h>

using namespace nvcuda;
typedef __nv_bfloat16 bf16;

#define Bdim 256
#define Tdim 256
#define Ddim 128
#define Hdim 1024
#define Odim 64
#define BT (Bdim*Tdim)
#define DK (Ddim*Hdim)

// ---------------- scratch (device globals; allocations forbidden) ----------
__device__ float g_pre_z[67108864];          // [BT, H] fp32
__device__ float g_pre_r[67108864];
__device__ float g_pre_h[67108864];
__device__ float g_gamma[67108864];
__device__ float g_hs[Bdim*Hdim];            // gamma-scaled hidden state (fp32)
__device__ float g_h [Bdim*Hdim];            // post-update hidden state
__device__ float g_z [Bdim*Hdim];            // z gate

// bf16 hi/lo split operands
__device__ bf16 g_hs_hi[Bdim*Hdim], g_hs_lo[Bdim*Hdim];
__device__ bf16 g_rh_hi[Bdim*Hdim], g_rh_lo[Bdim*Hdim];
__device__ bf16 g_x_hi[BT*Ddim],   g_x_lo[BT*Ddim];
__device__ bf16 g_mb [BT*Ddim];              // m   (exact in bf16)
__device__ bf16 g_mib[BT*Ddim];              // 1-m (exact in bf16)

// split weights
__device__ bf16 g_Uzr_hi[1024*2048], g_Uzr_lo[1024*2048];   // [k=1024][n: Uz|Ur]
__device__ bf16 g_U_hi[1024*1024],   g_U_lo[1024*1024];
// small weights, slots: 0=Wz 1=Vz 2=Wr 3=Vr 4=Wh 5=Vh 6=Wgh, each [128][1024]
__device__ bf16 g_Wsm_hi[7*DK], g_Wsm_lo[7*DK];

__device__ __forceinline__ void split2(float v, bf16& hi, bf16& lo) {
    hi = __float2bfloat16(v);
    lo = __float2bfloat16(v - __bfloat162float(hi));
}

// ---------------- elementwise: input decay + operand prep ------------------
__global__ void k_xmod(const float* __restrict__ x, const float* __restrict__ delta,
                       const float* __restrict__ m, const float* __restrict__ wgx,
                       const float* __restrict__ bgx) {
    int i = blockIdx.x*blockDim.x + threadIdx.x;
    if (i >= BT*Ddim) return;
    int d = i & (Ddim-1);
    float mv = m[i];
    float dec = delta[i]*wgx[d] + bgx[d];
    float xv = (mv > 0.0f) ? (1.0f - dec)*0.001f : x[i];
    split2(xv, g_x_hi[i], g_x_lo[i]);
    g_mb[i]  = __float2bfloat16(mv);
    g_mib[i] = __float2bfloat16(1.0f - mv);
}

// ---------------- weight splitting -----------------------------------------
__global__ void k_split_small(const float* __restrict__ src, int slot) {
    int i = blockIdx.x*blockDim.x + threadIdx.x;
    if (i >= DK) return;
    split2(src[i], g_Wsm_hi[(size_t)slot*DK + i], g_Wsm_lo[(size_t)slot*DK + i]);
}
__global__ void k_split_U(const float* __restrict__ U) {
    int i = blockIdx.x*blockDim.x + threadIdx.x;
    if (i >= 1024*1024) return;
    split2(U[i], g_U_hi[i], g_U_lo[i]);
}
__global__ void k_split_uzr(const float* __restrict__ Uz, const float* __restrict__ Ur) {
    int i = blockIdx.x*blockDim.x + threadIdx.x;
    if (i >= 1024*2048) return;
    int k = i >> 11, n = i & 2047;
    float v = (n < 1024) ? Uz[k*1024 + n] : Ur[k*1024 + n - 1024];
    split2(v, g_Uzr_hi[i], g_Uzr_lo[i]);
}

// ---------------- precompute GEMMs (tensor cores) ---------------------------
// which: 0=pre_z 1=pre_r 2=pre_h (x@W + (1-m)@V + bias), 3=gamma (exp(-relu(m@Wg+bg)))
__global__ void k_pre(const float* __restrict__ pbz, const float* __restrict__ pbr,
                      const float* __restrict__ pbh, const float* __restrict__ pbg)
{
    int which = blockIdx.z;
    int nb = blockIdx.x, mb = blockIdx.y;
    int wid = threadIdx.x >> 5;
    int r0 = mb*64, c0 = nb*64;
    __shared__ float cs[64*64];

    wmma::fragment<wmma::accumulator,16,16,16,float> acc[4];
    #pragma unroll
    for (int f = 0; f < 4; f++) wmma::fill_fragment(acc[f], 0.0f);

    const bf16 *Wh_p, *Wl_p, *Vh_p = nullptr, *Vl_p = nullptr;
    if (which < 3) {
        Wh_p = g_Wsm_hi + (size_t)(which*2)*DK;
        Wl_p = g_Wsm_lo + (size_t)(which*2)*DK;
        Vh_p = g_Wsm_hi + (size_t)(which*2+1)*DK;
        Vl_p = g_Wsm_lo + (size_t)(which*2+1)*DK;
    } else {
        Wh_p = g_Wsm_hi + (size_t)6*DK;
        Wl_p = g_Wsm_lo + (size_t)6*DK;
    }

    int arow = r0 + wid*16;
    for (int kk = 0; kk < Ddim; kk += 16) {
        wmma::fragment<wmma::matrix_a,16,16,16,bf16,wmma::row_major> ah, al, am;
        if (which < 3) {
            wmma::load_matrix_sync(ah, g_x_hi + (size_t)arow*Ddim + kk, Ddim);
            wmma::load_matrix_sync(al, g_x_lo + (size_t)arow*Ddim + kk, Ddim);
            wmma::load_matrix_sync(am, g_mib + (size_t)arow*Ddim + kk, Ddim);
        } else {
            wmma::load_matrix_sync(am, g_mb + (size_t)arow*Ddim + kk, Ddim);
        }
        #pragma unroll
        for (int f = 0; f < 4; f++) {
            int cc = c0 + f*16;
            wmma::fragment<wmma::matrix_b,16,16,16,bf16,wmma::row_major> bh_, bl_;
            wmma::load_matrix_sync(bh_, Wh_p + (size_t)kk*Hdim + cc, Hdim);
            wmma::load_matrix_sync(bl_, Wl_p + (size_t)kk*Hdim + cc, Hdim);
            if (which < 3) {
                wmma::mma_sync(acc[f], ah, bh_, acc[f]);
                wmma::mma_sync(acc[f], ah, bl_, acc[f]);
                wmma::mma_sync(acc[f], al, bh_, acc[f]);
                wmma::fragment<wmma::matrix_b,16,16,16,bf16,wmma::row_major> vh_, vl_;
                wmma::load_matrix_sync(vh_, Vh_p + (size_t)kk*Hdim + cc, Hdim);
                wmma::load_matrix_sync(vl_, Vl_p + (size_t)kk*Hdim + cc, Hdim);
                wmma::mma_sync(acc[f], am, vh_, acc[f]);
                wmma::mma_sync(acc[f], am, vl_, acc[f]);
            } else {
                wmma::mma_sync(acc[f], am, bh_, acc[f]);
                wmma::mma_sync(acc[f], am, bl_, acc[f]);
            }
        }
    }
    #pragma unroll
    for (int f = 0; f < 4; f++)
        wmma::store_matrix_sync(cs + (wid*16)*64 + f*16, acc[f], 64, wmma::mem_row_major);
    __syncthreads();

    const float* bias = (which==0)?pbz : (which==1)?pbr : (which==2)?pbh : pbg;
    float* out = (which==0)?g_pre_z : (which==1)?g_pre_r : (which==2)?g_pre_h : g_gamma;
    for (int i = threadIdx.x; i < 64*64; i += blockDim.x) {
        int rr = i >> 6, cj = i & 63;
        float v = cs[i] + bias[c0 + cj];
        if (which == 3) v = expf(-fmaxf(0.0f, v));
        out[(size_t)(r0+rr)*Hdim + c0 + cj] = v;
    }
}

__global__ void k_init() {
    int i = blockIdx.x*blockDim.x + threadIdx.x;
    if (i < Bdim*Hdim) {
        g_hs[i] = 0.0f; g_h[i] = 0.0f;
        g_hs_hi[i] = __float2bfloat16(0.0f);
        g_hs_lo[i] = __float2bfloat16(0.0f);
    }
}

// ---------------- scan phase A: [256,2048] = hs @ [Uz|Ur] -------------------
__global__ void k_scanA(int t)
{
    int nb = blockIdx.x;           // 0..31 → global col block
    int mb = blockIdx.y;           // 0..3
    int wid = threadIdx.x >> 5;
    int r0 = mb*64, c0 = nb*64;
    __shared__ float cs[64*64];

    wmma::fragment<wmma::accumulator,16,16,16,float> acc[4];
    #pragma unroll
    for (int f = 0; f < 4; f++) wmma::fill_fragment(acc[f], 0.0f);

    int arow = r0 + wid*16;
    for (int kk = 0; kk < Hdim; kk += 16) {
        wmma::fragment<wmma::matrix_a,16,16,16,bf16,wmma::row_major> ah, al;
        wmma::load_matrix_sync(ah, g_hs_hi + (size_t)arow*Hdim + kk, Hdim);
        wmma::load_matrix_sync(al, g_hs_lo + (size_t)arow*Hdim + kk, Hdim);
        #pragma unroll
        for (int f = 0; f < 4; f++) {
            int cc = c0 + f*16;
            wmma::fragment<wmma::matrix_b,16,16,16,bf16,wmma::row_major> bh_, bl_;
            wmma::load_matrix_sync(bh_, g_Uzr_hi + (size_t)kk*2048 + cc, 2048);
            wmma::load_matrix_sync(bl_, g_Uzr_lo + (size_t)kk*2048 + cc, 2048);
            wmma::mma_sync(acc[f], ah, bh_, acc[f]);
            wmma::mma_sync(acc[f], ah, bl_, acc[f]);
            wmma::mma_sync(acc[f], al, bh_, acc[f]);
        }
    }
    #pragma unroll
    for (int f = 0; f < 4; f++)
        wmma::store_matrix_sync(cs + (wid*16)*64 + f*16, acc[f], 64, wmma::mem_row_major);
    __syncthreads();

    bool is_z = (nb < 16);
    int cbase = is_z ? c0 : (c0 - 1024);
    const float* pre = is_z ? g_pre_z : g_pre_r;
    for (int i = threadIdx.x; i < 64*64; i += blockDim.x) {
        int rr = i >> 6, cj = i & 63;
        int b = r0 + rr, c = cbase + cj;
        float v = pre[((size_t)b*Tdim + t)*Hdim + c] + cs[i];
        float s = 1.0f/(1.0f + expf(-v));
        int idx = b*Hdim + c;
        if (is_z) {
            g_z[idx] = s;
        } else {
            float rh = s * g_hs[idx];
            split2(rh, g_rh_hi[idx], g_rh_lo[idx]);
        }
    }
}

// ---------------- scan phase B: [256,1024] = rh @ U + state update ----------
__global__ void k_scanB(int t)
{
    int nb = blockIdx.x;           // 0..15
    int mb = blockIdx.y;           // 0..3
    int wid = threadIdx.x >> 5;
    int r0 = mb*64, c0 = nb*64;
    __shared__ float cs[64*64];

    wmma::fragment<wmma::accumulator,16,16,16,float> acc[4];
    #pragma unroll
    for (int f = 0; f < 4; f++) wmma::fill_fragment(acc[f], 0.0f);

    int arow = r0 + wid*16;
    for (int kk = 0; kk < Hdim; kk += 16) {
        wmma::fragment<wmma::matrix_a,16,16,16,bf16,wmma::row_major> ah, al;
        wmma::load_matrix_sync(ah, g_rh_hi + (size_t)arow*Hdim + kk, Hdim);
        wmma::load_matrix_sync(al, g_rh_lo + (size_t)arow*Hdim + kk, Hdim);
        #pragma unroll
        for (int f = 0; f < 4; f++) {
            int cc = c0 + f*16;
            wmma::fragment<wmma::matrix_b,16,16,16,bf16,wmma::row_major> bh_, bl_;
            wmma::load_matrix_sync(bh_, g_U_hi + (size_t)kk*Hdim + cc, Hdim);
            wmma::load_matrix_sync(bl_, g_U_lo + (size_t)kk*Hdim + cc, Hdim);
            wmma::mma_sync(acc[f], ah, bh_, acc[f]);
            wmma::mma_sync(acc[f], ah, bl_, acc[f]);
            wmma::mma_sync(acc[f], al, bh_, acc[f]);
        }
    }
    #pragma unroll
    for (int f = 0; f < 4; f++)
        wmma::store_matrix_sync(cs + (wid*16)*64 + f*16, acc[f], 64, wmma::mem_row_major);
    __syncthreads();

    for (int i = threadIdx.x; i < 64*64; i += blockDim.x) {
        int rr = i >> 6, cj = i & 63;
        int b = r0 + rr, c = c0 + cj;
        int idx = b*Hdim + c;
        float ht = tanhf(g_pre_h[((size_t)b*Tdim + t)*Hdim + c] + cs[i]);
        float hs = g_hs[idx];
        float z  = g_z[idx];
        float hn = (1.0f - z)*hs + z*ht;
        g_h[idx] = hn;
        float gn = (t+1 < Tdim) ? g_gamma[((size_t)b*Tdim + (t+1))*Hdim + c] : 1.0f;
        float nhs = gn*hn;
        g_hs[idx] = nhs;
        split2(nhs, g_hs_hi[idx], g_hs_lo[idx]);
    }
}

// ---------------- decoder ---------------------------------------------------
__global__ void k_dec(const float* __restrict__ dW, const float* __restrict__ db,
                      float* __restrict__ out)
{
    __shared__ float hrow[Hdim];
    int b = blockIdx.x;
    for (int i = threadIdx.x; i < Hdim; i += blockDim.x)
        hrow[i] = g_h[b*Hdim + i];
    __syncthreads();
    int o = threadIdx.x;
    float acc = db[o];
    #pragma unroll 8
    for (int k = 0; k < Hdim; k++)
        acc += hrow[k]*dW[k*Odim + o];
    out[b*Odim + o] = acc;
}

// ---------------- launch ----------------------------------------------------
extern "C" void kernel_launch(void* const* d_in, const int* in_sizes, int n_in,
                              void* d_out, int out_size)
{
    const float* x     = (const float*)d_in[0];
    const float* delta = (const float*)d_in[1];
    const float* m     = (const float*)d_in[2];
    const float* W_r   = (const float*)d_in[3];
    const float* U_r   = (const float*)d_in[4];
    const float* V_r   = (const float*)d_in[5];
    const float* b_r   = (const float*)d_in[6];
    const float* W_z   = (const float*)d_in[7];
    const float* U_z   = (const float*)d_in[8];
    const float* V_z   = (const float*)d_in[9];
    const float* b_z   = (const float*)d_in[10];
    const float* W     = (const float*)d_in[11];
    const float* U     = (const float*)d_in[12];
    const float* V     = (const float*)d_in[13];
    const float* b     = (const float*)d_in[14];
    const float* Wgx   = (const float*)d_in[15];
    const float* bgx   = (const float*)d_in[16];
    const float* Wgh   = (const float*)d_in[17];
    const float* bgh   = (const float*)d_in[18];
    const float* decW  = (const float*)d_in[19];
    const float* decb  = (const float*)d_in[20];
    float* out = (float*)d_out;

    // operand prep
    k_xmod<<<(BT*Ddim + 255)/256, 256>>>(x, delta, m, Wgx, bgx);
    k_split_small<<<(DK+255)/256, 256>>>(W_z, 0);
    k_split_small<<<(DK+255)/256, 256>>>(V_z, 1);
    k_split_small<<<(DK+255)/256, 256>>>(W_r, 2);
    k_split_small<<<(DK+255)/256, 256>>>(V_r, 3);
    k_split_small<<<(DK+255)/256, 256>>>(W,   4);
    k_split_small<<<(DK+255)/256, 256>>>(V,   5);
    k_split_small<<<(DK+255)/256, 256>>>(Wgh, 6);
    k_split_U<<<(1024*1024 + 255)/256, 256>>>(U);
    k_split_uzr<<<(1024*2048 + 255)/256, 256>>>(U_z, U_r);

    // precompute pre_z / pre_r / pre_h / gamma
    k_pre<<<dim3(Hdim/64, BT/64, 4), 128>>>(b_z, b_r, b, bgh);

    k_init<<<(Bdim*Hdim + 255)/256, 256>>>();

    for (int t = 0; t < Tdim; t++) {
        k_scanA<<<dim3(32, Bdim/64), 128>>>(t);
        k_scanB<<<dim3(16, Bdim/64), 128>>>(t);
    }
    k_dec<<<Bdim, Odim>>>(decW, decb, out);
}

// round 3
// speedup vs baseline: 1.9953x; 1.9953x over previous
#include <cuda_runtime.h>
#include <cuda_bf16.h>
#include <mma.h>
#include <math.h>

using namespace nvcuda;
typedef __nv_bfloat16 bf16;

#define Bdim 256
#define Tdim 256
#define Ddim 128
#define Hdim 1024
#define Odim 64
#define BT (Bdim*Tdim)
#define DK (Ddim*Hdim)

// ---------------- scratch (device globals; allocations forbidden) ----------
__device__ float g_pre_z[67108864];          // [BT, H] fp32
__device__ float g_pre_r[67108864];
__device__ float g_pre_h[67108864];
__device__ float g_gamma[67108864];
__device__ float g_hs[Bdim*Hdim];            // gamma-scaled hidden state (fp32)
__device__ float g_h [Bdim*Hdim];            // post-update hidden state
__device__ float g_z [Bdim*Hdim];            // z gate

// bf16 hi/lo split operands
__device__ bf16 g_hs_hi[Bdim*Hdim], g_hs_lo[Bdim*Hdim];
__device__ bf16 g_rh_hi[Bdim*Hdim], g_rh_lo[Bdim*Hdim];
__device__ bf16 g_x_hi[BT*Ddim],   g_x_lo[BT*Ddim];
__device__ bf16 g_mb [BT*Ddim];              // m   (exact in bf16)
__device__ bf16 g_mib[BT*Ddim];              // 1-m (exact in bf16)

// split weights
__device__ bf16 g_Uzr_hi[1024*2048], g_Uzr_lo[1024*2048];   // [k=1024][n: Uz|Ur]
__device__ bf16 g_U_hi[1024*1024],   g_U_lo[1024*1024];
// small weights, slots: 0=Wz 1=Vz 2=Wr 3=Vr 4=Wh 5=Vh 6=Wgh, each [128][1024]
__device__ bf16 g_Wsm_hi[7*DK], g_Wsm_lo[7*DK];

__device__ __forceinline__ void split2(float v, bf16& hi, bf16& lo) {
    hi = __float2bfloat16(v);
    lo = __float2bfloat16(v - __bfloat162float(hi));
}

// ---------------- elementwise: input decay + operand prep ------------------
__global__ void k_xmod(const float* __restrict__ x, const float* __restrict__ delta,
                       const float* __restrict__ m, const float* __restrict__ wgx,
                       const float* __restrict__ bgx) {
    int i = blockIdx.x*blockDim.x + threadIdx.x;
    if (i >= BT*Ddim) return;
    int d = i & (Ddim-1);
    float mv = m[i];
    float dec = delta[i]*wgx[d] + bgx[d];
    float xv = (mv > 0.0f) ? (1.0f - dec)*0.001f : x[i];
    split2(xv, g_x_hi[i], g_x_lo[i]);
    g_mb[i]  = __float2bfloat16(mv);
    g_mib[i] = __float2bfloat16(1.0f - mv);
}

// ---------------- weight splitting -----------------------------------------
__global__ void k_split_small(const float* __restrict__ src, int slot) {
    int i = blockIdx.x*blockDim.x + threadIdx.x;
    if (i >= DK) return;
    split2(src[i], g_Wsm_hi[(size_t)slot*DK + i], g_Wsm_lo[(size_t)slot*DK + i]);
}
__global__ void k_split_U(const float* __restrict__ U) {
    int i = blockIdx.x*blockDim.x + threadIdx.x;
    if (i >= 1024*1024) return;
    split2(U[i], g_U_hi[i], g_U_lo[i]);
}
__global__ void k_split_uzr(const float* __restrict__ Uz, const float* __restrict__ Ur) {
    int i = blockIdx.x*blockDim.x + threadIdx.x;
    if (i >= 1024*2048) return;
    int k = i >> 11, n = i & 2047;
    float v = (n < 1024) ? Uz[k*1024 + n] : Ur[k*1024 + n - 1024];
    split2(v, g_Uzr_hi[i], g_Uzr_lo[i]);
}

__global__ void k_init() {
    int i = blockIdx.x*blockDim.x + threadIdx.x;
    if (i < Bdim*Hdim) {
        g_hs[i] = 0.0f; g_h[i] = 0.0f;
        g_hs_hi[i] = __float2bfloat16(0.0f);
        g_hs_lo[i] = __float2bfloat16(0.0f);
    }
}

// ============ precompute GEMMs (smem-staged wmma) ===========================
// which: 0=pre_z 1=pre_r 2=pre_h (x@W + (1-m)@V + bias), 3=gamma exp(-relu(m@Wg+bg))
__global__ void __launch_bounds__(128) k_pre(const float* __restrict__ pbz,
                                             const float* __restrict__ pbr,
                                             const float* __restrict__ pbh,
                                             const float* __restrict__ pbg)
{
    __shared__ __align__(16) char smem_raw[33792];
    bf16* sA0 = (bf16*)smem_raw;           // xh  (or mb for which=3)
    bf16* sA1 = sA0 + 64*40;               // xl
    bf16* sA2 = sA1 + 64*40;               // 1-m
    bf16* sB0 = sA2 + 64*40;               // Wh
    bf16* sB1 = sB0 + 32*72;               // Wl
    bf16* sB2 = sB1 + 32*72;               // Vh
    bf16* sB3 = sB2 + 32*72;               // Vl
    float* cs = (float*)smem_raw;

    const int which = blockIdx.z;
    const bool dual = (which < 3);
    const int tid = threadIdx.x;
    const int wid = tid >> 5;
    const int wr = wid >> 1, wc = wid & 1;
    const int r0 = blockIdx.y*64, c0 = blockIdx.x*64;

    const bf16 *Wh_p, *Wl_p, *Vh_p = nullptr, *Vl_p = nullptr;
    if (dual) {
        Wh_p = g_Wsm_hi + (size_t)(which*2)*DK;   Wl_p = g_Wsm_lo + (size_t)(which*2)*DK;
        Vh_p = g_Wsm_hi + (size_t)(which*2+1)*DK; Vl_p = g_Wsm_lo + (size_t)(which*2+1)*DK;
    } else {
        Wh_p = g_Wsm_hi + (size_t)6*DK;           Wl_p = g_Wsm_lo + (size_t)6*DK;
    }

    wmma::fragment<wmma::accumulator,16,16,16,float> acc[2][2];
    #pragma unroll
    for (int r=0;r<2;r++)
        #pragma unroll
        for (int c=0;c<2;c++) wmma::fill_fragment(acc[r][c], 0.0f);

    int aRow[2], aOff[2], bRow[2], bOff[2];
    #pragma unroll
    for (int j=0;j<2;j++) {
        int li = tid + 128*j;
        aRow[j] = li >> 2; aOff[j] = (li & 3)*8;
        bRow[j] = li >> 3; bOff[j] = (li & 7)*8;
    }

    for (int kk = 0; kk < Ddim; kk += 32) {
        __syncthreads();
        #pragma unroll
        for (int j=0;j<2;j++) {
            size_t ga = (size_t)(r0 + aRow[j])*Ddim + kk + aOff[j];
            size_t gb = (size_t)(kk + bRow[j])*Hdim + c0 + bOff[j];
            if (dual) {
                *(uint4*)(sA0 + aRow[j]*40 + aOff[j]) = *(const uint4*)(g_x_hi + ga);
                *(uint4*)(sA1 + aRow[j]*40 + aOff[j]) = *(const uint4*)(g_x_lo + ga);
                *(uint4*)(sA2 + aRow[j]*40 + aOff[j]) = *(const uint4*)(g_mib + ga);
                *(uint4*)(sB2 + bRow[j]*72 + bOff[j]) = *(const uint4*)(Vh_p + gb);
                *(uint4*)(sB3 + bRow[j]*72 + bOff[j]) = *(const uint4*)(Vl_p + gb);
            } else {
                *(uint4*)(sA0 + aRow[j]*40 + aOff[j]) = *(const uint4*)(g_mb + ga);
            }
            *(uint4*)(sB0 + bRow[j]*72 + bOff[j]) = *(const uint4*)(Wh_p + gb);
            *(uint4*)(sB1 + bRow[j]*72 + bOff[j]) = *(const uint4*)(Wl_p + gb);
        }
        __syncthreads();
        #pragma unroll
        for (int ks=0; ks<32; ks+=16) {
            wmma::fragment<wmma::matrix_a,16,16,16,bf16,wmma::row_major> a0[2], a1[2], a2[2];
            wmma::fragment<wmma::matrix_b,16,16,16,bf16,wmma::row_major> b0[2], b1[2], b2[2], b3[2];
            #pragma unroll
            for (int r=0;r<2;r++) {
                wmma::load_matrix_sync(a0[r], sA0 + (wr*32+r*16)*40 + ks, 40);
                if (dual) {
                    wmma::load_matrix_sync(a1[r], sA1 + (wr*32+r*16)*40 + ks, 40);
                    wmma::load_matrix_sync(a2[r], sA2 + (wr*32+r*16)*40 + ks, 40);
                }
            }
            #pragma unroll
            for (int c=0;c<2;c++) {
                wmma::load_matrix_sync(b0[c], sB0 + ks*72 + wc*32 + c*16, 72);
                wmma::load_matrix_sync(b1[c], sB1 + ks*72 + wc*32 + c*16, 72);
                if (dual) {
                    wmma::load_matrix_sync(b2[c], sB2 + ks*72 + wc*32 + c*16, 72);
                    wmma::load_matrix_sync(b3[c], sB3 + ks*72 + wc*32 + c*16, 72);
                }
            }
            #pragma unroll
            for (int r=0;r<2;r++)
                #pragma unroll
                for (int c=0;c<2;c++) {
                    wmma::mma_sync(acc[r][c], a0[r], b0[c], acc[r][c]);
                    wmma::mma_sync(acc[r][c], a0[r], b1[c], acc[r][c]);
                    if (dual) {
                        wmma::mma_sync(acc[r][c], a1[r], b0[c], acc[r][c]);
                        wmma::mma_sync(acc[r][c], a2[r], b2[c], acc[r][c]);
                        wmma::mma_sync(acc[r][c], a2[r], b3[c], acc[r][c]);
                    }
                }
        }
    }
    __syncthreads();
    #pragma unroll
    for (int r=0;r<2;r++)
        #pragma unroll
        for (int c=0;c<2;c++)
            wmma::store_matrix_sync(cs + (wr*32+r*16)*64 + wc*32 + c*16, acc[r][c], 64, wmma::mem_row_major);
    __syncthreads();

    const float* bias = (which==0)?pbz : (which==1)?pbr : (which==2)?pbh : pbg;
    float* out = (which==0)?g_pre_z : (which==1)?g_pre_r : (which==2)?g_pre_h : g_gamma;
    for (int i = tid; i < 64*64; i += 128) {
        int rr = i >> 6, cj = i & 63;
        float v = cs[i] + bias[c0 + cj];
        if (which == 3) v = expf(-fmaxf(0.0f, v));
        out[(size_t)(r0+rr)*Hdim + c0 + cj] = v;
    }
}

// ============ scan phase A: [256,2048] = hs @ [Uz|Ur] =======================
__global__ void __launch_bounds__(128) k_scanA(int t)
{
    __shared__ __align__(16) char smem_raw[19456];
    bf16* sAh = (bf16*)smem_raw;       // 64 x 40
    bf16* sAl = sAh + 64*40;
    bf16* sBh = sAl + 64*40;           // 32 x 72
    bf16* sBl = sBh + 32*72;
    float* cs = (float*)smem_raw;

    const int tid = threadIdx.x;
    const int wid = tid >> 5;
    const int wr = wid >> 1, wc = wid & 1;
    const int r0 = blockIdx.y*64, c0 = blockIdx.x*64;

    wmma::fragment<wmma::accumulator,16,16,16,float> acc[2][2];
    #pragma unroll
    for (int r=0;r<2;r++)
        #pragma unroll
        for (int c=0;c<2;c++) wmma::fill_fragment(acc[r][c], 0.0f);

    int aRow[2], aOff[2], bRow[2], bOff[2];
    #pragma unroll
    for (int j=0;j<2;j++) {
        int li = tid + 128*j;
        aRow[j] = li >> 2; aOff[j] = (li & 3)*8;
        bRow[j] = li >> 3; bOff[j] = (li & 7)*8;
    }
    uint4 pAh[2], pAl[2], pBh[2], pBl[2];
    #pragma unroll
    for (int j=0;j<2;j++) {
        pAh[j] = *(const uint4*)(g_hs_hi + (size_t)(r0+aRow[j])*Hdim + aOff[j]);
        pAl[j] = *(const uint4*)(g_hs_lo + (size_t)(r0+aRow[j])*Hdim + aOff[j]);
        pBh[j] = *(const uint4*)(g_Uzr_hi + (size_t)bRow[j]*2048 + c0 + bOff[j]);
        pBl[j] = *(const uint4*)(g_Uzr_lo + (size_t)bRow[j]*2048 + c0 + bOff[j]);
    }

    for (int kk = 0; kk < Hdim; kk += 32) {
        #pragma unroll
        for (int j=0;j<2;j++) {
            *(uint4*)(sAh + aRow[j]*40 + aOff[j]) = pAh[j];
            *(uint4*)(sAl + aRow[j]*40 + aOff[j]) = pAl[j];
            *(uint4*)(sBh + bRow[j]*72 + bOff[j]) = pBh[j];
            *(uint4*)(sBl + bRow[j]*72 + bOff[j]) = pBl[j];
        }
        __syncthreads();
        int kn = kk + 32;
        if (kn < Hdim) {
            #pragma unroll
            for (int j=0;j<2;j++) {
                pAh[j] = *(const uint4*)(g_hs_hi + (size_t)(r0+aRow[j])*Hdim + kn + aOff[j]);
                pAl[j] = *(const uint4*)(g_hs_lo + (size_t)(r0+aRow[j])*Hdim + kn + aOff[j]);
                pBh[j] = *(const uint4*)(g_Uzr_hi + (size_t)(kn+bRow[j])*2048 + c0 + bOff[j]);
                pBl[j] = *(const uint4*)(g_Uzr_lo + (size_t)(kn+bRow[j])*2048 + c0 + bOff[j]);
            }
        }
        #pragma unroll
        for (int ks=0; ks<32; ks+=16) {
            wmma::fragment<wmma::matrix_a,16,16,16,bf16,wmma::row_major> ah[2], al[2];
            wmma::fragment<wmma::matrix_b,16,16,16,bf16,wmma::row_major> bh[2], bl[2];
            #pragma unroll
            for (int r=0;r<2;r++) {
                wmma::load_matrix_sync(ah[r], sAh + (wr*32+r*16)*40 + ks, 40);
                wmma::load_matrix_sync(al[r], sAl + (wr*32+r*16)*40 + ks, 40);
            }
            #pragma unroll
            for (int c=0;c<2;c++) {
                wmma::load_matrix_sync(bh[c], sBh + ks*72 + wc*32 + c*16, 72);
                wmma::load_matrix_sync(bl[c], sBl + ks*72 + wc*32 + c*16, 72);
            }
            #pragma unroll
            for (int r=0;r<2;r++)
                #pragma unroll
                for (int c=0;c<2;c++) {
                    wmma::mma_sync(acc[r][c], ah[r], bh[c], acc[r][c]);
                    wmma::mma_sync(acc[r][c], ah[r], bl[c], acc[r][c]);
                    wmma::mma_sync(acc[r][c], al[r], bh[c], acc[r][c]);
                }
        }
        __syncthreads();
    }
    #pragma unroll
    for (int r=0;r<2;r++)
        #pragma unroll
        for (int c=0;c<2;c++)
            wmma::store_matrix_sync(cs + (wr*32+r*16)*64 + wc*32 + c*16, acc[r][c], 64, wmma::mem_row_major);
    __syncthreads();

    const bool is_z = (c0 < 1024);
    const int cbase = is_z ? c0 : c0 - 1024;
    const float* pre = is_z ? g_pre_z : g_pre_r;
    for (int i = tid; i < 64*64; i += 128) {
        int rr = i >> 6, cj = i & 63;
        int b = r0 + rr, c = cbase + cj;
        float v = pre[((size_t)b*Tdim + t)*Hdim + c] + cs[i];
        float s = 1.0f/(1.0f + expf(-v));
        int idx = b*Hdim + c;
        if (is_z) {
            g_z[idx] = s;
        } else {
            float rh = s * g_hs[idx];
            split2(rh, g_rh_hi[idx], g_rh_lo[idx]);
        }
    }
}

// ============ scan phase B: [256,1024] = rh @ U + state update ==============
__global__ void __launch_bounds__(128) k_scanB(int t)
{
    __shared__ __align__(16) char smem_raw[19456];
    bf16* sAh = (bf16*)smem_raw;
    bf16* sAl = sAh + 64*40;
    bf16* sBh = sAl + 64*40;
    bf16* sBl = sBh + 32*72;
    float* cs = (float*)smem_raw;

    const int tid = threadIdx.x;
    const int wid = tid >> 5;
    const int wr = wid >> 1, wc = wid & 1;
    const int r0 = blockIdx.y*64, c0 = blockIdx.x*64;

    wmma::fragment<wmma::accumulator,16,16,16,float> acc[2][2];
    #pragma unroll
    for (int r=0;r<2;r++)
        #pragma unroll
        for (int c=0;c<2;c++) wmma::fill_fragment(acc[r][c], 0.0f);

    int aRow[2], aOff[2], bRow[2], bOff[2];
    #pragma unroll
    for (int j=0;j<2;j++) {
        int li = tid + 128*j;
        aRow[j] = li >> 2; aOff[j] = (li & 3)*8;
        bRow[j] = li >> 3; bOff[j] = (li & 7)*8;
    }
    uint4 pAh[2], pAl[2], pBh[2], pBl[2];
    #pragma unroll
    for (int j=0;j<2;j++) {
        pAh[j] = *(const uint4*)(g_rh_hi + (size_t)(r0+aRow[j])*Hdim + aOff[j]);
        pAl[j] = *(const uint4*)(g_rh_lo + (size_t)(r0+aRow[j])*Hdim + aOff[j]);
        pBh[j] = *(const uint4*)(g_U_hi + (size_t)bRow[j]*Hdim + c0 + bOff[j]);
        pBl[j] = *(const uint4*)(g_U_lo + (size_t)bRow[j]*Hdim + c0 + bOff[j]);
    }

    for (int kk = 0; kk < Hdim; kk += 32) {
        #pragma unroll
        for (int j=0;j<2;j++) {
            *(uint4*)(sAh + aRow[j]*40 + aOff[j]) = pAh[j];
            *(uint4*)(sAl + aRow[j]*40 + aOff[j]) = pAl[j];
            *(uint4*)(sBh + bRow[j]*72 + bOff[j]) = pBh[j];
            *(uint4*)(sBl + bRow[j]*72 + bOff[j]) = pBl[j];
        }
        __syncthreads();
        int kn = kk + 32;
        if (kn < Hdim) {
            #pragma unroll
            for (int j=0;j<2;j++) {
                pAh[j] = *(const uint4*)(g_rh_hi + (size_t)(r0+aRow[j])*Hdim + kn + aOff[j]);
                pAl[j] = *(const uint4*)(g_rh_lo + (size_t)(r0+aRow[j])*Hdim + kn + aOff[j]);
                pBh[j] = *(const uint4*)(g_U_hi + (size_t)(kn+bRow[j])*Hdim + c0 + bOff[j]);
                pBl[j] = *(const uint4*)(g_U_lo + (size_t)(kn+bRow[j])*Hdim + c0 + bOff[j]);
            }
        }
        #pragma unroll
        for (int ks=0; ks<32; ks+=16) {
            wmma::fragment<wmma::matrix_a,16,16,16,bf16,wmma::row_major> ah[2], al[2];
            wmma::fragment<wmma::matrix_b,16,16,16,bf16,wmma::row_major> bh[2], bl[2];
            #pragma unroll
            for (int r=0;r<2;r++) {
                wmma::load_matrix_sync(ah[r], sAh + (wr*32+r*16)*40 + ks, 40);
                wmma::load_matrix_sync(al[r], sAl + (wr*32+r*16)*40 + ks, 40);
            }
            #pragma unroll
            for (int c=0;c<2;c++) {
                wmma::load_matrix_sync(bh[c], sBh + ks*72 + wc*32 + c*16, 72);
                wmma::load_matrix_sync(bl[c], sBl + ks*72 + wc*32 + c*16, 72);
            }
            #pragma unroll
            for (int r=0;r<2;r++)
                #pragma unroll
                for (int c=0;c<2;c++) {
                    wmma::mma_sync(acc[r][c], ah[r], bh[c], acc[r][c]);
                    wmma::mma_sync(acc[r][c], ah[r], bl[c], acc[r][c]);
                    wmma::mma_sync(acc[r][c], al[r], bh[c], acc[r][c]);
                }
        }
        __syncthreads();
    }
    #pragma unroll
    for (int r=0;r<2;r++)
        #pragma unroll
        for (int c=0;c<2;c++)
            wmma::store_matrix_sync(cs + (wr*32+r*16)*64 + wc*32 + c*16, acc[r][c], 64, wmma::mem_row_major);
    __syncthreads();

    for (int i = tid; i < 64*64; i += 128) {
        int rr = i >> 6, cj = i & 63;
        int b = r0 + rr, c = c0 + cj;
        int idx = b*Hdim + c;
        float ht = tanhf(g_pre_h[((size_t)b*Tdim + t)*Hdim + c] + cs[i]);
        float hs = g_hs[idx];
        float z  = g_z[idx];
        float hn = (1.0f - z)*hs + z*ht;
        g_h[idx] = hn;
        float gn = (t+1 < Tdim) ? g_gamma[((size_t)b*Tdim + (t+1))*Hdim + c] : 1.0f;
        float nhs = gn*hn;
        g_hs[idx] = nhs;
        split2(nhs, g_hs_hi[idx], g_hs_lo[idx]);
    }
}

// ---------------- decoder ---------------------------------------------------
__global__ void k_dec(const float* __restrict__ dW, const float* __restrict__ db,
                      float* __restrict__ out)
{
    __shared__ float hrow[Hdim];
    int b = blockIdx.x;
    for (int i = threadIdx.x; i < Hdim; i += blockDim.x)
        hrow[i] = g_h[b*Hdim + i];
    __syncthreads();
    int o = threadIdx.x;
    float acc = db[o];
    #pragma unroll 8
    for (int k = 0; k < Hdim; k++)
        acc += hrow[k]*dW[k*Odim + o];
    out[b*Odim + o] = acc;
}

// ---------------- launch ----------------------------------------------------
extern "C" void kernel_launch(void* const* d_in, const int* in_sizes, int n_in,
                              void* d_out, int out_size)
{
    const float* x     = (const float*)d_in[0];
    const float* delta = (const float*)d_in[1];
    const float* m     = (const float*)d_in[2];
    const float* W_r   = (const float*)d_in[3];
    const float* U_r   = (const float*)d_in[4];
    const float* V_r   = (const float*)d_in[5];
    const float* b_r   = (const float*)d_in[6];
    const float* W_z   = (const float*)d_in[7];
    const float* U_z   = (const float*)d_in[8];
    const float* V_z   = (const float*)d_in[9];
    const float* b_z   = (const float*)d_in[10];
    const float* W     = (const float*)d_in[11];
    const float* U     = (const float*)d_in[12];
    const float* V     = (const float*)d_in[13];
    const float* b     = (const float*)d_in[14];
    const float* Wgx   = (const float*)d_in[15];
    const float* bgx   = (const float*)d_in[16];
    const float* Wgh   = (const float*)d_in[17];
    const float* bgh   = (const float*)d_in[18];
    const float* decW  = (const float*)d_in[19];
    const float* decb  = (const float*)d_in[20];
    float* out = (float*)d_out;

    // operand prep
    k_xmod<<<(BT*Ddim + 255)/256, 256>>>(x, delta, m, Wgx, bgx);
    k_split_small<<<(DK+255)/256, 256>>>(W_z, 0);
    k_split_small<<<(DK+255)/256, 256>>>(V_z, 1);
    k_split_small<<<(DK+255)/256, 256>>>(W_r, 2);
    k_split_small<<<(DK+255)/256, 256>>>(V_r, 3);
    k_split_small<<<(DK+255)/256, 256>>>(W,   4);
    k_split_small<<<(DK+255)/256, 256>>>(V,   5);
    k_split_small<<<(DK+255)/256, 256>>>(Wgh, 6);
    k_split_U<<<(1024*1024 + 255)/256, 256>>>(U);
    k_split_uzr<<<(1024*2048 + 255)/256, 256>>>(U_z, U_r);

    // precompute pre_z / pre_r / pre_h / gamma
    k_pre<<<dim3(Hdim/64, BT/64, 4), 128>>>(b_z, b_r, b, bgh);

    k_init<<<(Bdim*Hdim + 255)/256, 256>>>();

    for (int t = 0; t < Tdim; t++) {
        k_scanA<<<dim3(32, Bdim/64), 128>>>(t);
        k_scanB<<<dim3(16, Bdim/64), 128>>>(t);
    }
    k_dec<<<Bdim, Odim>>>(decW, decb, out);
}

// round 4
// speedup vs baseline: 2.2632x; 1.1342x over previous
#include <cuda_runtime.h>
#include <cuda_bf16.h>
#include <mma.h>
#include <math.h>

using namespace nvcuda;
typedef __nv_bfloat16 bf16;

#define Bdim 256
#define Tdim 256
#define Ddim 128
#define Hdim 1024
#define Odim 64
#define BT (Bdim*Tdim)
#define DK (Ddim*Hdim)
#define NBLK 128

// ---------------- scratch (device globals; allocations forbidden) ----------
__device__ float g_pre_z[67108864];          // [BT, H]
__device__ float g_pre_r[67108864];
__device__ float g_pre_h[67108864];
__device__ float g_gamma[67108864];
__device__ float g_hs[Bdim*Hdim];
__device__ float g_h [Bdim*Hdim];
__device__ float g_z [Bdim*Hdim];

__device__ bf16 g_hs_hi[Bdim*Hdim], g_hs_lo[Bdim*Hdim];
__device__ bf16 g_rh_hi[Bdim*Hdim], g_rh_lo[Bdim*Hdim];
__device__ bf16 g_x_hi[BT*Ddim],   g_x_lo[BT*Ddim];
__device__ bf16 g_mb [BT*Ddim];
__device__ bf16 g_mib[BT*Ddim];

__device__ bf16 g_Uzr_hi[1024*2048], g_Uzr_lo[1024*2048];
__device__ bf16 g_U_hi[1024*1024],   g_U_lo[1024*1024];
__device__ bf16 g_Wsm_hi[7*DK], g_Wsm_lo[7*DK];

// grid barrier state
__device__ unsigned g_bar_cnt = 0;
__device__ unsigned g_bar_gen = 0;

__device__ __forceinline__ void split2(float v, bf16& hi, bf16& lo) {
    hi = __float2bfloat16(v);
    lo = __float2bfloat16(v - __bfloat162float(hi));
}

__device__ __forceinline__ void grid_sync() {
    __threadfence();
    __syncthreads();
    if (threadIdx.x == 0) {
        unsigned my = atomicAdd(&g_bar_gen, 0u);
        if (atomicAdd(&g_bar_cnt, 1u) == NBLK - 1u) {
            atomicExch(&g_bar_cnt, 0u);
            atomicAdd(&g_bar_gen, 1u);
        } else {
            while (atomicAdd(&g_bar_gen, 0u) == my) { }
        }
    }
    __syncthreads();
}

// ---------------- elementwise: input decay + operand prep ------------------
__global__ void k_xmod(const float* __restrict__ x, const float* __restrict__ delta,
                       const float* __restrict__ m, const float* __restrict__ wgx,
                       const float* __restrict__ bgx) {
    int i = blockIdx.x*blockDim.x + threadIdx.x;
    if (i >= BT*Ddim) return;
    int d = i & (Ddim-1);
    float mv = m[i];
    float dec = delta[i]*wgx[d] + bgx[d];
    float xv = (mv > 0.0f) ? (1.0f - dec)*0.001f : x[i];
    split2(xv, g_x_hi[i], g_x_lo[i]);
    g_mb[i]  = __float2bfloat16(mv);
    g_mib[i] = __float2bfloat16(1.0f - mv);
}

// ---------------- weight splitting -----------------------------------------
__global__ void k_split_small(const float* __restrict__ src, int slot) {
    int i = blockIdx.x*blockDim.x + threadIdx.x;
    if (i >= DK) return;
    split2(src[i], g_Wsm_hi[(size_t)slot*DK + i], g_Wsm_lo[(size_t)slot*DK + i]);
}
__global__ void k_split_U(const float* __restrict__ U) {
    int i = blockIdx.x*blockDim.x + threadIdx.x;
    if (i >= 1024*1024) return;
    split2(U[i], g_U_hi[i], g_U_lo[i]);
}
__global__ void k_split_uzr(const float* __restrict__ Uz, const float* __restrict__ Ur) {
    int i = blockIdx.x*blockDim.x + threadIdx.x;
    if (i >= 1024*2048) return;
    int k = i >> 11, n = i & 2047;
    float v = (n < 1024) ? Uz[k*1024 + n] : Ur[k*1024 + n - 1024];
    split2(v, g_Uzr_hi[i], g_Uzr_lo[i]);
}

__global__ void k_init() {
    int i = blockIdx.x*blockDim.x + threadIdx.x;
    if (i < Bdim*Hdim) {
        g_hs[i] = 0.0f; g_h[i] = 0.0f;
        g_hs_hi[i] = __float2bfloat16(0.0f);
        g_hs_lo[i] = __float2bfloat16(0.0f);
    }
}

// ============ precompute GEMMs (smem-staged wmma) ===========================
__global__ void __launch_bounds__(128) k_pre(const float* __restrict__ pbz,
                                             const float* __restrict__ pbr,
                                             const float* __restrict__ pbh,
                                             const float* __restrict__ pbg)
{
    __shared__ __align__(16) char smem_raw[33792];
    bf16* sA0 = (bf16*)smem_raw;
    bf16* sA1 = sA0 + 64*40;
    bf16* sA2 = sA1 + 64*40;
    bf16* sB0 = sA2 + 64*40;
    bf16* sB1 = sB0 + 32*72;
    bf16* sB2 = sB1 + 32*72;
    bf16* sB3 = sB2 + 32*72;
    float* cs = (float*)smem_raw;

    const int which = blockIdx.z;
    const bool dual = (which < 3);
    const int tid = threadIdx.x;
    const int wid = tid >> 5;
    const int wr = wid >> 1, wc = wid & 1;
    const int r0 = blockIdx.y*64, c0 = blockIdx.x*64;

    const bf16 *Wh_p, *Wl_p, *Vh_p = nullptr, *Vl_p = nullptr;
    if (dual) {
        Wh_p = g_Wsm_hi + (size_t)(which*2)*DK;   Wl_p = g_Wsm_lo + (size_t)(which*2)*DK;
        Vh_p = g_Wsm_hi + (size_t)(which*2+1)*DK; Vl_p = g_Wsm_lo + (size_t)(which*2+1)*DK;
    } else {
        Wh_p = g_Wsm_hi + (size_t)6*DK;           Wl_p = g_Wsm_lo + (size_t)6*DK;
    }

    wmma::fragment<wmma::accumulator,16,16,16,float> acc[2][2];
    #pragma unroll
    for (int r=0;r<2;r++)
        #pragma unroll
        for (int c=0;c<2;c++) wmma::fill_fragment(acc[r][c], 0.0f);

    int aRow[2], aOff[2], bRow[2], bOff[2];
    #pragma unroll
    for (int j=0;j<2;j++) {
        int li = tid + 128*j;
        aRow[j] = li >> 2; aOff[j] = (li & 3)*8;
        bRow[j] = li >> 3; bOff[j] = (li & 7)*8;
    }

    for (int kk = 0; kk < Ddim; kk += 32) {
        __syncthreads();
        #pragma unroll
        for (int j=0;j<2;j++) {
            size_t ga = (size_t)(r0 + aRow[j])*Ddim + kk + aOff[j];
            size_t gb = (size_t)(kk + bRow[j])*Hdim + c0 + bOff[j];
            if (dual) {
                *(uint4*)(sA0 + aRow[j]*40 + aOff[j]) = *(const uint4*)(g_x_hi + ga);
                *(uint4*)(sA1 + aRow[j]*40 + aOff[j]) = *(const uint4*)(g_x_lo + ga);
                *(uint4*)(sA2 + aRow[j]*40 + aOff[j]) = *(const uint4*)(g_mib + ga);
                *(uint4*)(sB2 + bRow[j]*72 + bOff[j]) = *(const uint4*)(Vh_p + gb);
                *(uint4*)(sB3 + bRow[j]*72 + bOff[j]) = *(const uint4*)(Vl_p + gb);
            } else {
                *(uint4*)(sA0 + aRow[j]*40 + aOff[j]) = *(const uint4*)(g_mb + ga);
            }
            *(uint4*)(sB0 + bRow[j]*72 + bOff[j]) = *(const uint4*)(Wh_p + gb);
            *(uint4*)(sB1 + bRow[j]*72 + bOff[j]) = *(const uint4*)(Wl_p + gb);
        }
        __syncthreads();
        #pragma unroll
        for (int ks=0; ks<32; ks+=16) {
            wmma::fragment<wmma::matrix_a,16,16,16,bf16,wmma::row_major> a0[2], a1[2], a2[2];
            wmma::fragment<wmma::matrix_b,16,16,16,bf16,wmma::row_major> b0[2], b1[2], b2[2], b3[2];
            #pragma unroll
            for (int r=0;r<2;r++) {
                wmma::load_matrix_sync(a0[r], sA0 + (wr*32+r*16)*40 + ks, 40);
                if (dual) {
                    wmma::load_matrix_sync(a1[r], sA1 + (wr*32+r*16)*40 + ks, 40);
                    wmma::load_matrix_sync(a2[r], sA2 + (wr*32+r*16)*40 + ks, 40);
                }
            }
            #pragma unroll
            for (int c=0;c<2;c++) {
                wmma::load_matrix_sync(b0[c], sB0 + ks*72 + wc*32 + c*16, 72);
                wmma::load_matrix_sync(b1[c], sB1 + ks*72 + wc*32 + c*16, 72);
                if (dual) {
                    wmma::load_matrix_sync(b2[c], sB2 + ks*72 + wc*32 + c*16, 72);
                    wmma::load_matrix_sync(b3[c], sB3 + ks*72 + wc*32 + c*16, 72);
                }
            }
            #pragma unroll
            for (int r=0;r<2;r++)
                #pragma unroll
                for (int c=0;c<2;c++) {
                    wmma::mma_sync(acc[r][c], a0[r], b0[c], acc[r][c]);
                    wmma::mma_sync(acc[r][c], a0[r], b1[c], acc[r][c]);
                    if (dual) {
                        wmma::mma_sync(acc[r][c], a1[r], b0[c], acc[r][c]);
                        wmma::mma_sync(acc[r][c], a2[r], b2[c], acc[r][c]);
                        wmma::mma_sync(acc[r][c], a2[r], b3[c], acc[r][c]);
                    }
                }
        }
    }
    __syncthreads();
    #pragma unroll
    for (int r=0;r<2;r++)
        #pragma unroll
        for (int c=0;c<2;c++)
            wmma::store_matrix_sync(cs + (wr*32+r*16)*64 + wc*32 + c*16, acc[r][c], 64, wmma::mem_row_major);
    __syncthreads();

    const float* bias = (which==0)?pbz : (which==1)?pbr : (which==2)?pbh : pbg;
    float* out = (which==0)?g_pre_z : (which==1)?g_pre_r : (which==2)?g_pre_h : g_gamma;
    for (int i = tid; i < 64*64; i += 128) {
        int rr = i >> 6, cj = i & 63;
        float v = cs[i] + bias[c0 + cj];
        if (which == 3) v = expf(-fmaxf(0.0f, v));
        out[(size_t)(r0+rr)*Hdim + c0 + cj] = v;
    }
}

// ============ persistent scan kernel ========================================
// NF = number of 16-col N fragments (2 for phase A, 1 for phase B)
template<int NF>
__device__ __forceinline__ void run_gemm(
    const bf16* __restrict__ gAh, const bf16* __restrict__ gAl, int r0,
    const bf16* __restrict__ sWh, const bf16* __restrict__ sWl,
    bf16* __restrict__ sStage, float* __restrict__ cs,
    wmma::fragment<wmma::accumulator,16,16,16,float>* acc)
{
    const int tid = threadIdx.x;
    const int wid = tid >> 5;
    const int arow = tid >> 1;
    const int aoff = (tid & 1) * 8;
    const size_t abase = (size_t)(r0 + arow) * Hdim + aoff;

    #pragma unroll
    for (int f = 0; f < NF; f++) wmma::fill_fragment(acc[f], 0.0f);

    bf16* sAh0 = sStage;
    bf16* sAl0 = sStage + 2048;
    bf16* sAh1 = sStage + 4096;
    bf16* sAl1 = sStage + 6144;

    uint4 ph = __ldcg((const uint4*)(gAh + abase));
    uint4 pl = __ldcg((const uint4*)(gAl + abase));
    *(uint4*)(sAh0 + arow*16 + aoff) = ph;
    *(uint4*)(sAl0 + arow*16 + aoff) = pl;
    ph = __ldcg((const uint4*)(gAh + abase + 16));
    pl = __ldcg((const uint4*)(gAl + abase + 16));
    __syncthreads();

    for (int ki = 0; ki < 64; ki++) {
        bf16* cAh = (ki & 1) ? sAh1 : sAh0;
        bf16* cAl = (ki & 1) ? sAl1 : sAl0;
        if (ki + 1 < 64) {
            bf16* nAh = (ki & 1) ? sAh0 : sAh1;
            bf16* nAl = (ki & 1) ? sAl0 : sAl1;
            *(uint4*)(nAh + arow*16 + aoff) = ph;
            *(uint4*)(nAl + arow*16 + aoff) = pl;
        }
        if (ki + 2 < 64) {
            ph = __ldcg((const uint4*)(gAh + abase + (size_t)(ki+2)*16));
            pl = __ldcg((const uint4*)(gAl + abase + (size_t)(ki+2)*16));
        }
        wmma::fragment<wmma::matrix_a,16,16,16,bf16,wmma::row_major> ah, al;
        wmma::load_matrix_sync(ah, cAh + wid*16*16, 16);
        wmma::load_matrix_sync(al, cAl + wid*16*16, 16);
        #pragma unroll
        for (int f = 0; f < NF; f++) {
            wmma::fragment<wmma::matrix_b,16,16,16,bf16,wmma::row_major> bh, bl;
            wmma::load_matrix_sync(bh, sWh + ki*16*(NF*16) + f*16, NF*16);
            wmma::load_matrix_sync(bl, sWl + ki*16*(NF*16) + f*16, NF*16);
            wmma::mma_sync(acc[f], ah, bh, acc[f]);
            wmma::mma_sync(acc[f], ah, bl, acc[f]);
            wmma::mma_sync(acc[f], al, bh, acc[f]);
        }
        __syncthreads();
    }
    #pragma unroll
    for (int f = 0; f < NF; f++)
        wmma::store_matrix_sync(cs + (wid*16)*(NF*16) + f*16, acc[f], NF*16, wmma::mem_row_major);
    __syncthreads();
}

extern "C" __global__ void __launch_bounds__(256, 1) k_scan()
{
    extern __shared__ __align__(16) char dsm[];
    bf16* sWAh = (bf16*)dsm;                     // 1024 x 32
    bf16* sWAl = sWAh + 1024*32;
    bf16* sWBh = sWAl + 1024*32;                 // 1024 x 16
    bf16* sWBl = sWBh + 1024*16;
    bf16* sStage = sWBl + 1024*16;               // 2 bufs x (hi,lo) x 128x16
    float* cs = (float*)sStage;                  // epilogue accum (aliases stage)

    const int tid = threadIdx.x;
    const int blk = blockIdx.x;
    const int mi = blk >> 6;                     // 0..1
    const int nj = blk & 63;                     // 0..63
    const int r0 = mi * 128;
    const int c0A = nj * 32;                     // 0..2047
    const int c0B = nj * 16;                     // 0..1023
    const bool isz = (c0A < 1024);

    // load resident weight slices (once)
    for (int i = tid; i < 1024*32/8; i += 256) {
        int row = i >> 2, off = (i & 3) * 8;
        *(uint4*)(sWAh + row*32 + off) = *(const uint4*)(g_Uzr_hi + (size_t)row*2048 + c0A + off);
        *(uint4*)(sWAl + row*32 + off) = *(const uint4*)(g_Uzr_lo + (size_t)row*2048 + c0A + off);
    }
    for (int i = tid; i < 1024*16/8; i += 256) {
        int row = i >> 1, off = (i & 1) * 8;
        *(uint4*)(sWBh + row*16 + off) = *(const uint4*)(g_U_hi + (size_t)row*1024 + c0B + off);
        *(uint4*)(sWBl + row*16 + off) = *(const uint4*)(g_U_lo + (size_t)row*1024 + c0B + off);
    }
    __syncthreads();

    wmma::fragment<wmma::accumulator,16,16,16,float> acc[2];

    for (int t = 0; t < Tdim; t++) {
        // ---- phase A: hs @ [Uz|Ur] slice ----
        run_gemm<2>(g_hs_hi, g_hs_lo, r0, sWAh, sWAl, sStage, cs, acc);
        if (isz) {
            for (int i = tid; i < 128*32; i += 256) {
                int rr = i >> 5, cj = i & 31;
                int row = r0 + rr, c = c0A + cj;
                float v = g_pre_z[((size_t)row*Tdim + t)*Hdim + c] + cs[i];
                g_z[row*Hdim + c] = 1.0f/(1.0f + expf(-v));
            }
        } else {
            for (int i = tid; i < 128*32; i += 256) {
                int rr = i >> 5, cj = i & 31;
                int row = r0 + rr, c = c0A - 1024 + cj;
                float v = g_pre_r[((size_t)row*Tdim + t)*Hdim + c] + cs[i];
                float s = 1.0f/(1.0f + expf(-v));
                float hs = __ldcg(&g_hs[row*Hdim + c]);
                float rh = s * hs;
                int idx = row*Hdim + c;
                bf16 hi, lo; split2(rh, hi, lo);
                g_rh_hi[idx] = hi; g_rh_lo[idx] = lo;
            }
        }
        grid_sync();

        // ---- phase B: rh @ U slice + state update ----
        run_gemm<1>(g_rh_hi, g_rh_lo, r0, sWBh, sWBl, sStage, cs, acc);
        for (int i = tid; i < 128*16; i += 256) {
            int rr = i >> 4, cj = i & 15;
            int row = r0 + rr, c = c0B + cj;
            int idx = row*Hdim + c;
            float ht = tanhf(g_pre_h[((size_t)row*Tdim + t)*Hdim + c] + cs[i]);
            float hs = __ldcg(&g_hs[idx]);
            float z  = __ldcg(&g_z[idx]);
            float hn = (1.0f - z)*hs + z*ht;
            if (t == Tdim-1) g_h[idx] = hn;
            float gn = (t+1 < Tdim) ? g_gamma[((size_t)row*Tdim + (t+1))*Hdim + c] : 1.0f;
            float nhs = gn*hn;
            g_hs[idx] = nhs;
            bf16 hi, lo; split2(nhs, hi, lo);
            g_hs_hi[idx] = hi; g_hs_lo[idx] = lo;
        }
        grid_sync();
    }
}

// ---------------- decoder ---------------------------------------------------
__global__ void k_dec(const float* __restrict__ dW, const float* __restrict__ db,
                      float* __restrict__ out)
{
    __shared__ float hrow[Hdim];
    int b = blockIdx.x;
    for (int i = threadIdx.x; i < Hdim; i += blockDim.x)
        hrow[i] = g_h[b*Hdim + i];
    __syncthreads();
    int o = threadIdx.x;
    float acc = db[o];
    #pragma unroll 8
    for (int k = 0; k < Hdim; k++)
        acc += hrow[k]*dW[k*Odim + o];
    out[b*Odim + o] = acc;
}

// ---------------- launch ----------------------------------------------------
extern "C" void kernel_launch(void* const* d_in, const int* in_sizes, int n_in,
                              void* d_out, int out_size)
{
    const float* x     = (const float*)d_in[0];
    const float* delta = (const float*)d_in[1];
    const float* m     = (const float*)d_in[2];
    const float* W_r   = (const float*)d_in[3];
    const float* U_r   = (const float*)d_in[4];
    const float* V_r   = (const float*)d_in[5];
    const float* b_r   = (const float*)d_in[6];
    const float* W_z   = (const float*)d_in[7];
    const float* U_z   = (const float*)d_in[8];
    const float* V_z   = (const float*)d_in[9];
    const float* b_z   = (const float*)d_in[10];
    const float* W     = (const float*)d_in[11];
    const float* U     = (const float*)d_in[12];
    const float* V     = (const float*)d_in[13];
    const float* b     = (const float*)d_in[14];
    const float* Wgx   = (const float*)d_in[15];
    const float* bgx   = (const float*)d_in[16];
    const float* Wgh   = (const float*)d_in[17];
    const float* bgh   = (const float*)d_in[18];
    const float* decW  = (const float*)d_in[19];
    const float* decb  = (const float*)d_in[20];
    float* out = (float*)d_out;

    static int smem_set = 0;
    const int SCAN_SMEM = 212992;   // 208 KB
    if (!smem_set) {
        cudaFuncSetAttribute(k_scan, cudaFuncAttributeMaxDynamicSharedMemorySize, SCAN_SMEM);
        smem_set = 1;
    }

    k_xmod<<<(BT*Ddim + 255)/256, 256>>>(x, delta, m, Wgx, bgx);
    k_split_small<<<(DK+255)/256, 256>>>(W_z, 0);
    k_split_small<<<(DK+255)/256, 256>>>(V_z, 1);
    k_split_small<<<(DK+255)/256, 256>>>(W_r, 2);
    k_split_small<<<(DK+255)/256, 256>>>(V_r, 3);
    k_split_small<<<(DK+255)/256, 256>>>(W,   4);
    k_split_small<<<(DK+255)/256, 256>>>(V,   5);
    k_split_small<<<(DK+255)/256, 256>>>(Wgh, 6);
    k_split_U<<<(1024*1024 + 255)/256, 256>>>(U);
    k_split_uzr<<<(1024*2048 + 255)/256, 256>>>(U_z, U_r);

    k_pre<<<dim3(Hdim/64, BT/64, 4), 128>>>(b_z, b_r, b, bgh);
    k_init<<<(Bdim*Hdim + 255)/256, 256>>>();

    k_scan<<<NBLK, 256, SCAN_SMEM>>>();

    k_dec<<<Bdim, Odim>>>(decW, decb, out);
}

// round 6
// speedup vs baseline: 3.3505x; 1.4804x over previous
#include <cuda_runtime.h>
#include <cuda_bf16.h>
#include <mma.h>
#include <math.h>
#include <stdint.h>

using namespace nvcuda;
typedef __nv_bfloat16 bf16;

#define Bdim 256
#define Tdim 256
#define Ddim 128
#define Hdim 1024
#define Odim 64
#define BT (Bdim*Tdim)
#define DK (Ddim*Hdim)
#define NBLK 128

// ---------------- scratch (device globals; allocations forbidden) ----------
__device__ float g_pre_z[67108864];
__device__ float g_pre_r[67108864];
__device__ float g_pre_h[67108864];
__device__ float g_gamma[67108864];
__device__ float g_hs[Bdim*Hdim];
__device__ float g_h [Bdim*Hdim];
__device__ float g_z [Bdim*Hdim];

__device__ bf16 g_hs_hi[Bdim*Hdim], g_hs_lo[Bdim*Hdim];
__device__ bf16 g_rh_hi[Bdim*Hdim], g_rh_lo[Bdim*Hdim];
__device__ bf16 g_x_hi[BT*Ddim],   g_x_lo[BT*Ddim];
__device__ bf16 g_mb [BT*Ddim];
__device__ bf16 g_mib[BT*Ddim];

// transposed split weights: [n][k] n-major rows (k stride 1024)
__device__ bf16 g_UzrT_hi[2048*1024], g_UzrT_lo[2048*1024];
__device__ bf16 g_UT_hi[1024*1024],   g_UT_lo[1024*1024];
__device__ bf16 g_Wsm_hi[7*DK], g_Wsm_lo[7*DK];

__device__ unsigned g_bar_cnt = 0;
__device__ unsigned g_bar_gen = 0;

__device__ __forceinline__ void split2(float v, bf16& hi, bf16& lo) {
    hi = __float2bfloat16(v);
    lo = __float2bfloat16(v - __bfloat162float(hi));
}

__device__ __forceinline__ void grid_sync() {
    __threadfence();
    __syncthreads();
    if (threadIdx.x == 0) {
        unsigned my = atomicAdd(&g_bar_gen, 0u);
        if (atomicAdd(&g_bar_cnt, 1u) == NBLK - 1u) {
            atomicExch(&g_bar_cnt, 0u);
            atomicAdd(&g_bar_gen, 1u);
        } else {
            while (atomicAdd(&g_bar_gen, 0u) == my) { }
        }
    }
    __syncthreads();
}

// ---------------- elementwise: input decay + operand prep ------------------
__global__ void k_xmod(const float* __restrict__ x, const float* __restrict__ delta,
                       const float* __restrict__ m, const float* __restrict__ wgx,
                       const float* __restrict__ bgx) {
    int i = blockIdx.x*blockDim.x + threadIdx.x;
    if (i >= BT*Ddim) return;
    int d = i & (Ddim-1);
    float mv = m[i];
    float dec = delta[i]*wgx[d] + bgx[d];
    float xv = (mv > 0.0f) ? (1.0f - dec)*0.001f : x[i];
    split2(xv, g_x_hi[i], g_x_lo[i]);
    g_mb[i]  = __float2bfloat16(mv);
    g_mib[i] = __float2bfloat16(1.0f - mv);
}

// ---------------- weight splitting -----------------------------------------
__global__ void k_split_small_all(const float* __restrict__ Wz, const float* __restrict__ Vz,
                                  const float* __restrict__ Wr, const float* __restrict__ Vr,
                                  const float* __restrict__ Wh, const float* __restrict__ Vh,
                                  const float* __restrict__ Wg) {
    int i = blockIdx.x*blockDim.x + threadIdx.x;
    if (i >= 7*DK) return;
    int slot = i >> 17;
    int j = i & (DK-1);
    const float* src = (slot==0)?Wz:(slot==1)?Vz:(slot==2)?Wr:(slot==3)?Vr:(slot==4)?Wh:(slot==5)?Vh:Wg;
    split2(src[j], g_Wsm_hi[i], g_Wsm_lo[i]);
}
__global__ void k_split_bigT(const float* __restrict__ Uz, const float* __restrict__ Ur,
                             const float* __restrict__ U) {
    int i = blockIdx.x*blockDim.x + threadIdx.x;
    if (i < 2048*1024) {
        int n = i >> 10, k = i & 1023;
        float v = (n < 1024) ? Uz[k*1024 + n] : Ur[k*1024 + (n-1024)];
        split2(v, g_UzrT_hi[i], g_UzrT_lo[i]);
    } else if (i < 3*1024*1024) {
        int j = i - 2048*1024;
        int n = j >> 10, k = j & 1023;
        split2(U[k*1024 + n], g_UT_hi[j], g_UT_lo[j]);
    }
}

__global__ void k_init() {
    int i = blockIdx.x*blockDim.x + threadIdx.x;
    if (i < Bdim*Hdim) {
        g_hs[i] = 0.0f; g_h[i] = 0.0f;
        g_hs_hi[i] = __float2bfloat16(0.0f);
        g_hs_lo[i] = __float2bfloat16(0.0f);
    }
    if (i == 0) { g_bar_cnt = 0; g_bar_gen = 0; }
}

// ============ precompute GEMMs (smem-staged wmma) ===========================
__global__ void __launch_bounds__(128) k_pre(const float* __restrict__ pbz,
                                             const float* __restrict__ pbr,
                                             const float* __restrict__ pbh,
                                             const float* __restrict__ pbg)
{
    __shared__ __align__(16) char smem_raw[33792];
    bf16* sA0 = (bf16*)smem_raw;
    bf16* sA1 = sA0 + 64*40;
    bf16* sA2 = sA1 + 64*40;
    bf16* sB0 = sA2 + 64*40;
    bf16* sB1 = sB0 + 32*72;
    bf16* sB2 = sB1 + 32*72;
    bf16* sB3 = sB2 + 32*72;
    float* cs = (float*)smem_raw;

    const int which = blockIdx.z;
    const bool dual = (which < 3);
    const int tid = threadIdx.x;
    const int wid = tid >> 5;
    const int wr = wid >> 1, wc = wid & 1;
    const int r0 = blockIdx.y*64, c0 = blockIdx.x*64;

    const bf16 *Wh_p, *Wl_p, *Vh_p = nullptr, *Vl_p = nullptr;
    if (dual) {
        Wh_p = g_Wsm_hi + (size_t)(which*2)*DK;   Wl_p = g_Wsm_lo + (size_t)(which*2)*DK;
        Vh_p = g_Wsm_hi + (size_t)(which*2+1)*DK; Vl_p = g_Wsm_lo + (size_t)(which*2+1)*DK;
    } else {
        Wh_p = g_Wsm_hi + (size_t)6*DK;           Wl_p = g_Wsm_lo + (size_t)6*DK;
    }

    wmma::fragment<wmma::accumulator,16,16,16,float> acc[2][2];
    #pragma unroll
    for (int r=0;r<2;r++)
        #pragma unroll
        for (int c=0;c<2;c++) wmma::fill_fragment(acc[r][c], 0.0f);

    int aRow[2], aOff[2], bRow[2], bOff[2];
    #pragma unroll
    for (int j=0;j<2;j++) {
        int li = tid + 128*j;
        aRow[j] = li >> 2; aOff[j] = (li & 3)*8;
        bRow[j] = li >> 3; bOff[j] = (li & 7)*8;
    }

    for (int kk = 0; kk < Ddim; kk += 32) {
        __syncthreads();
        #pragma unroll
        for (int j=0;j<2;j++) {
            size_t ga = (size_t)(r0 + aRow[j])*Ddim + kk + aOff[j];
            size_t gb = (size_t)(kk + bRow[j])*Hdim + c0 + bOff[j];
            if (dual) {
                *(uint4*)(sA0 + aRow[j]*40 + aOff[j]) = *(const uint4*)(g_x_hi + ga);
                *(uint4*)(sA1 + aRow[j]*40 + aOff[j]) = *(const uint4*)(g_x_lo + ga);
                *(uint4*)(sA2 + aRow[j]*40 + aOff[j]) = *(const uint4*)(g_mib + ga);
                *(uint4*)(sB2 + bRow[j]*72 + bOff[j]) = *(const uint4*)(Vh_p + gb);
                *(uint4*)(sB3 + bRow[j]*72 + bOff[j]) = *(const uint4*)(Vl_p + gb);
            } else {
                *(uint4*)(sA0 + aRow[j]*40 + aOff[j]) = *(const uint4*)(g_mb + ga);
            }
            *(uint4*)(sB0 + bRow[j]*72 + bOff[j]) = *(const uint4*)(Wh_p + gb);
            *(uint4*)(sB1 + bRow[j]*72 + bOff[j]) = *(const uint4*)(Wl_p + gb);
        }
        __syncthreads();
        #pragma unroll
        for (int ks=0; ks<32; ks+=16) {
            wmma::fragment<wmma::matrix_a,16,16,16,bf16,wmma::row_major> a0[2], a1[2], a2[2];
            wmma::fragment<wmma::matrix_b,16,16,16,bf16,wmma::row_major> b0[2], b1[2], b2[2], b3[2];
            #pragma unroll
            for (int r=0;r<2;r++) {
                wmma::load_matrix_sync(a0[r], sA0 + (wr*32+r*16)*40 + ks, 40);
                if (dual) {
                    wmma::load_matrix_sync(a1[r], sA1 + (wr*32+r*16)*40 + ks, 40);
                    wmma::load_matrix_sync(a2[r], sA2 + (wr*32+r*16)*40 + ks, 40);
                }
            }
            #pragma unroll
            for (int c=0;c<2;c++) {
                wmma::load_matrix_sync(b0[c], sB0 + ks*72 + wc*32 + c*16, 72);
                wmma::load_matrix_sync(b1[c], sB1 + ks*72 + wc*32 + c*16, 72);
                if (dual) {
                    wmma::load_matrix_sync(b2[c], sB2 + ks*72 + wc*32 + c*16, 72);
                    wmma::load_matrix_sync(b3[c], sB3 + ks*72 + wc*32 + c*16, 72);
                }
            }
            #pragma unroll
            for (int r=0;r<2;r++)
                #pragma unroll
                for (int c=0;c<2;c++) {
                    wmma::mma_sync(acc[r][c], a0[r], b0[c], acc[r][c]);
                    wmma::mma_sync(acc[r][c], a0[r], b1[c], acc[r][c]);
                    if (dual) {
                        wmma::mma_sync(acc[r][c], a1[r], b0[c], acc[r][c]);
                        wmma::mma_sync(acc[r][c], a2[r], b2[c], acc[r][c]);
                        wmma::mma_sync(acc[r][c], a2[r], b3[c], acc[r][c]);
                    }
                }
        }
    }
    __syncthreads();
    #pragma unroll
    for (int r=0;r<2;r++)
        #pragma unroll
        for (int c=0;c<2;c++)
            wmma::store_matrix_sync(cs + (wr*32+r*16)*64 + wc*32 + c*16, acc[r][c], 64, wmma::mem_row_major);
    __syncthreads();

    const float* bias = (which==0)?pbz : (which==1)?pbr : (which==2)?pbh : pbg;
    float* out = (which==0)?g_pre_z : (which==1)?g_pre_r : (which==2)?g_pre_h : g_gamma;
    for (int i = tid; i < 64*64; i += 128) {
        int rr = i >> 6, cj = i & 63;
        float v = cs[i] + bias[c0 + cj];
        if (which == 3) v = expf(-fmaxf(0.0f, v));
        out[(size_t)(r0+rr)*Hdim + c0 + cj] = v;
    }
}

// ============ persistent wmma scan =========================================
// smem layout (bf16 elements unless noted):
//   sWAh [32][1032]  (66048 B)   resident Uzr_hi slice, col-major [n][k]
//   sWAl [32][1032]  (66048 B)   resident Uzr_lo slice
//   sWBh [16][1032]  (33024 B)   resident U_hi slice
//   sA_hi[128][72]   (18432 B)   staged A chunk
//   sA_lo[128][72]   (18432 B)
//   sBl  [16][72]    ( 2304 B)   staged U_lo chunk (phase B)
#define WKS 1032
#define OFF_WAH 0
#define OFF_WAL 66048
#define OFF_WBH 132096
#define OFF_SAH 165120
#define OFF_SAL 183552
#define OFF_SBL 201984
#define SCAN_SMEM 204416

extern "C" __global__ void __launch_bounds__(256, 1) k_scan()
{
    extern __shared__ __align__(16) char sm[];
    bf16* sWAh = (bf16*)(sm + OFF_WAH);
    bf16* sWAl = (bf16*)(sm + OFF_WAL);
    bf16* sWBh = (bf16*)(sm + OFF_WBH);
    bf16* sAh  = (bf16*)(sm + OFF_SAH);
    bf16* sAl  = (bf16*)(sm + OFF_SAL);
    bf16* sBl  = (bf16*)(sm + OFF_SBL);
    float* cs  = (float*)(sm + OFF_SAH);    // epilogue accum (aliases staging)

    const int tid = threadIdx.x;
    const int wid = tid >> 5, lane = tid & 31;
    const int blk = blockIdx.x;
    const int mi = blk >> 6, nj = blk & 63;
    const int r0 = mi * 128;
    const int c0A = nj * 32;                // 0..2047
    const int c0B = nj * 16;                // 0..1023
    const bool isz = (nj < 32);

    // load resident weights (once)
    for (int i = tid; i < 4096; i += 256) {
        int n = i >> 7, k8 = (i & 127) * 8;
        *(uint4*)(sWAh + n*WKS + k8) = *(const uint4*)(g_UzrT_hi + (size_t)(c0A + n)*1024 + k8);
        *(uint4*)(sWAl + n*WKS + k8) = *(const uint4*)(g_UzrT_lo + (size_t)(c0A + n)*1024 + k8);
    }
    for (int i = tid; i < 2048; i += 256) {
        int n = i >> 7, k8 = (i & 127) * 8;
        *(uint4*)(sWBh + n*WKS + k8) = *(const uint4*)(g_UT_hi + (size_t)(c0B + n)*1024 + k8);
    }
    __syncthreads();

    // A-staging thread map: 1024 uint4 per component, 4 per thread
    int aRow[4], aOff[4];
    #pragma unroll
    for (int v = 0; v < 4; v++) {
        int li = tid + 256*v;
        aRow[v] = li >> 3; aOff[v] = (li & 7)*8;
    }
    const int bRow = tid >> 3, bOff = (tid & 7)*8;    // for sBl (threads 0..127)

    wmma::fragment<wmma::accumulator,16,16,16,float> acc[2];
    const int m0 = wid * 16;

    for (int t = 0; t < Tdim; t++) {
        // ================= phase A: hs @ [Uz|Ur] slice =================
        {
            uint4 ph[4], pl[4];
            #pragma unroll
            for (int v = 0; v < 4; v++) {
                size_t g = (size_t)(r0 + aRow[v])*1024 + aOff[v];
                ph[v] = __ldcg((const uint4*)(g_hs_hi + g));
                pl[v] = __ldcg((const uint4*)(g_hs_lo + g));
            }
            wmma::fill_fragment(acc[0], 0.0f);
            wmma::fill_fragment(acc[1], 0.0f);

            for (int kc = 0; kc < 16; kc++) {
                __syncthreads();
                #pragma unroll
                for (int v = 0; v < 4; v++) {
                    *(uint4*)(sAh + aRow[v]*72 + aOff[v]) = ph[v];
                    *(uint4*)(sAl + aRow[v]*72 + aOff[v]) = pl[v];
                }
                __syncthreads();
                if (kc < 15) {
                    #pragma unroll
                    for (int v = 0; v < 4; v++) {
                        size_t g = (size_t)(r0 + aRow[v])*1024 + (kc+1)*64 + aOff[v];
                        ph[v] = __ldcg((const uint4*)(g_hs_hi + g));
                        pl[v] = __ldcg((const uint4*)(g_hs_lo + g));
                    }
                }
                #pragma unroll
                for (int kf = 0; kf < 4; kf++) {
                    const int k0 = kf*16;
                    wmma::fragment<wmma::matrix_a,16,16,16,bf16,wmma::row_major> ah, al;
                    wmma::load_matrix_sync(ah, sAh + m0*72 + k0, 72);
                    wmma::load_matrix_sync(al, sAl + m0*72 + k0, 72);
                    #pragma unroll
                    for (int nf = 0; nf < 2; nf++) {
                        wmma::fragment<wmma::matrix_b,16,16,16,bf16,wmma::col_major> bh, bl;
                        const bf16* wb = sWAh + (nf*16)*WKS + kc*64 + k0;
                        const bf16* wl = sWAl + (nf*16)*WKS + kc*64 + k0;
                        wmma::load_matrix_sync(bh, wb, WKS);
                        wmma::load_matrix_sync(bl, wl, WKS);
                        wmma::mma_sync(acc[nf], ah, bh, acc[nf]);
                        wmma::mma_sync(acc[nf], ah, bl, acc[nf]);
                        wmma::mma_sync(acc[nf], al, bh, acc[nf]);
                    }
                }
            }
            __syncthreads();
            wmma::store_matrix_sync(cs + m0*32 +  0, acc[0], 32, wmma::mem_row_major);
            wmma::store_matrix_sync(cs + m0*32 + 16, acc[1], 32, wmma::mem_row_major);
            __syncthreads();

            if (isz) {
                for (int i = tid; i < 128*32; i += 256) {
                    int rr = i >> 5, cj = i & 31;
                    int row = r0 + rr, c = c0A + cj;
                    float v = g_pre_z[((size_t)row*Tdim + t)*Hdim + c] + cs[i];
                    g_z[row*Hdim + c] = 1.0f/(1.0f + expf(-v));
                }
            } else {
                for (int i = tid; i < 128*32; i += 256) {
                    int rr = i >> 5, cj = i & 31;
                    int row = r0 + rr, c = c0A - 1024 + cj;
                    float v = g_pre_r[((size_t)row*Tdim + t)*Hdim + c] + cs[i];
                    float s = 1.0f/(1.0f + expf(-v));
                    int idx = row*Hdim + c;
                    float rh = s * __ldcg(&g_hs[idx]);
                    bf16 hi, lo; split2(rh, hi, lo);
                    g_rh_hi[idx] = hi; g_rh_lo[idx] = lo;
                }
            }
        }
        grid_sync();

        // ================= phase B: rh @ U slice + state update =========
        {
            uint4 ph[4], pl[4], pw;
            #pragma unroll
            for (int v = 0; v < 4; v++) {
                size_t g = (size_t)(r0 + aRow[v])*1024 + aOff[v];
                ph[v] = __ldcg((const uint4*)(g_rh_hi + g));
                pl[v] = __ldcg((const uint4*)(g_rh_lo + g));
            }
            if (tid < 128)
                pw = *(const uint4*)(g_UT_lo + (size_t)(c0B + bRow)*1024 + bOff);
            wmma::fill_fragment(acc[0], 0.0f);

            for (int kc = 0; kc < 16; kc++) {
                __syncthreads();
                #pragma unroll
                for (int v = 0; v < 4; v++) {
                    *(uint4*)(sAh + aRow[v]*72 + aOff[v]) = ph[v];
                    *(uint4*)(sAl + aRow[v]*72 + aOff[v]) = pl[v];
                }
                if (tid < 128)
                    *(uint4*)(sBl + bRow*72 + bOff) = pw;
                __syncthreads();
                if (kc < 15) {
                    #pragma unroll
                    for (int v = 0; v < 4; v++) {
                        size_t g = (size_t)(r0 + aRow[v])*1024 + (kc+1)*64 + aOff[v];
                        ph[v] = __ldcg((const uint4*)(g_rh_hi + g));
                        pl[v] = __ldcg((const uint4*)(g_rh_lo + g));
                    }
                    if (tid < 128)
                        pw = *(const uint4*)(g_UT_lo + (size_t)(c0B + bRow)*1024 + (kc+1)*64 + bOff);
                }
                #pragma unroll
                for (int kf = 0; kf < 4; kf++) {
                    const int k0 = kf*16;
                    wmma::fragment<wmma::matrix_a,16,16,16,bf16,wmma::row_major> ah, al;
                    wmma::load_matrix_sync(ah, sAh + m0*72 + k0, 72);
                    wmma::load_matrix_sync(al, sAl + m0*72 + k0, 72);
                    wmma::fragment<wmma::matrix_b,16,16,16,bf16,wmma::col_major> bh, bl;
                    wmma::load_matrix_sync(bh, sWBh + kc*64 + k0, WKS);
                    wmma::load_matrix_sync(bl, sBl + k0, 72);
                    wmma::mma_sync(acc[0], ah, bh, acc[0]);
                    wmma::mma_sync(acc[0], ah, bl, acc[0]);
                    wmma::mma_sync(acc[0], al, bh, acc[0]);
                }
            }
            __syncthreads();
            wmma::store_matrix_sync(cs + m0*16, acc[0], 16, wmma::mem_row_major);
            __syncthreads();

            for (int i = tid; i < 128*16; i += 256) {
                int rr = i >> 4, cj = i & 15;
                int row = r0 + rr, c = c0B + cj;
                int idx = row*Hdim + c;
                float ht = tanhf(g_pre_h[((size_t)row*Tdim + t)*Hdim + c] + cs[i]);
                float hs = __ldcg(&g_hs[idx]);
                float zv = __ldcg(&g_z[idx]);
                float hn = (1.0f - zv)*hs + zv*ht;
                if (t == Tdim-1) g_h[idx] = hn;
                float gn = (t+1 < Tdim) ? g_gamma[((size_t)row*Tdim + (t+1))*Hdim + c] : 1.0f;
                float nh = gn*hn;
                g_hs[idx] = nh;
                bf16 hi, lo; split2(nh, hi, lo);
                g_hs_hi[idx] = hi; g_hs_lo[idx] = lo;
            }
        }
        grid_sync();
    }
}

// ---------------- decoder ---------------------------------------------------
__global__ void k_dec(const float* __restrict__ dW, const float* __restrict__ db,
                      float* __restrict__ out)
{
    __shared__ float hrow[Hdim];
    int b = blockIdx.x;
    for (int i = threadIdx.x; i < Hdim; i += blockDim.x)
        hrow[i] = g_h[b*Hdim + i];
    __syncthreads();
    int o = threadIdx.x;
    float acc = db[o];
    #pragma unroll 8
    for (int k = 0; k < Hdim; k++)
        acc += hrow[k]*dW[k*Odim + o];
    out[b*Odim + o] = acc;
}

// ---------------- launch ----------------------------------------------------
extern "C" void kernel_launch(void* const* d_in, const int* in_sizes, int n_in,
                              void* d_out, int out_size)
{
    const float* x     = (const float*)d_in[0];
    const float* delta = (const float*)d_in[1];
    const float* m     = (const float*)d_in[2];
    const float* W_r   = (const float*)d_in[3];
    const float* U_r   = (const float*)d_in[4];
    const float* V_r   = (const float*)d_in[5];
    const float* b_r   = (const float*)d_in[6];
    const float* W_z   = (const float*)d_in[7];
    const float* U_z   = (const float*)d_in[8];
    const float* V_z   = (const float*)d_in[9];
    const float* b_z   = (const float*)d_in[10];
    const float* W     = (const float*)d_in[11];
    const float* U     = (const float*)d_in[12];
    const float* V     = (const float*)d_in[13];
    const float* b     = (const float*)d_in[14];
    const float* Wgx   = (const float*)d_in[15];
    const float* bgx   = (const float*)d_in[16];
    const float* Wgh   = (const float*)d_in[17];
    const float* bgh   = (const float*)d_in[18];
    const float* decW  = (const float*)d_in[19];
    const float* decb  = (const float*)d_in[20];
    float* out = (float*)d_out;

    static int smem_set = 0;
    if (!smem_set) {
        cudaFuncSetAttribute(k_scan, cudaFuncAttributeMaxDynamicSharedMemorySize, SCAN_SMEM);
        smem_set = 1;
    }

    // order keeps k_scan as launch #6 (ncu -s 5 -c 1 captures it)
    k_xmod<<<(BT*Ddim + 255)/256, 256>>>(x, delta, m, Wgx, bgx);
    k_split_small_all<<<(7*DK + 255)/256, 256>>>(W_z, V_z, W_r, V_r, W, V, Wgh);
    k_split_bigT<<<(3*1024*1024 + 255)/256, 256>>>(U_z, U_r, U);
    k_pre<<<dim3(Hdim/64, BT/64, 4), 128>>>(b_z, b_r, b, bgh);
    k_init<<<(Bdim*Hdim + 255)/256, 256>>>();
    k_scan<<<NBLK, 256, SCAN_SMEM>>>();
    k_dec<<<Bdim, Odim>>>(decW, decb, out);
}

// round 8
// speedup vs baseline: 3.3837x; 1.0099x over previous
#include <cuda_runtime.h>
#include <cuda_bf16.h>
#include <mma.h>
#include <math.h>
#include <stdint.h>

using namespace nvcuda;
typedef __nv_bfloat16 bf16;

#define Bdim 256
#define Tdim 256
#define Ddim 128
#define Hdim 1024
#define Odim 64
#define BT (Bdim*Tdim)
#define DK (Ddim*Hdim)
#define NBLK 128

// ---------------- scratch (device globals; allocations forbidden) ----------
// pre_* and gamma are BT-MAJOR: index = ((b*Tdim + t)*Hdim + h)   [R6 layout]
__device__ float g_pre_z[67108864];
__device__ float g_pre_r[67108864];
__device__ float g_pre_h[67108864];
__device__ float g_gamma[67108864];
__device__ float g_hs[Bdim*Hdim];
__device__ float g_h [Bdim*Hdim];
__device__ float g_z [Bdim*Hdim];

__device__ bf16 g_hs_hi[Bdim*Hdim], g_hs_lo[Bdim*Hdim];
__device__ bf16 g_rh_hi[Bdim*Hdim], g_rh_lo[Bdim*Hdim];
__device__ bf16 g_x_hi[BT*Ddim],   g_x_lo[BT*Ddim];
__device__ bf16 g_mb [BT*Ddim];
__device__ bf16 g_mib[BT*Ddim];

// transposed split weights: [n][k], k stride 1024
__device__ bf16 g_UzrT_hi[2048*1024], g_UzrT_lo[2048*1024];
__device__ bf16 g_UT_hi[1024*1024],   g_UT_lo[1024*1024];
__device__ bf16 g_Wsm_hi[7*DK], g_Wsm_lo[7*DK];

__device__ unsigned g_bar_cnt = 0;
__device__ unsigned g_bar_gen = 0;

__device__ __forceinline__ void split2(float v, bf16& hi, bf16& lo) {
    hi = __float2bfloat16(v);
    lo = __float2bfloat16(v - __bfloat162float(hi));
}

// R6-proven grid barrier (atomic spin)
__device__ __forceinline__ void grid_sync() {
    __threadfence();
    __syncthreads();
    if (threadIdx.x == 0) {
        unsigned my = atomicAdd(&g_bar_gen, 0u);
        if (atomicAdd(&g_bar_cnt, 1u) == NBLK - 1u) {
            atomicExch(&g_bar_cnt, 0u);
            atomicAdd(&g_bar_gen, 1u);
        } else {
            while (atomicAdd(&g_bar_gen, 0u) == my) { }
        }
    }
    __syncthreads();
}

// ---------------- fused prep: xmod + all weight splits ----------------------
#define SEG1 8388608u            /* BT*D */
#define SEG2 (SEG1 + 917504u)    /* + 7*DK */
#define SEG3 (SEG2 + 2097152u)   /* + Uzr */
#define SEG4 (SEG3 + 1048576u)   /* + U   */
__global__ void k_prep(const float* __restrict__ x, const float* __restrict__ delta,
                       const float* __restrict__ m, const float* __restrict__ wgx,
                       const float* __restrict__ bgx,
                       const float* __restrict__ Wz, const float* __restrict__ Vz,
                       const float* __restrict__ Wr, const float* __restrict__ Vr,
                       const float* __restrict__ Wh, const float* __restrict__ Vh,
                       const float* __restrict__ Wg,
                       const float* __restrict__ Uz, const float* __restrict__ Ur,
                       const float* __restrict__ U)
{
    unsigned i = blockIdx.x*256u + threadIdx.x;
    if (i < SEG1) {
        int d = i & (Ddim-1);
        float mv = m[i];
        float dec = delta[i]*wgx[d] + bgx[d];
        float xv = (mv > 0.0f) ? (1.0f - dec)*0.001f : x[i];
        split2(xv, g_x_hi[i], g_x_lo[i]);
        g_mb[i]  = __float2bfloat16(mv);
        g_mib[i] = __float2bfloat16(1.0f - mv);
    } else if (i < SEG2) {
        unsigned j2 = i - SEG1;
        int slot = j2 >> 17;
        int j = j2 & (DK-1);
        const float* src = (slot==0)?Wz:(slot==1)?Vz:(slot==2)?Wr:(slot==3)?Vr:(slot==4)?Wh:(slot==5)?Vh:Wg;
        split2(src[j], g_Wsm_hi[j2], g_Wsm_lo[j2]);
    } else if (i < SEG3) {
        unsigned j2 = i - SEG2;
        int n = j2 >> 10, k = j2 & 1023;
        float v = (n < 1024) ? Uz[k*1024 + n] : Ur[k*1024 + (n-1024)];
        split2(v, g_UzrT_hi[j2], g_UzrT_lo[j2]);
    } else {
        unsigned j2 = i - SEG3;
        int n = j2 >> 10, k = j2 & 1023;
        split2(U[k*1024 + n], g_UT_hi[j2], g_UT_lo[j2]);
    }
}

__global__ void k_init() {
    int i = blockIdx.x*blockDim.x + threadIdx.x;
    if (i < Bdim*Hdim) {
        g_hs[i] = 0.0f; g_h[i] = 0.0f;
        g_hs_hi[i] = __float2bfloat16(0.0f);
        g_hs_lo[i] = __float2bfloat16(0.0f);
    }
    if (i == 0) { g_bar_cnt = 0; g_bar_gen = 0; }
}

// ============ precompute GEMMs (R6 version, bt-major outputs) ===============
__global__ void __launch_bounds__(128) k_pre(const float* __restrict__ pbz,
                                             const float* __restrict__ pbr,
                                             const float* __restrict__ pbh,
                                             const float* __restrict__ pbg)
{
    __shared__ __align__(16) char smem_raw[33792];
    bf16* sA0 = (bf16*)smem_raw;
    bf16* sA1 = sA0 + 64*40;
    bf16* sA2 = sA1 + 64*40;
    bf16* sB0 = sA2 + 64*40;
    bf16* sB1 = sB0 + 32*72;
    bf16* sB2 = sB1 + 32*72;
    bf16* sB3 = sB2 + 32*72;
    float* cs = (float*)smem_raw;

    const int which = blockIdx.z;
    const bool dual = (which < 3);
    const int tid = threadIdx.x;
    const int wid = tid >> 5;
    const int wr = wid >> 1, wc = wid & 1;
    const int r0 = blockIdx.y*64, c0 = blockIdx.x*64;

    const bf16 *Wh_p, *Wl_p, *Vh_p = nullptr, *Vl_p = nullptr;
    if (dual) {
        Wh_p = g_Wsm_hi + (size_t)(which*2)*DK;   Wl_p = g_Wsm_lo + (size_t)(which*2)*DK;
        Vh_p = g_Wsm_hi + (size_t)(which*2+1)*DK; Vl_p = g_Wsm_lo + (size_t)(which*2+1)*DK;
    } else {
        Wh_p = g_Wsm_hi + (size_t)6*DK;           Wl_p = g_Wsm_lo + (size_t)6*DK;
    }

    wmma::fragment<wmma::accumulator,16,16,16,float> acc[2][2];
    #pragma unroll
    for (int r=0;r<2;r++)
        #pragma unroll
        for (int c=0;c<2;c++) wmma::fill_fragment(acc[r][c], 0.0f);

    int aRow[2], aOff[2], bRow[2], bOff[2];
    #pragma unroll
    for (int j=0;j<2;j++) {
        int li = tid + 128*j;
        aRow[j] = li >> 2; aOff[j] = (li & 3)*8;
        bRow[j] = li >> 3; bOff[j] = (li & 7)*8;
    }

    for (int kk = 0; kk < Ddim; kk += 32) {
        __syncthreads();
        #pragma unroll
        for (int j=0;j<2;j++) {
            size_t ga = (size_t)(r0 + aRow[j])*Ddim + kk + aOff[j];
            size_t gb = (size_t)(kk + bRow[j])*Hdim + c0 + bOff[j];
            if (dual) {
                *(uint4*)(sA0 + aRow[j]*40 + aOff[j]) = *(const uint4*)(g_x_hi + ga);
                *(uint4*)(sA1 + aRow[j]*40 + aOff[j]) = *(const uint4*)(g_x_lo + ga);
                *(uint4*)(sA2 + aRow[j]*40 + aOff[j]) = *(const uint4*)(g_mib + ga);
                *(uint4*)(sB2 + bRow[j]*72 + bOff[j]) = *(const uint4*)(Vh_p + gb);
                *(uint4*)(sB3 + bRow[j]*72 + bOff[j]) = *(const uint4*)(Vl_p + gb);
            } else {
                *(uint4*)(sA0 + aRow[j]*40 + aOff[j]) = *(const uint4*)(g_mb + ga);
            }
            *(uint4*)(sB0 + bRow[j]*72 + bOff[j]) = *(const uint4*)(Wh_p + gb);
            *(uint4*)(sB1 + bRow[j]*72 + bOff[j]) = *(const uint4*)(Wl_p + gb);
        }
        __syncthreads();
        #pragma unroll
        for (int ks=0; ks<32; ks+=16) {
            wmma::fragment<wmma::matrix_a,16,16,16,bf16,wmma::row_major> a0[2], a1[2], a2[2];
            wmma::fragment<wmma::matrix_b,16,16,16,bf16,wmma::row_major> b0[2], b1[2], b2[2], b3[2];
            #pragma unroll
            for (int r=0;r<2;r++) {
                wmma::load_matrix_sync(a0[r], sA0 + (wr*32+r*16)*40 + ks, 40);
                if (dual) {
                    wmma::load_matrix_sync(a1[r], sA1 + (wr*32+r*16)*40 + ks, 40);
                    wmma::load_matrix_sync(a2[r], sA2 + (wr*32+r*16)*40 + ks, 40);
                }
            }
            #pragma unroll
            for (int c=0;c<2;c++) {
                wmma::load_matrix_sync(b0[c], sB0 + ks*72 + wc*32 + c*16, 72);
                wmma::load_matrix_sync(b1[c], sB1 + ks*72 + wc*32 + c*16, 72);
                if (dual) {
                    wmma::load_matrix_sync(b2[c], sB2 + ks*72 + wc*32 + c*16, 72);
                    wmma::load_matrix_sync(b3[c], sB3 + ks*72 + wc*32 + c*16, 72);
                }
            }
            #pragma unroll
            for (int r=0;r<2;r++)
                #pragma unroll
                for (int c=0;c<2;c++) {
                    wmma::mma_sync(acc[r][c], a0[r], b0[c], acc[r][c]);
                    wmma::mma_sync(acc[r][c], a0[r], b1[c], acc[r][c]);
                    if (dual) {
                        wmma::mma_sync(acc[r][c], a1[r], b0[c], acc[r][c]);
                        wmma::mma_sync(acc[r][c], a2[r], b2[c], acc[r][c]);
                        wmma::mma_sync(acc[r][c], a2[r], b3[c], acc[r][c]);
                    }
                }
        }
    }
    __syncthreads();
    #pragma unroll
    for (int r=0;r<2;r++)
        #pragma unroll
        for (int c=0;c<2;c++)
            wmma::store_matrix_sync(cs + (wr*32+r*16)*64 + wc*32 + c*16, acc[r][c], 64, wmma::mem_row_major);
    __syncthreads();

    const float* bias = (which==0)?pbz : (which==1)?pbr : (which==2)?pbh : pbg;
    float* out = (which==0)?g_pre_z : (which==1)?g_pre_r : (which==2)?g_pre_h : g_gamma;
    for (int i = tid; i < 64*64; i += 128) {
        int rr = i >> 6, cj = i & 63;
        float v = cs[i] + bias[c0 + cj];
        if (which == 3) v = expf(-fmaxf(0.0f, v));
        out[(size_t)(r0+rr)*Hdim + c0 + cj] = v;
    }
}

// ============ persistent wmma scan (R6 version, verbatim) ===================
#define WKS 1032
#define OFF_WAH 0
#define OFF_WAL 66048
#define OFF_WBH 132096
#define OFF_SAH 165120
#define OFF_SAL 183552
#define OFF_SBL 201984
#define SCAN_SMEM 204416

extern "C" __global__ void __launch_bounds__(256, 1) k_scan()
{
    extern __shared__ __align__(16) char sm[];
    bf16* sWAh = (bf16*)(sm + OFF_WAH);
    bf16* sWAl = (bf16*)(sm + OFF_WAL);
    bf16* sWBh = (bf16*)(sm + OFF_WBH);
    bf16* sAh  = (bf16*)(sm + OFF_SAH);
    bf16* sAl  = (bf16*)(sm + OFF_SAL);
    bf16* sBl  = (bf16*)(sm + OFF_SBL);
    float* cs  = (float*)(sm + OFF_SAH);

    const int tid = threadIdx.x;
    const int wid = tid >> 5;
    const int blk = blockIdx.x;
    const int mi = blk >> 6, nj = blk & 63;
    const int r0 = mi * 128;
    const int c0A = nj * 32;
    const int c0B = nj * 16;
    const bool isz = (nj < 32);

    for (int i = tid; i < 4096; i += 256) {
        int n = i >> 7, k8 = (i & 127) * 8;
        *(uint4*)(sWAh + n*WKS + k8) = *(const uint4*)(g_UzrT_hi + (size_t)(c0A + n)*1024 + k8);
        *(uint4*)(sWAl + n*WKS + k8) = *(const uint4*)(g_UzrT_lo + (size_t)(c0A + n)*1024 + k8);
    }
    for (int i = tid; i < 2048; i += 256) {
        int n = i >> 7, k8 = (i & 127) * 8;
        *(uint4*)(sWBh + n*WKS + k8) = *(const uint4*)(g_UT_hi + (size_t)(c0B + n)*1024 + k8);
    }
    __syncthreads();

    int aRow[4], aOff[4];
    #pragma unroll
    for (int v = 0; v < 4; v++) {
        int li = tid + 256*v;
        aRow[v] = li >> 3; aOff[v] = (li & 7)*8;
    }
    const int bRow = tid >> 3, bOff = (tid & 7)*8;

    wmma::fragment<wmma::accumulator,16,16,16,float> acc[2];
    const int m0 = wid * 16;

    for (int t = 0; t < Tdim; t++) {
        // ================= phase A: hs @ [Uz|Ur] slice =================
        {
            uint4 ph[4], pl[4];
            #pragma unroll
            for (int v = 0; v < 4; v++) {
                size_t g = (size_t)(r0 + aRow[v])*1024 + aOff[v];
                ph[v] = __ldcg((const uint4*)(g_hs_hi + g));
                pl[v] = __ldcg((const uint4*)(g_hs_lo + g));
            }
            wmma::fill_fragment(acc[0], 0.0f);
            wmma::fill_fragment(acc[1], 0.0f);

            for (int kc = 0; kc < 16; kc++) {
                __syncthreads();
                #pragma unroll
                for (int v = 0; v < 4; v++) {
                    *(uint4*)(sAh + aRow[v]*72 + aOff[v]) = ph[v];
                    *(uint4*)(sAl + aRow[v]*72 + aOff[v]) = pl[v];
                }
                __syncthreads();
                if (kc < 15) {
                    #pragma unroll
                    for (int v = 0; v < 4; v++) {
                        size_t g = (size_t)(r0 + aRow[v])*1024 + (kc+1)*64 + aOff[v];
                        ph[v] = __ldcg((const uint4*)(g_hs_hi + g));
                        pl[v] = __ldcg((const uint4*)(g_hs_lo + g));
                    }
                }
                #pragma unroll
                for (int kf = 0; kf < 4; kf++) {
                    const int k0 = kf*16;
                    wmma::fragment<wmma::matrix_a,16,16,16,bf16,wmma::row_major> ah, al;
                    wmma::load_matrix_sync(ah, sAh + m0*72 + k0, 72);
                    wmma::load_matrix_sync(al, sAl + m0*72 + k0, 72);
                    #pragma unroll
                    for (int nf = 0; nf < 2; nf++) {
                        wmma::fragment<wmma::matrix_b,16,16,16,bf16,wmma::col_major> bh, bl;
                        wmma::load_matrix_sync(bh, sWAh + (nf*16)*WKS + kc*64 + k0, WKS);
                        wmma::load_matrix_sync(bl, sWAl + (nf*16)*WKS + kc*64 + k0, WKS);
                        wmma::mma_sync(acc[nf], ah, bh, acc[nf]);
                        wmma::mma_sync(acc[nf], ah, bl, acc[nf]);
                        wmma::mma_sync(acc[nf], al, bh, acc[nf]);
                    }
                }
            }
            __syncthreads();
            wmma::store_matrix_sync(cs + m0*32 +  0, acc[0], 32, wmma::mem_row_major);
            wmma::store_matrix_sync(cs + m0*32 + 16, acc[1], 32, wmma::mem_row_major);
            __syncthreads();

            if (isz) {
                for (int i = tid; i < 128*32; i += 256) {
                    int rr = i >> 5, cj = i & 31;
                    int row = r0 + rr, c = c0A + cj;
                    float v = g_pre_z[((size_t)row*Tdim + t)*Hdim + c] + cs[i];
                    g_z[row*Hdim + c] = 1.0f/(1.0f + expf(-v));
                }
            } else {
                for (int i = tid; i < 128*32; i += 256) {
                    int rr = i >> 5, cj = i & 31;
                    int row = r0 + rr, c = c0A - 1024 + cj;
                    float v = g_pre_r[((size_t)row*Tdim + t)*Hdim + c] + cs[i];
                    float s = 1.0f/(1.0f + expf(-v));
                    int idx = row*Hdim + c;
                    float rh = s * __ldcg(&g_hs[idx]);
                    bf16 hi, lo; split2(rh, hi, lo);
                    g_rh_hi[idx] = hi; g_rh_lo[idx] = lo;
                }
            }
        }
        grid_sync();

        // ================= phase B: rh @ U slice + state update =========
        {
            uint4 ph[4], pl[4], pw;
            #pragma unroll
            for (int v = 0; v < 4; v++) {
                size_t g = (size_t)(r0 + aRow[v])*1024 + aOff[v];
                ph[v] = __ldcg((const uint4*)(g_rh_hi + g));
                pl[v] = __ldcg((const uint4*)(g_rh_lo + g));
            }
            if (tid < 128)
                pw = *(const uint4*)(g_UT_lo + (size_t)(c0B + bRow)*1024 + bOff);
            wmma::fill_fragment(acc[0], 0.0f);

            for (int kc = 0; kc < 16; kc++) {
                __syncthreads();
                #pragma unroll
                for (int v = 0; v < 4; v++) {
                    *(uint4*)(sAh + aRow[v]*72 + aOff[v]) = ph[v];
                    *(uint4*)(sAl + aRow[v]*72 + aOff[v]) = pl[v];
                }
                if (tid < 128)
                    *(uint4*)(sBl + bRow*72 + bOff) = pw;
                __syncthreads();
                if (kc < 15) {
                    #pragma unroll
                    for (int v = 0; v < 4; v++) {
                        size_t g = (size_t)(r0 + aRow[v])*1024 + (kc+1)*64 + aOff[v];
                        ph[v] = __ldcg((const uint4*)(g_rh_hi + g));
                        pl[v] = __ldcg((const uint4*)(g_rh_lo + g));
                    }
                    if (tid < 128)
                        pw = *(const uint4*)(g_UT_lo + (size_t)(c0B + bRow)*1024 + (kc+1)*64 + bOff);
                }
                #pragma unroll
                for (int kf = 0; kf < 4; kf++) {
                    const int k0 = kf*16;
                    wmma::fragment<wmma::matrix_a,16,16,16,bf16,wmma::row_major> ah, al;
                    wmma::load_matrix_sync(ah, sAh + m0*72 + k0, 72);
                    wmma::load_matrix_sync(al, sAl + m0*72 + k0, 72);
                    wmma::fragment<wmma::matrix_b,16,16,16,bf16,wmma::col_major> bh, bl;
                    wmma::load_matrix_sync(bh, sWBh + kc*64 + k0, WKS);
                    wmma::load_matrix_sync(bl, sBl + k0, 72);
                    wmma::mma_sync(acc[0], ah, bh, acc[0]);
                    wmma::mma_sync(acc[0], ah, bl, acc[0]);
                    wmma::mma_sync(acc[0], al, bh, acc[0]);
                }
            }
            __syncthreads();
            wmma::store_matrix_sync(cs + m0*16, acc[0], 16, wmma::mem_row_major);
            __syncthreads();

            for (int i = tid; i < 128*16; i += 256) {
                int rr = i >> 4, cj = i & 15;
                int row = r0 + rr, c = c0B + cj;
                int idx = row*Hdim + c;
                float ht = tanhf(g_pre_h[((size_t)row*Tdim + t)*Hdim + c] + cs[i]);
                float hs = __ldcg(&g_hs[idx]);
                float zv = __ldcg(&g_z[idx]);
                float hn = (1.0f - zv)*hs + zv*ht;
                if (t == Tdim-1) g_h[idx] = hn;
                float gn = (t+1 < Tdim) ? g_gamma[((size_t)row*Tdim + (t+1))*Hdim + c] : 1.0f;
                float nh = gn*hn;
                g_hs[idx] = nh;
                bf16 hi, lo; split2(nh, hi, lo);
                g_hs_hi[idx] = hi; g_hs_lo[idx] = lo;
            }
        }
        grid_sync();
    }
}

// ---------------- decoder ---------------------------------------------------
__global__ void k_dec(const float* __restrict__ dW, const float* __restrict__ db,
                      float* __restrict__ out)
{
    __shared__ float hrow[Hdim];
    int b = blockIdx.x;
    for (int i = threadIdx.x; i < Hdim; i += blockDim.x)
        hrow[i] = g_h[b*Hdim + i];
    __syncthreads();
    int o = threadIdx.x;
    float acc = db[o];
    #pragma unroll 8
    for (int k = 0; k < Hdim; k++)
        acc += hrow[k]*dW[k*Odim + o];
    out[b*Odim + o] = acc;
}

// ---------------- launch ----------------------------------------------------
extern "C" void kernel_launch(void* const* d_in, const int* in_sizes, int n_in,
                              void* d_out, int out_size)
{
    const float* x     = (const float*)d_in[0];
    const float* delta = (const float*)d_in[1];
    const float* m     = (const float*)d_in[2];
    const float* W_r   = (const float*)d_in[3];
    const float* U_r   = (const float*)d_in[4];
    const float* V_r   = (const float*)d_in[5];
    const float* b_r   = (const float*)d_in[6];
    const float* W_z   = (const float*)d_in[7];
    const float* U_z   = (const float*)d_in[8];
    const float* V_z   = (const float*)d_in[9];
    const float* b_z   = (const float*)d_in[10];
    const float* W     = (const float*)d_in[11];
    const float* U     = (const float*)d_in[12];
    const float* V     = (const float*)d_in[13];
    const float* b     = (const float*)d_in[14];
    const float* Wgx   = (const float*)d_in[15];
    const float* bgx   = (const float*)d_in[16];
    const float* Wgh   = (const float*)d_in[17];
    const float* bgh   = (const float*)d_in[18];
    const float* decW  = (const float*)d_in[19];
    const float* decb  = (const float*)d_in[20];
    float* out = (float*)d_out;

    static int smem_set = 0;
    if (!smem_set) {
        cudaFuncSetAttribute(k_scan, cudaFuncAttributeMaxDynamicSharedMemorySize, SCAN_SMEM);
        smem_set = 1;
    }

    // launch order: k_scan is launch #4 (observed ncu capture point)
    k_prep<<<SEG4/256, 256>>>(x, delta, m, Wgx, bgx,
                              W_z, V_z, W_r, V_r, W, V, Wgh, U_z, U_r, U);
    k_pre<<<dim3(Hdim/64, BT/64, 4), 128>>>(b_z, b_r, b, bgh);
    k_init<<<(Bdim*Hdim + 255)/256, 256>>>();
    k_scan<<<NBLK, 256, SCAN_SMEM>>>();
    k_dec<<<Bdim, Odim>>>(decW, decb, out);
}

// round 9
// speedup vs baseline: 4.1724x; 1.2331x over previous
#include <cuda_runtime.h>
#include <cuda_bf16.h>
#include <mma.h>
#include <math.h>
#include <stdint.h>

using namespace nvcuda;
typedef __nv_bfloat16 bf16;

#define Bdim 256
#define Tdim 256
#define Ddim 128
#define Hdim 1024
#define Odim 64
#define BT (Bdim*Tdim)
#define DK (Ddim*Hdim)
#define NBLK 128
#define SCANT 512

// ---------------- scratch (device globals; allocations forbidden) ----------
// pre_* and gamma are BT-MAJOR: index = ((b*Tdim + t)*Hdim + h)
__device__ float g_pre_z[67108864];
__device__ float g_pre_r[67108864];
__device__ float g_pre_h[67108864];
__device__ float g_gamma[67108864];
__device__ float g_hs[Bdim*Hdim];
__device__ float g_h [Bdim*Hdim];
__device__ float g_z [Bdim*Hdim];

__device__ bf16 g_hs_hi[Bdim*Hdim], g_hs_lo[Bdim*Hdim];
__device__ bf16 g_rh_hi[Bdim*Hdim], g_rh_lo[Bdim*Hdim];
__device__ bf16 g_x_hi[BT*Ddim],   g_x_lo[BT*Ddim];
__device__ bf16 g_mb [BT*Ddim];
__device__ bf16 g_mib[BT*Ddim];

// transposed split weights: [n][k], k stride 1024
__device__ bf16 g_UzrT_hi[2048*1024], g_UzrT_lo[2048*1024];
__device__ bf16 g_UT_hi[1024*1024],   g_UT_lo[1024*1024];
__device__ bf16 g_Wsm_hi[7*DK], g_Wsm_lo[7*DK];

__device__ unsigned g_bar_cnt = 0;
__device__ unsigned g_bar_gen = 0;

__device__ __forceinline__ void split2(float v, bf16& hi, bf16& lo) {
    hi = __float2bfloat16(v);
    lo = __float2bfloat16(v - __bfloat162float(hi));
}

__device__ __forceinline__ void grid_sync() {
    __threadfence();
    __syncthreads();
    if (threadIdx.x == 0) {
        unsigned my = atomicAdd(&g_bar_gen, 0u);
        if (atomicAdd(&g_bar_cnt, 1u) == NBLK - 1u) {
            atomicExch(&g_bar_cnt, 0u);
            atomicAdd(&g_bar_gen, 1u);
        } else {
            while (atomicAdd(&g_bar_gen, 0u) == my) { }
        }
    }
    __syncthreads();
}

// ---------------- fused prep: xmod + all weight splits ----------------------
#define SEG1 8388608u
#define SEG2 (SEG1 + 917504u)
#define SEG3 (SEG2 + 2097152u)
#define SEG4 (SEG3 + 1048576u)
__global__ void k_prep(const float* __restrict__ x, const float* __restrict__ delta,
                       const float* __restrict__ m, const float* __restrict__ wgx,
                       const float* __restrict__ bgx,
                       const float* __restrict__ Wz, const float* __restrict__ Vz,
                       const float* __restrict__ Wr, const float* __restrict__ Vr,
                       const float* __restrict__ Wh, const float* __restrict__ Vh,
                       const float* __restrict__ Wg,
                       const float* __restrict__ Uz, const float* __restrict__ Ur,
                       const float* __restrict__ U)
{
    unsigned i = blockIdx.x*256u + threadIdx.x;
    if (i < SEG1) {
        int d = i & (Ddim-1);
        float mv = m[i];
        float dec = delta[i]*wgx[d] + bgx[d];
        float xv = (mv > 0.0f) ? (1.0f - dec)*0.001f : x[i];
        split2(xv, g_x_hi[i], g_x_lo[i]);
        g_mb[i]  = __float2bfloat16(mv);
        g_mib[i] = __float2bfloat16(1.0f - mv);
    } else if (i < SEG2) {
        unsigned j2 = i - SEG1;
        int slot = j2 >> 17;
        int j = j2 & (DK-1);
        const float* src = (slot==0)?Wz:(slot==1)?Vz:(slot==2)?Wr:(slot==3)?Vr:(slot==4)?Wh:(slot==5)?Vh:Wg;
        split2(src[j], g_Wsm_hi[j2], g_Wsm_lo[j2]);
    } else if (i < SEG3) {
        unsigned j2 = i - SEG2;
        int n = j2 >> 10, k = j2 & 1023;
        float v = (n < 1024) ? Uz[k*1024 + n] : Ur[k*1024 + (n-1024)];
        split2(v, g_UzrT_hi[j2], g_UzrT_lo[j2]);
    } else {
        unsigned j2 = i - SEG3;
        int n = j2 >> 10, k = j2 & 1023;
        split2(U[k*1024 + n], g_UT_hi[j2], g_UT_lo[j2]);
    }
}

__global__ void k_init() {
    int i = blockIdx.x*blockDim.x + threadIdx.x;
    if (i < Bdim*Hdim) {
        g_hs[i] = 0.0f; g_h[i] = 0.0f;
        g_hs_hi[i] = __float2bfloat16(0.0f);
        g_hs_lo[i] = __float2bfloat16(0.0f);
    }
    if (i == 0) { g_bar_cnt = 0; g_bar_gen = 0; }
}

// ============ precompute GEMMs (unchanged) ==================================
__global__ void __launch_bounds__(128) k_pre(const float* __restrict__ pbz,
                                             const float* __restrict__ pbr,
                                             const float* __restrict__ pbh,
                                             const float* __restrict__ pbg)
{
    __shared__ __align__(16) char smem_raw[33792];
    bf16* sA0 = (bf16*)smem_raw;
    bf16* sA1 = sA0 + 64*40;
    bf16* sA2 = sA1 + 64*40;
    bf16* sB0 = sA2 + 64*40;
    bf16* sB1 = sB0 + 32*72;
    bf16* sB2 = sB1 + 32*72;
    bf16* sB3 = sB2 + 32*72;
    float* cs = (float*)smem_raw;

    const int which = blockIdx.z;
    const bool dual = (which < 3);
    const int tid = threadIdx.x;
    const int wid = tid >> 5;
    const int wr = wid >> 1, wc = wid & 1;
    const int r0 = blockIdx.y*64, c0 = blockIdx.x*64;

    const bf16 *Wh_p, *Wl_p, *Vh_p = nullptr, *Vl_p = nullptr;
    if (dual) {
        Wh_p = g_Wsm_hi + (size_t)(which*2)*DK;   Wl_p = g_Wsm_lo + (size_t)(which*2)*DK;
        Vh_p = g_Wsm_hi + (size_t)(which*2+1)*DK; Vl_p = g_Wsm_lo + (size_t)(which*2+1)*DK;
    } else {
        Wh_p = g_Wsm_hi + (size_t)6*DK;           Wl_p = g_Wsm_lo + (size_t)6*DK;
    }

    wmma::fragment<wmma::accumulator,16,16,16,float> acc[2][2];
    #pragma unroll
    for (int r=0;r<2;r++)
        #pragma unroll
        for (int c=0;c<2;c++) wmma::fill_fragment(acc[r][c], 0.0f);

    int aRow[2], aOff[2], bRow[2], bOff[2];
    #pragma unroll
    for (int j=0;j<2;j++) {
        int li = tid + 128*j;
        aRow[j] = li >> 2; aOff[j] = (li & 3)*8;
        bRow[j] = li >> 3; bOff[j] = (li & 7)*8;
    }

    for (int kk = 0; kk < Ddim; kk += 32) {
        __syncthreads();
        #pragma unroll
        for (int j=0;j<2;j++) {
            size_t ga = (size_t)(r0 + aRow[j])*Ddim + kk + aOff[j];
            size_t gb = (size_t)(kk + bRow[j])*Hdim + c0 + bOff[j];
            if (dual) {
                *(uint4*)(sA0 + aRow[j]*40 + aOff[j]) = *(const uint4*)(g_x_hi + ga);
                *(uint4*)(sA1 + aRow[j]*40 + aOff[j]) = *(const uint4*)(g_x_lo + ga);
                *(uint4*)(sA2 + aRow[j]*40 + aOff[j]) = *(const uint4*)(g_mib + ga);
                *(uint4*)(sB2 + bRow[j]*72 + bOff[j]) = *(const uint4*)(Vh_p + gb);
                *(uint4*)(sB3 + bRow[j]*72 + bOff[j]) = *(const uint4*)(Vl_p + gb);
            } else {
                *(uint4*)(sA0 + aRow[j]*40 + aOff[j]) = *(const uint4*)(g_mb + ga);
            }
            *(uint4*)(sB0 + bRow[j]*72 + bOff[j]) = *(const uint4*)(Wh_p + gb);
            *(uint4*)(sB1 + bRow[j]*72 + bOff[j]) = *(const uint4*)(Wl_p + gb);
        }
        __syncthreads();
        #pragma unroll
        for (int ks=0; ks<32; ks+=16) {
            wmma::fragment<wmma::matrix_a,16,16,16,bf16,wmma::row_major> a0[2], a1[2], a2[2];
            wmma::fragment<wmma::matrix_b,16,16,16,bf16,wmma::row_major> b0[2], b1[2], b2[2], b3[2];
            #pragma unroll
            for (int r=0;r<2;r++) {
                wmma::load_matrix_sync(a0[r], sA0 + (wr*32+r*16)*40 + ks, 40);
                if (dual) {
                    wmma::load_matrix_sync(a1[r], sA1 + (wr*32+r*16)*40 + ks, 40);
                    wmma::load_matrix_sync(a2[r], sA2 + (wr*32+r*16)*40 + ks, 40);
                }
            }
            #pragma unroll
            for (int c=0;c<2;c++) {
                wmma::load_matrix_sync(b0[c], sB0 + ks*72 + wc*32 + c*16, 72);
                wmma::load_matrix_sync(b1[c], sB1 + ks*72 + wc*32 + c*16, 72);
                if (dual) {
                    wmma::load_matrix_sync(b2[c], sB2 + ks*72 + wc*32 + c*16, 72);
                    wmma::load_matrix_sync(b3[c], sB3 + ks*72 + wc*32 + c*16, 72);
                }
            }
            #pragma unroll
            for (int r=0;r<2;r++)
                #pragma unroll
                for (int c=0;c<2;c++) {
                    wmma::mma_sync(acc[r][c], a0[r], b0[c], acc[r][c]);
                    wmma::mma_sync(acc[r][c], a0[r], b1[c], acc[r][c]);
                    if (dual) {
                        wmma::mma_sync(acc[r][c], a1[r], b0[c], acc[r][c]);
                        wmma::mma_sync(acc[r][c], a2[r], b2[c], acc[r][c]);
                        wmma::mma_sync(acc[r][c], a2[r], b3[c], acc[r][c]);
                    }
                }
        }
    }
    __syncthreads();
    #pragma unroll
    for (int r=0;r<2;r++)
        #pragma unroll
        for (int c=0;c<2;c++)
            wmma::store_matrix_sync(cs + (wr*32+r*16)*64 + wc*32 + c*16, acc[r][c], 64, wmma::mem_row_major);
    __syncthreads();

    const float* bias = (which==0)?pbz : (which==1)?pbr : (which==2)?pbh : pbg;
    float* out = (which==0)?g_pre_z : (which==1)?g_pre_r : (which==2)?g_pre_h : g_gamma;
    for (int i = tid; i < 64*64; i += 128) {
        int rr = i >> 6, cj = i & 63;
        float v = cs[i] + bias[c0 + cj];
        if (which == 3) v = expf(-fmaxf(0.0f, v));
        out[(size_t)(r0+rr)*Hdim + c0 + cj] = v;
    }
}

// ============ persistent wmma scan — 512 threads ============================
#define WKS 1032
#define OFF_WAH 0
#define OFF_WAL 66048
#define OFF_WBH 132096
#define OFF_SAH 165120
#define OFF_SAL 183552
#define OFF_SBL 201984
#define SCAN_SMEM 204416

extern "C" __global__ void __launch_bounds__(SCANT, 1) k_scan()
{
    extern __shared__ __align__(16) char sm[];
    bf16* sWAh = (bf16*)(sm + OFF_WAH);
    bf16* sWAl = (bf16*)(sm + OFF_WAL);
    bf16* sWBh = (bf16*)(sm + OFF_WBH);
    bf16* sAh  = (bf16*)(sm + OFF_SAH);
    bf16* sAl  = (bf16*)(sm + OFF_SAL);
    bf16* sBl  = (bf16*)(sm + OFF_SBL);
    float* cs  = (float*)(sm + OFF_SAH);

    const int tid = threadIdx.x;
    const int wid = tid >> 5;
    const int blk = blockIdx.x;
    const int mi = blk >> 6, nj = blk & 63;
    const int r0 = mi * 128;
    const int c0A = nj * 32;
    const int c0B = nj * 16;
    const bool isz = (nj < 32);

    // resident weights
    for (int i = tid; i < 4096; i += SCANT) {
        int n = i >> 7, k8 = (i & 127) * 8;
        *(uint4*)(sWAh + n*WKS + k8) = *(const uint4*)(g_UzrT_hi + (size_t)(c0A + n)*1024 + k8);
        *(uint4*)(sWAl + n*WKS + k8) = *(const uint4*)(g_UzrT_lo + (size_t)(c0A + n)*1024 + k8);
    }
    for (int i = tid; i < 2048; i += SCANT) {
        int n = i >> 7, k8 = (i & 127) * 8;
        *(uint4*)(sWBh + n*WKS + k8) = *(const uint4*)(g_UT_hi + (size_t)(c0B + n)*1024 + k8);
    }
    __syncthreads();

    // A-staging map: 1024 uint4 per component, 2 per thread
    int aRow[2], aOff[2];
    #pragma unroll
    for (int v = 0; v < 2; v++) {
        int li = tid + SCANT*v;
        aRow[v] = li >> 3; aOff[v] = (li & 7)*8;
    }
    const int bRow = tid >> 3, bOff = (tid & 7)*8;   // sBl staging (tid < 128)

    // phase A warp tiling: 16 warps, each 16x16
    const int m0A = (wid >> 1) * 16;
    const int nfA = wid & 1;
    // phase B warp tiling: warps 0..7 compute
    const int m0B = (wid & 7) * 16;

    wmma::fragment<wmma::accumulator,16,16,16,float> acc;

    for (int t = 0; t < Tdim; t++) {
        // ================= phase A: hs @ [Uz|Ur] slice =================
        {
            uint4 ph[2], pl[2];
            #pragma unroll
            for (int v = 0; v < 2; v++) {
                size_t g = (size_t)(r0 + aRow[v])*1024 + aOff[v];
                ph[v] = __ldcg((const uint4*)(g_hs_hi + g));
                pl[v] = __ldcg((const uint4*)(g_hs_lo + g));
            }
            wmma::fill_fragment(acc, 0.0f);

            for (int kc = 0; kc < 16; kc++) {
                __syncthreads();
                #pragma unroll
                for (int v = 0; v < 2; v++) {
                    *(uint4*)(sAh + aRow[v]*72 + aOff[v]) = ph[v];
                    *(uint4*)(sAl + aRow[v]*72 + aOff[v]) = pl[v];
                }
                __syncthreads();
                if (kc < 15) {
                    #pragma unroll
                    for (int v = 0; v < 2; v++) {
                        size_t g = (size_t)(r0 + aRow[v])*1024 + (kc+1)*64 + aOff[v];
                        ph[v] = __ldcg((const uint4*)(g_hs_hi + g));
                        pl[v] = __ldcg((const uint4*)(g_hs_lo + g));
                    }
                }
                #pragma unroll
                for (int kf = 0; kf < 4; kf++) {
                    const int k0 = kf*16;
                    wmma::fragment<wmma::matrix_a,16,16,16,bf16,wmma::row_major> ah, al;
                    wmma::load_matrix_sync(ah, sAh + m0A*72 + k0, 72);
                    wmma::load_matrix_sync(al, sAl + m0A*72 + k0, 72);
                    wmma::fragment<wmma::matrix_b,16,16,16,bf16,wmma::col_major> bh, bl;
                    wmma::load_matrix_sync(bh, sWAh + (nfA*16)*WKS + kc*64 + k0, WKS);
                    wmma::load_matrix_sync(bl, sWAl + (nfA*16)*WKS + kc*64 + k0, WKS);
                    wmma::mma_sync(acc, ah, bh, acc);
                    wmma::mma_sync(acc, ah, bl, acc);
                    wmma::mma_sync(acc, al, bh, acc);
                }
            }
            __syncthreads();
            wmma::store_matrix_sync(cs + m0A*32 + nfA*16, acc, 32, wmma::mem_row_major);
            __syncthreads();

            if (isz) {
                for (int i = tid; i < 128*32; i += SCANT) {
                    int rr = i >> 5, cj = i & 31;
                    int row = r0 + rr, c = c0A + cj;
                    float v = g_pre_z[((size_t)row*Tdim + t)*Hdim + c] + cs[i];
                    g_z[row*Hdim + c] = 1.0f/(1.0f + expf(-v));
                }
            } else {
                for (int i = tid; i < 128*32; i += SCANT) {
                    int rr = i >> 5, cj = i & 31;
                    int row = r0 + rr, c = c0A - 1024 + cj;
                    float v = g_pre_r[((size_t)row*Tdim + t)*Hdim + c] + cs[i];
                    float s = 1.0f/(1.0f + expf(-v));
                    int idx = row*Hdim + c;
                    float rh = s * __ldcg(&g_hs[idx]);
                    bf16 hi, lo; split2(rh, hi, lo);
                    g_rh_hi[idx] = hi; g_rh_lo[idx] = lo;
                }
            }
        }
        grid_sync();

        // ================= phase B: rh @ U slice + state update =========
        {
            uint4 ph[2], pl[2], pw;
            #pragma unroll
            for (int v = 0; v < 2; v++) {
                size_t g = (size_t)(r0 + aRow[v])*1024 + aOff[v];
                ph[v] = __ldcg((const uint4*)(g_rh_hi + g));
                pl[v] = __ldcg((const uint4*)(g_rh_lo + g));
            }
            if (tid < 128)
                pw = *(const uint4*)(g_UT_lo + (size_t)(c0B + bRow)*1024 + bOff);
            wmma::fill_fragment(acc, 0.0f);

            for (int kc = 0; kc < 16; kc++) {
                __syncthreads();
                #pragma unroll
                for (int v = 0; v < 2; v++) {
                    *(uint4*)(sAh + aRow[v]*72 + aOff[v]) = ph[v];
                    *(uint4*)(sAl + aRow[v]*72 + aOff[v]) = pl[v];
                }
                if (tid < 128)
                    *(uint4*)(sBl + bRow*72 + bOff) = pw;
                __syncthreads();
                if (kc < 15) {
                    #pragma unroll
                    for (int v = 0; v < 2; v++) {
                        size_t g = (size_t)(r0 + aRow[v])*1024 + (kc+1)*64 + aOff[v];
                        ph[v] = __ldcg((const uint4*)(g_rh_hi + g));
                        pl[v] = __ldcg((const uint4*)(g_rh_lo + g));
                    }
                    if (tid < 128)
                        pw = *(const uint4*)(g_UT_lo + (size_t)(c0B + bRow)*1024 + (kc+1)*64 + bOff);
                }
                if (wid < 8) {
                    #pragma unroll
                    for (int kf = 0; kf < 4; kf++) {
                        const int k0 = kf*16;
                        wmma::fragment<wmma::matrix_a,16,16,16,bf16,wmma::row_major> ah, al;
                        wmma::load_matrix_sync(ah, sAh + m0B*72 + k0, 72);
                        wmma::load_matrix_sync(al, sAl + m0B*72 + k0, 72);
                        wmma::fragment<wmma::matrix_b,16,16,16,bf16,wmma::col_major> bh, bl;
                        wmma::load_matrix_sync(bh, sWBh + kc*64 + k0, WKS);
                        wmma::load_matrix_sync(bl, sBl + k0, 72);
                        wmma::mma_sync(acc, ah, bh, acc);
                        wmma::mma_sync(acc, ah, bl, acc);
                        wmma::mma_sync(acc, al, bh, acc);
                    }
                }
            }
            __syncthreads();
            if (wid < 8)
                wmma::store_matrix_sync(cs + m0B*16, acc, 16, wmma::mem_row_major);
            __syncthreads();

            for (int i = tid; i < 128*16; i += SCANT) {
                int rr = i >> 4, cj = i & 15;
                int row = r0 + rr, c = c0B + cj;
                int idx = row*Hdim + c;
                float ht = tanhf(g_pre_h[((size_t)row*Tdim + t)*Hdim + c] + cs[i]);
                float hs = __ldcg(&g_hs[idx]);
                float zv = __ldcg(&g_z[idx]);
                float hn = (1.0f - zv)*hs + zv*ht;
                if (t == Tdim-1) g_h[idx] = hn;
                float gn = (t+1 < Tdim) ? g_gamma[((size_t)row*Tdim + (t+1))*Hdim + c] : 1.0f;
                float nh = gn*hn;
                g_hs[idx] = nh;
                bf16 hi, lo; split2(nh, hi, lo);
                g_hs_hi[idx] = hi; g_hs_lo[idx] = lo;
            }
        }
        grid_sync();
    }
}

// ---------------- decoder ---------------------------------------------------
__global__ void k_dec(const float* __restrict__ dW, const float* __restrict__ db,
                      float* __restrict__ out)
{
    __shared__ float hrow[Hdim];
    int b = blockIdx.x;
    for (int i = threadIdx.x; i < Hdim; i += blockDim.x)
        hrow[i] = g_h[b*Hdim + i];
    __syncthreads();
    int o = threadIdx.x;
    float acc = db[o];
    #pragma unroll 8
    for (int k = 0; k < Hdim; k++)
        acc += hrow[k]*dW[k*Odim + o];
    out[b*Odim + o] = acc;
}

// ---------------- launch ----------------------------------------------------
extern "C" void kernel_launch(void* const* d_in, const int* in_sizes, int n_in,
                              void* d_out, int out_size)
{
    const float* x     = (const float*)d_in[0];
    const float* delta = (const float*)d_in[1];
    const float* m     = (const float*)d_in[2];
    const float* W_r   = (const float*)d_in[3];
    const float* U_r   = (const float*)d_in[4];
    const float* V_r   = (const float*)d_in[5];
    const float* b_r   = (const float*)d_in[6];
    const float* W_z   = (const float*)d_in[7];
    const float* U_z   = (const float*)d_in[8];
    const float* V_z   = (const float*)d_in[9];
    const float* b_z   = (const float*)d_in[10];
    const float* W     = (const float*)d_in[11];
    const float* U     = (const float*)d_in[12];
    const float* V     = (const float*)d_in[13];
    const float* b     = (const float*)d_in[14];
    const float* Wgx   = (const float*)d_in[15];
    const float* bgx   = (const float*)d_in[16];
    const float* Wgh   = (const float*)d_in[17];
    const float* bgh   = (const float*)d_in[18];
    const float* decW  = (const float*)d_in[19];
    const float* decb  = (const float*)d_in[20];
    float* out = (float*)d_out;

    static int smem_set = 0;
    if (!smem_set) {
        cudaFuncSetAttribute(k_scan, cudaFuncAttributeMaxDynamicSharedMemorySize, SCAN_SMEM);
        smem_set = 1;
    }

    // launch order: k_scan is launch #4 (ncu capture point)
    k_prep<<<SEG4/256, 256>>>(x, delta, m, Wgx, bgx,
                              W_z, V_z, W_r, V_r, W, V, Wgh, U_z, U_r, U);
    k_pre<<<dim3(Hdim/64, BT/64, 4), 128>>>(b_z, b_r, b, bgh);
    k_init<<<(Bdim*Hdim + 255)/256, 256>>>();
    k_scan<<<NBLK, SCANT, SCAN_SMEM>>>();
    k_dec<<<Bdim, Odim>>>(decW, decb, out);
}

// round 10
// speedup vs baseline: 4.2168x; 1.0106x over previous
#include <cuda_runtime.h>
#include <cuda_bf16.h>
#include <mma.h>
#include <math.h>
#include <stdint.h>

using namespace nvcuda;
typedef __nv_bfloat16 bf16;

#define Bdim 256
#define Tdim 256
#define Ddim 128
#define Hdim 1024
#define Odim 64
#define BT (Bdim*Tdim)
#define DK (Ddim*Hdim)
#define NBLK 128
#define SCANT 512

// ---------------- scratch (device globals; allocations forbidden) ----------
// pre_* and gamma are BT-MAJOR: index = ((b*Tdim + t)*Hdim + h)
__device__ float g_pre_z[67108864];
__device__ float g_pre_r[67108864];
__device__ float g_pre_h[67108864];
__device__ float g_gamma[67108864];
__device__ float g_hs[Bdim*Hdim];
__device__ float g_h [Bdim*Hdim];
__device__ float g_z [Bdim*Hdim];

__device__ bf16 g_hs_hi[Bdim*Hdim], g_hs_lo[Bdim*Hdim];
__device__ bf16 g_rh_hi[Bdim*Hdim], g_rh_lo[Bdim*Hdim];
__device__ bf16 g_x_hi[BT*Ddim],   g_x_lo[BT*Ddim];
__device__ bf16 g_mb [BT*Ddim];
__device__ bf16 g_mib[BT*Ddim];

// transposed split weights: [n][k], k stride 1024
__device__ bf16 g_UzrT_hi[2048*1024], g_UzrT_lo[2048*1024];
__device__ bf16 g_UT_hi[1024*1024],   g_UT_lo[1024*1024];
__device__ bf16 g_Wsm_hi[7*DK], g_Wsm_lo[7*DK];

__device__ unsigned g_bar_cnt = 0;
__device__ unsigned g_bar_gen = 0;

__device__ __forceinline__ void split2(float v, bf16& hi, bf16& lo) {
    hi = __float2bfloat16(v);
    lo = __float2bfloat16(v - __bfloat162float(hi));
}

__device__ __forceinline__ void grid_sync() {
    __threadfence();
    __syncthreads();
    if (threadIdx.x == 0) {
        unsigned my = atomicAdd(&g_bar_gen, 0u);
        if (atomicAdd(&g_bar_cnt, 1u) == NBLK - 1u) {
            atomicExch(&g_bar_cnt, 0u);
            atomicAdd(&g_bar_gen, 1u);
        } else {
            while (atomicAdd(&g_bar_gen, 0u) == my) { }
        }
    }
    __syncthreads();
}

// ---------------- fused prep: xmod + all weight splits ----------------------
#define SEG1 8388608u
#define SEG2 (SEG1 + 917504u)
#define SEG3 (SEG2 + 2097152u)
#define SEG4 (SEG3 + 1048576u)
__global__ void k_prep(const float* __restrict__ x, const float* __restrict__ delta,
                       const float* __restrict__ m, const float* __restrict__ wgx,
                       const float* __restrict__ bgx,
                       const float* __restrict__ Wz, const float* __restrict__ Vz,
                       const float* __restrict__ Wr, const float* __restrict__ Vr,
                       const float* __restrict__ Wh, const float* __restrict__ Vh,
                       const float* __restrict__ Wg,
                       const float* __restrict__ Uz, const float* __restrict__ Ur,
                       const float* __restrict__ U)
{
    unsigned i = blockIdx.x*256u + threadIdx.x;
    if (i < SEG1) {
        int d = i & (Ddim-1);
        float mv = m[i];
        float dec = delta[i]*wgx[d] + bgx[d];
        float xv = (mv > 0.0f) ? (1.0f - dec)*0.001f : x[i];
        split2(xv, g_x_hi[i], g_x_lo[i]);
        g_mb[i]  = __float2bfloat16(mv);
        g_mib[i] = __float2bfloat16(1.0f - mv);
    } else if (i < SEG2) {
        unsigned j2 = i - SEG1;
        int slot = j2 >> 17;
        int j = j2 & (DK-1);
        const float* src = (slot==0)?Wz:(slot==1)?Vz:(slot==2)?Wr:(slot==3)?Vr:(slot==4)?Wh:(slot==5)?Vh:Wg;
        split2(src[j], g_Wsm_hi[j2], g_Wsm_lo[j2]);
    } else if (i < SEG3) {
        unsigned j2 = i - SEG2;
        int n = j2 >> 10, k = j2 & 1023;
        float v = (n < 1024) ? Uz[k*1024 + n] : Ur[k*1024 + (n-1024)];
        split2(v, g_UzrT_hi[j2], g_UzrT_lo[j2]);
    } else {
        unsigned j2 = i - SEG3;
        int n = j2 >> 10, k = j2 & 1023;
        split2(U[k*1024 + n], g_UT_hi[j2], g_UT_lo[j2]);
    }
}

__global__ void k_init() {
    int i = blockIdx.x*blockDim.x + threadIdx.x;
    if (i < Bdim*Hdim) {
        g_hs[i] = 0.0f; g_h[i] = 0.0f;
        g_hs_hi[i] = __float2bfloat16(0.0f);
        g_hs_lo[i] = __float2bfloat16(0.0f);
    }
    if (i == 0) { g_bar_cnt = 0; g_bar_gen = 0; }
}

// ============ precompute GEMMs (unchanged) ==================================
__global__ void __launch_bounds__(128) k_pre(const float* __restrict__ pbz,
                                             const float* __restrict__ pbr,
                                             const float* __restrict__ pbh,
                                             const float* __restrict__ pbg)
{
    __shared__ __align__(16) char smem_raw[33792];
    bf16* sA0 = (bf16*)smem_raw;
    bf16* sA1 = sA0 + 64*40;
    bf16* sA2 = sA1 + 64*40;
    bf16* sB0 = sA2 + 64*40;
    bf16* sB1 = sB0 + 32*72;
    bf16* sB2 = sB1 + 32*72;
    bf16* sB3 = sB2 + 32*72;
    float* cs = (float*)smem_raw;

    const int which = blockIdx.z;
    const bool dual = (which < 3);
    const int tid = threadIdx.x;
    const int wid = tid >> 5;
    const int wr = wid >> 1, wc = wid & 1;
    const int r0 = blockIdx.y*64, c0 = blockIdx.x*64;

    const bf16 *Wh_p, *Wl_p, *Vh_p = nullptr, *Vl_p = nullptr;
    if (dual) {
        Wh_p = g_Wsm_hi + (size_t)(which*2)*DK;   Wl_p = g_Wsm_lo + (size_t)(which*2)*DK;
        Vh_p = g_Wsm_hi + (size_t)(which*2+1)*DK; Vl_p = g_Wsm_lo + (size_t)(which*2+1)*DK;
    } else {
        Wh_p = g_Wsm_hi + (size_t)6*DK;           Wl_p = g_Wsm_lo + (size_t)6*DK;
    }

    wmma::fragment<wmma::accumulator,16,16,16,float> acc[2][2];
    #pragma unroll
    for (int r=0;r<2;r++)
        #pragma unroll
        for (int c=0;c<2;c++) wmma::fill_fragment(acc[r][c], 0.0f);

    int aRow[2], aOff[2], bRow[2], bOff[2];
    #pragma unroll
    for (int j=0;j<2;j++) {
        int li = tid + 128*j;
        aRow[j] = li >> 2; aOff[j] = (li & 3)*8;
        bRow[j] = li >> 3; bOff[j] = (li & 7)*8;
    }

    for (int kk = 0; kk < Ddim; kk += 32) {
        __syncthreads();
        #pragma unroll
        for (int j=0;j<2;j++) {
            size_t ga = (size_t)(r0 + aRow[j])*Ddim + kk + aOff[j];
            size_t gb = (size_t)(kk + bRow[j])*Hdim + c0 + bOff[j];
            if (dual) {
                *(uint4*)(sA0 + aRow[j]*40 + aOff[j]) = *(const uint4*)(g_x_hi + ga);
                *(uint4*)(sA1 + aRow[j]*40 + aOff[j]) = *(const uint4*)(g_x_lo + ga);
                *(uint4*)(sA2 + aRow[j]*40 + aOff[j]) = *(const uint4*)(g_mib + ga);
                *(uint4*)(sB2 + bRow[j]*72 + bOff[j]) = *(const uint4*)(Vh_p + gb);
                *(uint4*)(sB3 + bRow[j]*72 + bOff[j]) = *(const uint4*)(Vl_p + gb);
            } else {
                *(uint4*)(sA0 + aRow[j]*40 + aOff[j]) = *(const uint4*)(g_mb + ga);
            }
            *(uint4*)(sB0 + bRow[j]*72 + bOff[j]) = *(const uint4*)(Wh_p + gb);
            *(uint4*)(sB1 + bRow[j]*72 + bOff[j]) = *(const uint4*)(Wl_p + gb);
        }
        __syncthreads();
        #pragma unroll
        for (int ks=0; ks<32; ks+=16) {
            wmma::fragment<wmma::matrix_a,16,16,16,bf16,wmma::row_major> a0[2], a1[2], a2[2];
            wmma::fragment<wmma::matrix_b,16,16,16,bf16,wmma::row_major> b0[2], b1[2], b2[2], b3[2];
            #pragma unroll
            for (int r=0;r<2;r++) {
                wmma::load_matrix_sync(a0[r], sA0 + (wr*32+r*16)*40 + ks, 40);
                if (dual) {
                    wmma::load_matrix_sync(a1[r], sA1 + (wr*32+r*16)*40 + ks, 40);
                    wmma::load_matrix_sync(a2[r], sA2 + (wr*32+r*16)*40 + ks, 40);
                }
            }
            #pragma unroll
            for (int c=0;c<2;c++) {
                wmma::load_matrix_sync(b0[c], sB0 + ks*72 + wc*32 + c*16, 72);
                wmma::load_matrix_sync(b1[c], sB1 + ks*72 + wc*32 + c*16, 72);
                if (dual) {
                    wmma::load_matrix_sync(b2[c], sB2 + ks*72 + wc*32 + c*16, 72);
                    wmma::load_matrix_sync(b3[c], sB3 + ks*72 + wc*32 + c*16, 72);
                }
            }
            #pragma unroll
            for (int r=0;r<2;r++)
                #pragma unroll
                for (int c=0;c<2;c++) {
                    wmma::mma_sync(acc[r][c], a0[r], b0[c], acc[r][c]);
                    wmma::mma_sync(acc[r][c], a0[r], b1[c], acc[r][c]);
                    if (dual) {
                        wmma::mma_sync(acc[r][c], a1[r], b0[c], acc[r][c]);
                        wmma::mma_sync(acc[r][c], a2[r], b2[c], acc[r][c]);
                        wmma::mma_sync(acc[r][c], a2[r], b3[c], acc[r][c]);
                    }
                }
        }
    }
    __syncthreads();
    #pragma unroll
    for (int r=0;r<2;r++)
        #pragma unroll
        for (int c=0;c<2;c++)
            wmma::store_matrix_sync(cs + (wr*32+r*16)*64 + wc*32 + c*16, acc[r][c], 64, wmma::mem_row_major);
    __syncthreads();

    const float* bias = (which==0)?pbz : (which==1)?pbr : (which==2)?pbh : pbg;
    float* out = (which==0)?g_pre_z : (which==1)?g_pre_r : (which==2)?g_pre_h : g_gamma;
    for (int i = tid; i < 64*64; i += 128) {
        int rr = i >> 6, cj = i & 63;
        float v = cs[i] + bias[c0 + cj];
        if (which == 3) v = expf(-fmaxf(0.0f, v));
        out[(size_t)(r0+rr)*Hdim + c0 + cj] = v;
    }
}

// ============ persistent wmma scan — 512 threads, dual accumulators =========
#define WKS 1032
#define OFF_WAH 0
#define OFF_WAL 66048
#define OFF_WBH 132096
#define OFF_SAH 165120
#define OFF_SAL 183552
#define OFF_SBL 201984
#define SCAN_SMEM 204416

extern "C" __global__ void __launch_bounds__(SCANT, 1) k_scan()
{
    extern __shared__ __align__(16) char sm[];
    bf16* sWAh = (bf16*)(sm + OFF_WAH);
    bf16* sWAl = (bf16*)(sm + OFF_WAL);
    bf16* sWBh = (bf16*)(sm + OFF_WBH);
    bf16* sAh  = (bf16*)(sm + OFF_SAH);
    bf16* sAl  = (bf16*)(sm + OFF_SAL);
    bf16* sBl  = (bf16*)(sm + OFF_SBL);
    float* cs  = (float*)(sm + OFF_SAH);

    const int tid = threadIdx.x;
    const int wid = tid >> 5;
    const int blk = blockIdx.x;
    const int mi = blk >> 6, nj = blk & 63;
    const int r0 = mi * 128;
    const int c0A = nj * 32;
    const int c0B = nj * 16;
    const bool isz = (nj < 32);

    // resident weights
    for (int i = tid; i < 4096; i += SCANT) {
        int n = i >> 7, k8 = (i & 127) * 8;
        *(uint4*)(sWAh + n*WKS + k8) = *(const uint4*)(g_UzrT_hi + (size_t)(c0A + n)*1024 + k8);
        *(uint4*)(sWAl + n*WKS + k8) = *(const uint4*)(g_UzrT_lo + (size_t)(c0A + n)*1024 + k8);
    }
    for (int i = tid; i < 2048; i += SCANT) {
        int n = i >> 7, k8 = (i & 127) * 8;
        *(uint4*)(sWBh + n*WKS + k8) = *(const uint4*)(g_UT_hi + (size_t)(c0B + n)*1024 + k8);
    }
    __syncthreads();

    int aRow[2], aOff[2];
    #pragma unroll
    for (int v = 0; v < 2; v++) {
        int li = tid + SCANT*v;
        aRow[v] = li >> 3; aOff[v] = (li & 7)*8;
    }
    const int bRow = tid >> 3, bOff = (tid & 7)*8;

    const int m0A = (wid >> 1) * 16;
    const int nfA = wid & 1;
    const int m0B = (wid & 7) * 16;

    wmma::fragment<wmma::accumulator,16,16,16,float> acc0, acc1;

    for (int t = 0; t < Tdim; t++) {
        // ================= phase A: hs @ [Uz|Ur] slice =================
        {
            uint4 ph[2], pl[2];
            #pragma unroll
            for (int v = 0; v < 2; v++) {
                size_t g = (size_t)(r0 + aRow[v])*1024 + aOff[v];
                ph[v] = __ldcg((const uint4*)(g_hs_hi + g));
                pl[v] = __ldcg((const uint4*)(g_hs_lo + g));
            }
            wmma::fill_fragment(acc0, 0.0f);
            wmma::fill_fragment(acc1, 0.0f);

            for (int kc = 0; kc < 16; kc++) {
                __syncthreads();
                #pragma unroll
                for (int v = 0; v < 2; v++) {
                    *(uint4*)(sAh + aRow[v]*72 + aOff[v]) = ph[v];
                    *(uint4*)(sAl + aRow[v]*72 + aOff[v]) = pl[v];
                }
                __syncthreads();
                if (kc < 15) {
                    #pragma unroll
                    for (int v = 0; v < 2; v++) {
                        size_t g = (size_t)(r0 + aRow[v])*1024 + (kc+1)*64 + aOff[v];
                        ph[v] = __ldcg((const uint4*)(g_hs_hi + g));
                        pl[v] = __ldcg((const uint4*)(g_hs_lo + g));
                    }
                }
                #pragma unroll
                for (int kf = 0; kf < 4; kf++) {
                    const int k0 = kf*16;
                    wmma::fragment<wmma::matrix_a,16,16,16,bf16,wmma::row_major> ah, al;
                    wmma::load_matrix_sync(ah, sAh + m0A*72 + k0, 72);
                    wmma::load_matrix_sync(al, sAl + m0A*72 + k0, 72);
                    wmma::fragment<wmma::matrix_b,16,16,16,bf16,wmma::col_major> bh, bl;
                    wmma::load_matrix_sync(bh, sWAh + (nfA*16)*WKS + kc*64 + k0, WKS);
                    wmma::load_matrix_sync(bl, sWAl + (nfA*16)*WKS + kc*64 + k0, WKS);
                    wmma::mma_sync(acc0, ah, bh, acc0);
                    wmma::mma_sync(acc1, ah, bl, acc1);
                    wmma::mma_sync(acc0, al, bh, acc0);   // chain dist 2 on acc0, 4 on acc1
                }
            }
            #pragma unroll
            for (int e = 0; e < acc0.num_elements; e++)
                acc0.x[e] += acc1.x[e];
            __syncthreads();
            wmma::store_matrix_sync(cs + m0A*32 + nfA*16, acc0, 32, wmma::mem_row_major);
            __syncthreads();

            if (isz) {
                for (int i = tid; i < 128*32; i += SCANT) {
                    int rr = i >> 5, cj = i & 31;
                    int row = r0 + rr, c = c0A + cj;
                    float v = g_pre_z[((size_t)row*Tdim + t)*Hdim + c] + cs[i];
                    g_z[row*Hdim + c] = 1.0f/(1.0f + expf(-v));
                }
            } else {
                for (int i = tid; i < 128*32; i += SCANT) {
                    int rr = i >> 5, cj = i & 31;
                    int row = r0 + rr, c = c0A - 1024 + cj;
                    float v = g_pre_r[((size_t)row*Tdim + t)*Hdim + c] + cs[i];
                    float s = 1.0f/(1.0f + expf(-v));
                    int idx = row*Hdim + c;
                    float rh = s * __ldcg(&g_hs[idx]);
                    bf16 hi, lo; split2(rh, hi, lo);
                    g_rh_hi[idx] = hi; g_rh_lo[idx] = lo;
                }
            }
        }
        grid_sync();

        // ================= phase B: rh @ U slice + state update =========
        {
            uint4 ph[2], pl[2], pw;
            #pragma unroll
            for (int v = 0; v < 2; v++) {
                size_t g = (size_t)(r0 + aRow[v])*1024 + aOff[v];
                ph[v] = __ldcg((const uint4*)(g_rh_hi + g));
                pl[v] = __ldcg((const uint4*)(g_rh_lo + g));
            }
            if (tid < 128)
                pw = *(const uint4*)(g_UT_lo + (size_t)(c0B + bRow)*1024 + bOff);
            wmma::fill_fragment(acc0, 0.0f);
            wmma::fill_fragment(acc1, 0.0f);

            for (int kc = 0; kc < 16; kc++) {
                __syncthreads();
                #pragma unroll
                for (int v = 0; v < 2; v++) {
                    *(uint4*)(sAh + aRow[v]*72 + aOff[v]) = ph[v];
                    *(uint4*)(sAl + aRow[v]*72 + aOff[v]) = pl[v];
                }
                if (tid < 128)
                    *(uint4*)(sBl + bRow*72 + bOff) = pw;
                __syncthreads();
                if (kc < 15) {
                    #pragma unroll
                    for (int v = 0; v < 2; v++) {
                        size_t g = (size_t)(r0 + aRow[v])*1024 + (kc+1)*64 + aOff[v];
                        ph[v] = __ldcg((const uint4*)(g_rh_hi + g));
                        pl[v] = __ldcg((const uint4*)(g_rh_lo + g));
                    }
                    if (tid < 128)
                        pw = *(const uint4*)(g_UT_lo + (size_t)(c0B + bRow)*1024 + (kc+1)*64 + bOff);
                }
                if (wid < 8) {
                    #pragma unroll
                    for (int kf = 0; kf < 4; kf++) {
                        const int k0 = kf*16;
                        wmma::fragment<wmma::matrix_a,16,16,16,bf16,wmma::row_major> ah, al;
                        wmma::load_matrix_sync(ah, sAh + m0B*72 + k0, 72);
                        wmma::load_matrix_sync(al, sAl + m0B*72 + k0, 72);
                        wmma::fragment<wmma::matrix_b,16,16,16,bf16,wmma::col_major> bh, bl;
                        wmma::load_matrix_sync(bh, sWBh + kc*64 + k0, WKS);
                        wmma::load_matrix_sync(bl, sBl + k0, 72);
                        wmma::mma_sync(acc0, ah, bh, acc0);
                        wmma::mma_sync(acc1, ah, bl, acc1);
                        wmma::mma_sync(acc0, al, bh, acc0);
                    }
                }
            }
            __syncthreads();
            if (wid < 8) {
                #pragma unroll
                for (int e = 0; e < acc0.num_elements; e++)
                    acc0.x[e] += acc1.x[e];
                wmma::store_matrix_sync(cs + m0B*16, acc0, 16, wmma::mem_row_major);
            }
            __syncthreads();

            for (int i = tid; i < 128*16; i += SCANT) {
                int rr = i >> 4, cj = i & 15;
                int row = r0 + rr, c = c0B + cj;
                int idx = row*Hdim + c;
                float ht = tanhf(g_pre_h[((size_t)row*Tdim + t)*Hdim + c] + cs[i]);
                float hs = __ldcg(&g_hs[idx]);
                float zv = __ldcg(&g_z[idx]);
                float hn = (1.0f - zv)*hs + zv*ht;
                if (t == Tdim-1) g_h[idx] = hn;
                float gn = (t+1 < Tdim) ? g_gamma[((size_t)row*Tdim + (t+1))*Hdim + c] : 1.0f;
                float nh = gn*hn;
                g_hs[idx] = nh;
                bf16 hi, lo; split2(nh, hi, lo);
                g_hs_hi[idx] = hi; g_hs_lo[idx] = lo;
            }
        }
        grid_sync();
    }
}

// ---------------- decoder ---------------------------------------------------
__global__ void k_dec(const float* __restrict__ dW, const float* __restrict__ db,
                      float* __restrict__ out)
{
    __shared__ float hrow[Hdim];
    int b = blockIdx.x;
    for (int i = threadIdx.x; i < Hdim; i += blockDim.x)
        hrow[i] = g_h[b*Hdim + i];
    __syncthreads();
    int o = threadIdx.x;
    float acc = db[o];
    #pragma unroll 8
    for (int k = 0; k < Hdim; k++)
        acc += hrow[k]*dW[k*Odim + o];
    out[b*Odim + o] = acc;
}

// ---------------- launch ----------------------------------------------------
extern "C" void kernel_launch(void* const* d_in, const int* in_sizes, int n_in,
                              void* d_out, int out_size)
{
    const float* x     = (const float*)d_in[0];
    const float* delta = (const float*)d_in[1];
    const float* m     = (const float*)d_in[2];
    const float* W_r   = (const float*)d_in[3];
    const float* U_r   = (const float*)d_in[4];
    const float* V_r   = (const float*)d_in[5];
    const float* b_r   = (const float*)d_in[6];
    const float* W_z   = (const float*)d_in[7];
    const float* U_z   = (const float*)d_in[8];
    const float* V_z   = (const float*)d_in[9];
    const float* b_z   = (const float*)d_in[10];
    const float* W     = (const float*)d_in[11];
    const float* U     = (const float*)d_in[12];
    const float* V     = (const float*)d_in[13];
    const float* b     = (const float*)d_in[14];
    const float* Wgx   = (const float*)d_in[15];
    const float* bgx   = (const float*)d_in[16];
    const float* Wgh   = (const float*)d_in[17];
    const float* bgh   = (const float*)d_in[18];
    const float* decW  = (const float*)d_in[19];
    const float* decb  = (const float*)d_in[20];
    float* out = (float*)d_out;

    static int smem_set = 0;
    if (!smem_set) {
        cudaFuncSetAttribute(k_scan, cudaFuncAttributeMaxDynamicSharedMemorySize, SCAN_SMEM);
        smem_set = 1;
    }

    // launch order: k_scan is launch #4 (ncu capture point)
    k_prep<<<SEG4/256, 256>>>(x, delta, m, Wgx, bgx,
                              W_z, V_z, W_r, V_r, W, V, Wgh, U_z, U_r, U);
    k_pre<<<dim3(Hdim/64, BT/64, 4), 128>>>(b_z, b_r, b, bgh);
    k_init<<<(Bdim*Hdim + 255)/256, 256>>>();
    k_scan<<<NBLK, SCANT, SCAN_SMEM>>>();
    k_dec<<<Bdim, Odim>>>(decW, decb, out);
}

// round 11
// speedup vs baseline: 5.8590x; 1.3894x over previous
#include <cuda_runtime.h>
#include <cuda_bf16.h>
#include <cuda_fp16.h>
#include <mma.h>
#include <math.h>
#include <stdint.h>

using namespace nvcuda;
typedef __nv_bfloat16 bf16;
typedef __half hf;

#define Bdim 256
#define Tdim 256
#define Ddim 128
#define Hdim 1024
#define Odim 64
#define BT (Bdim*Tdim)
#define DK (Ddim*Hdim)
#define NBLK 128
#define SCANT 512

// ---------------- scratch (device globals; allocations forbidden) ----------
// pre_* and gamma are BT-MAJOR: index = ((b*Tdim + t)*Hdim + h)
__device__ float g_pre_z[67108864];
__device__ float g_pre_r[67108864];
__device__ float g_pre_h[67108864];
__device__ float g_gamma[67108864];
__device__ float g_hs[Bdim*Hdim];
__device__ float g_h [Bdim*Hdim];
__device__ float g_z [Bdim*Hdim];

// scan operands: fp16 (single precision-level A, split weights)
__device__ hf g_hs_h[Bdim*Hdim];
__device__ hf g_rh_h[Bdim*Hdim];

// k_pre operands stay bf16 3-product
__device__ bf16 g_x_hi[BT*Ddim],   g_x_lo[BT*Ddim];
__device__ bf16 g_mb [BT*Ddim];
__device__ bf16 g_mib[BT*Ddim];
__device__ bf16 g_Wsm_hi[7*DK], g_Wsm_lo[7*DK];

// transposed scan weights: [n][k], k stride 1024 — fp16 hi/lo split
__device__ hf g_UzrT_hi[2048*1024], g_UzrT_lo[2048*1024];
__device__ hf g_UT_hi[1024*1024],   g_UT_lo[1024*1024];

__device__ unsigned g_bar_cnt = 0;
__device__ unsigned g_bar_gen = 0;

__device__ __forceinline__ void split2(float v, bf16& hi, bf16& lo) {
    hi = __float2bfloat16(v);
    lo = __float2bfloat16(v - __bfloat162float(hi));
}
__device__ __forceinline__ void split2h(float v, hf& hi, hf& lo) {
    hi = __float2half(v);
    lo = __float2half(v - __half2float(hi));
}

__device__ __forceinline__ void grid_sync() {
    __threadfence();
    __syncthreads();
    if (threadIdx.x == 0) {
        unsigned my = atomicAdd(&g_bar_gen, 0u);
        if (atomicAdd(&g_bar_cnt, 1u) == NBLK - 1u) {
            atomicExch(&g_bar_cnt, 0u);
            atomicAdd(&g_bar_gen, 1u);
        } else {
            while (atomicAdd(&g_bar_gen, 0u) == my) { }
        }
    }
    __syncthreads();
}

// ---------------- fused prep: xmod + all weight splits ----------------------
#define SEG1 8388608u
#define SEG2 (SEG1 + 917504u)
#define SEG3 (SEG2 + 2097152u)
#define SEG4 (SEG3 + 1048576u)
__global__ void k_prep(const float* __restrict__ x, const float* __restrict__ delta,
                       const float* __restrict__ m, const float* __restrict__ wgx,
                       const float* __restrict__ bgx,
                       const float* __restrict__ Wz, const float* __restrict__ Vz,
                       const float* __restrict__ Wr, const float* __restrict__ Vr,
                       const float* __restrict__ Wh, const float* __restrict__ Vh,
                       const float* __restrict__ Wg,
                       const float* __restrict__ Uz, const float* __restrict__ Ur,
                       const float* __restrict__ U)
{
    unsigned i = blockIdx.x*256u + threadIdx.x;
    if (i < SEG1) {
        int d = i & (Ddim-1);
        float mv = m[i];
        float dec = delta[i]*wgx[d] + bgx[d];
        float xv = (mv > 0.0f) ? (1.0f - dec)*0.001f : x[i];
        split2(xv, g_x_hi[i], g_x_lo[i]);
        g_mb[i]  = __float2bfloat16(mv);
        g_mib[i] = __float2bfloat16(1.0f - mv);
    } else if (i < SEG2) {
        unsigned j2 = i - SEG1;
        int slot = j2 >> 17;
        int j = j2 & (DK-1);
        const float* src = (slot==0)?Wz:(slot==1)?Vz:(slot==2)?Wr:(slot==3)?Vr:(slot==4)?Wh:(slot==5)?Vh:Wg;
        split2(src[j], g_Wsm_hi[j2], g_Wsm_lo[j2]);
    } else if (i < SEG3) {
        unsigned j2 = i - SEG2;
        int n = j2 >> 10, k = j2 & 1023;
        float v = (n < 1024) ? Uz[k*1024 + n] : Ur[k*1024 + (n-1024)];
        split2h(v, g_UzrT_hi[j2], g_UzrT_lo[j2]);
    } else {
        unsigned j2 = i - SEG3;
        int n = j2 >> 10, k = j2 & 1023;
        split2h(U[k*1024 + n], g_UT_hi[j2], g_UT_lo[j2]);
    }
}

__global__ void k_init() {
    int i = blockIdx.x*blockDim.x + threadIdx.x;
    if (i < Bdim*Hdim) {
        g_hs[i] = 0.0f; g_h[i] = 0.0f;
        g_hs_h[i] = __float2half(0.0f);
    }
    if (i == 0) { g_bar_cnt = 0; g_bar_gen = 0; }
}

// ============ precompute GEMMs (unchanged, bf16 3-product) ==================
__global__ void __launch_bounds__(128) k_pre(const float* __restrict__ pbz,
                                             const float* __restrict__ pbr,
                                             const float* __restrict__ pbh,
                                             const float* __restrict__ pbg)
{
    __shared__ __align__(16) char smem_raw[33792];
    bf16* sA0 = (bf16*)smem_raw;
    bf16* sA1 = sA0 + 64*40;
    bf16* sA2 = sA1 + 64*40;
    bf16* sB0 = sA2 + 64*40;
    bf16* sB1 = sB0 + 32*72;
    bf16* sB2 = sB1 + 32*72;
    bf16* sB3 = sB2 + 32*72;
    float* cs = (float*)smem_raw;

    const int which = blockIdx.z;
    const bool dual = (which < 3);
    const int tid = threadIdx.x;
    const int wid = tid >> 5;
    const int wr = wid >> 1, wc = wid & 1;
    const int r0 = blockIdx.y*64, c0 = blockIdx.x*64;

    const bf16 *Wh_p, *Wl_p, *Vh_p = nullptr, *Vl_p = nullptr;
    if (dual) {
        Wh_p = g_Wsm_hi + (size_t)(which*2)*DK;   Wl_p = g_Wsm_lo + (size_t)(which*2)*DK;
        Vh_p = g_Wsm_hi + (size_t)(which*2+1)*DK; Vl_p = g_Wsm_lo + (size_t)(which*2+1)*DK;
    } else {
        Wh_p = g_Wsm_hi + (size_t)6*DK;           Wl_p = g_Wsm_lo + (size_t)6*DK;
    }

    wmma::fragment<wmma::accumulator,16,16,16,float> acc[2][2];
    #pragma unroll
    for (int r=0;r<2;r++)
        #pragma unroll
        for (int c=0;c<2;c++) wmma::fill_fragment(acc[r][c], 0.0f);

    int aRow[2], aOff[2], bRow[2], bOff[2];
    #pragma unroll
    for (int j=0;j<2;j++) {
        int li = tid + 128*j;
        aRow[j] = li >> 2; aOff[j] = (li & 3)*8;
        bRow[j] = li >> 3; bOff[j] = (li & 7)*8;
    }

    for (int kk = 0; kk < Ddim; kk += 32) {
        __syncthreads();
        #pragma unroll
        for (int j=0;j<2;j++) {
            size_t ga = (size_t)(r0 + aRow[j])*Ddim + kk + aOff[j];
            size_t gb = (size_t)(kk + bRow[j])*Hdim + c0 + bOff[j];
            if (dual) {
                *(uint4*)(sA0 + aRow[j]*40 + aOff[j]) = *(const uint4*)(g_x_hi + ga);
                *(uint4*)(sA1 + aRow[j]*40 + aOff[j]) = *(const uint4*)(g_x_lo + ga);
                *(uint4*)(sA2 + aRow[j]*40 + aOff[j]) = *(const uint4*)(g_mib + ga);
                *(uint4*)(sB2 + bRow[j]*72 + bOff[j]) = *(const uint4*)(Vh_p + gb);
                *(uint4*)(sB3 + bRow[j]*72 + bOff[j]) = *(const uint4*)(Vl_p + gb);
            } else {
                *(uint4*)(sA0 + aRow[j]*40 + aOff[j]) = *(const uint4*)(g_mb + ga);
            }
            *(uint4*)(sB0 + bRow[j]*72 + bOff[j]) = *(const uint4*)(Wh_p + gb);
            *(uint4*)(sB1 + bRow[j]*72 + bOff[j]) = *(const uint4*)(Wl_p + gb);
        }
        __syncthreads();
        #pragma unroll
        for (int ks=0; ks<32; ks+=16) {
            wmma::fragment<wmma::matrix_a,16,16,16,bf16,wmma::row_major> a0[2], a1[2], a2[2];
            wmma::fragment<wmma::matrix_b,16,16,16,bf16,wmma::row_major> b0[2], b1[2], b2[2], b3[2];
            #pragma unroll
            for (int r=0;r<2;r++) {
                wmma::load_matrix_sync(a0[r], sA0 + (wr*32+r*16)*40 + ks, 40);
                if (dual) {
                    wmma::load_matrix_sync(a1[r], sA1 + (wr*32+r*16)*40 + ks, 40);
                    wmma::load_matrix_sync(a2[r], sA2 + (wr*32+r*16)*40 + ks, 40);
                }
            }
            #pragma unroll
            for (int c=0;c<2;c++) {
                wmma::load_matrix_sync(b0[c], sB0 + ks*72 + wc*32 + c*16, 72);
                wmma::load_matrix_sync(b1[c], sB1 + ks*72 + wc*32 + c*16, 72);
                if (dual) {
                    wmma::load_matrix_sync(b2[c], sB2 + ks*72 + wc*32 + c*16, 72);
                    wmma::load_matrix_sync(b3[c], sB3 + ks*72 + wc*32 + c*16, 72);
                }
            }
            #pragma unroll
            for (int r=0;r<2;r++)
                #pragma unroll
                for (int c=0;c<2;c++) {
                    wmma::mma_sync(acc[r][c], a0[r], b0[c], acc[r][c]);
                    wmma::mma_sync(acc[r][c], a0[r], b1[c], acc[r][c]);
                    if (dual) {
                        wmma::mma_sync(acc[r][c], a1[r], b0[c], acc[r][c]);
                        wmma::mma_sync(acc[r][c], a2[r], b2[c], acc[r][c]);
                        wmma::mma_sync(acc[r][c], a2[r], b3[c], acc[r][c]);
                    }
                }
        }
    }
    __syncthreads();
    #pragma unroll
    for (int r=0;r<2;r++)
        #pragma unroll
        for (int c=0;c<2;c++)
            wmma::store_matrix_sync(cs + (wr*32+r*16)*64 + wc*32 + c*16, acc[r][c], 64, wmma::mem_row_major);
    __syncthreads();

    const float* bias = (which==0)?pbz : (which==1)?pbr : (which==2)?pbh : pbg;
    float* out = (which==0)?g_pre_z : (which==1)?g_pre_r : (which==2)?g_pre_h : g_gamma;
    for (int i = tid; i < 64*64; i += 128) {
        int rr = i >> 6, cj = i & 63;
        float v = cs[i] + bias[c0 + cj];
        if (which == 3) v = expf(-fmaxf(0.0f, v));
        out[(size_t)(r0+rr)*Hdim + c0 + cj] = v;
    }
}

// ============ persistent fp16 scan — 512 threads, 2-product =================
#define WKS 1032
#define OFF_WAH 0
#define OFF_WAL 66048
#define OFF_WBH 132096
#define OFF_SA  165120
#define OFF_SBL 201984
#define SCAN_SMEM 204416

extern "C" __global__ void __launch_bounds__(SCANT, 1) k_scan()
{
    extern __shared__ __align__(16) char sm[];
    hf* sWAh = (hf*)(sm + OFF_WAH);
    hf* sWAl = (hf*)(sm + OFF_WAL);
    hf* sWBh = (hf*)(sm + OFF_WBH);
    hf* sA   = (hf*)(sm + OFF_SA);
    hf* sBl  = (hf*)(sm + OFF_SBL);
    float* cs = (float*)(sm + OFF_SA);

    const int tid = threadIdx.x;
    const int wid = tid >> 5;
    const int blk = blockIdx.x;
    const int mi = blk >> 6, nj = blk & 63;
    const int r0 = mi * 128;
    const int c0A = nj * 32;
    const int c0B = nj * 16;
    const bool isz = (nj < 32);

    // resident weights
    for (int i = tid; i < 4096; i += SCANT) {
        int n = i >> 7, k8 = (i & 127) * 8;
        *(uint4*)(sWAh + n*WKS + k8) = *(const uint4*)(g_UzrT_hi + (size_t)(c0A + n)*1024 + k8);
        *(uint4*)(sWAl + n*WKS + k8) = *(const uint4*)(g_UzrT_lo + (size_t)(c0A + n)*1024 + k8);
    }
    for (int i = tid; i < 2048; i += SCANT) {
        int n = i >> 7, k8 = (i & 127) * 8;
        *(uint4*)(sWBh + n*WKS + k8) = *(const uint4*)(g_UT_hi + (size_t)(c0B + n)*1024 + k8);
    }
    __syncthreads();

    // A staging: 128 rows x 64 k (f16) = 1024 uint4; 2 per thread
    int aRow[2], aOff[2];
    #pragma unroll
    for (int v = 0; v < 2; v++) {
        int li = tid + SCANT*v;
        aRow[v] = li >> 3; aOff[v] = (li & 7)*8;
    }
    const int bRow = tid >> 3, bOff = (tid & 7)*8;

    const int m0A = (wid >> 1) * 16;
    const int nfA = wid & 1;
    const int m0B = (wid & 7) * 16;

    wmma::fragment<wmma::accumulator,16,16,16,float> acc0, acc1;

    for (int t = 0; t < Tdim; t++) {
        // ================= phase A: hs @ [Uz|Ur] slice =================
        {
            uint4 pa[2];
            #pragma unroll
            for (int v = 0; v < 2; v++)
                pa[v] = __ldcg((const uint4*)(g_hs_h + (size_t)(r0 + aRow[v])*1024 + aOff[v]));
            wmma::fill_fragment(acc0, 0.0f);
            wmma::fill_fragment(acc1, 0.0f);

            for (int kc = 0; kc < 16; kc++) {
                __syncthreads();
                #pragma unroll
                for (int v = 0; v < 2; v++)
                    *(uint4*)(sA + aRow[v]*72 + aOff[v]) = pa[v];
                __syncthreads();
                if (kc < 15) {
                    #pragma unroll
                    for (int v = 0; v < 2; v++)
                        pa[v] = __ldcg((const uint4*)(g_hs_h + (size_t)(r0 + aRow[v])*1024 + (kc+1)*64 + aOff[v]));
                }
                #pragma unroll
                for (int kf = 0; kf < 4; kf++) {
                    const int k0 = kf*16;
                    wmma::fragment<wmma::matrix_a,16,16,16,hf,wmma::row_major> af;
                    wmma::load_matrix_sync(af, sA + m0A*72 + k0, 72);
                    wmma::fragment<wmma::matrix_b,16,16,16,hf,wmma::col_major> bh, bl;
                    wmma::load_matrix_sync(bh, sWAh + (nfA*16)*WKS + kc*64 + k0, WKS);
                    wmma::load_matrix_sync(bl, sWAl + (nfA*16)*WKS + kc*64 + k0, WKS);
                    wmma::mma_sync(acc0, af, bh, acc0);
                    wmma::mma_sync(acc1, af, bl, acc1);
                }
            }
            #pragma unroll
            for (int e = 0; e < acc0.num_elements; e++)
                acc0.x[e] += acc1.x[e];
            __syncthreads();
            wmma::store_matrix_sync(cs + m0A*32 + nfA*16, acc0, 32, wmma::mem_row_major);
            __syncthreads();

            if (isz) {
                for (int i = tid; i < 128*32; i += SCANT) {
                    int rr = i >> 5, cj = i & 31;
                    int row = r0 + rr, c = c0A + cj;
                    float v = g_pre_z[((size_t)row*Tdim + t)*Hdim + c] + cs[i];
                    g_z[row*Hdim + c] = 1.0f/(1.0f + expf(-v));
                }
            } else {
                for (int i = tid; i < 128*32; i += SCANT) {
                    int rr = i >> 5, cj = i & 31;
                    int row = r0 + rr, c = c0A - 1024 + cj;
                    float v = g_pre_r[((size_t)row*Tdim + t)*Hdim + c] + cs[i];
                    float s = 1.0f/(1.0f + expf(-v));
                    int idx = row*Hdim + c;
                    float rh = s * __ldcg(&g_hs[idx]);
                    g_rh_h[idx] = __float2half(rh);
                }
            }
        }
        grid_sync();

        // ================= phase B: rh @ U slice + state update =========
        {
            uint4 pa[2], pw;
            #pragma unroll
            for (int v = 0; v < 2; v++)
                pa[v] = __ldcg((const uint4*)(g_rh_h + (size_t)(r0 + aRow[v])*1024 + aOff[v]));
            if (tid < 128)
                pw = *(const uint4*)(g_UT_lo + (size_t)(c0B + bRow)*1024 + bOff);
            wmma::fill_fragment(acc0, 0.0f);
            wmma::fill_fragment(acc1, 0.0f);

            for (int kc = 0; kc < 16; kc++) {
                __syncthreads();
                #pragma unroll
                for (int v = 0; v < 2; v++)
                    *(uint4*)(sA + aRow[v]*72 + aOff[v]) = pa[v];
                if (tid < 128)
                    *(uint4*)(sBl + bRow*72 + bOff) = pw;
                __syncthreads();
                if (kc < 15) {
                    #pragma unroll
                    for (int v = 0; v < 2; v++)
                        pa[v] = __ldcg((const uint4*)(g_rh_h + (size_t)(r0 + aRow[v])*1024 + (kc+1)*64 + aOff[v]));
                    if (tid < 128)
                        pw = *(const uint4*)(g_UT_lo + (size_t)(c0B + bRow)*1024 + (kc+1)*64 + bOff);
                }
                if (wid < 8) {
                    #pragma unroll
                    for (int kf = 0; kf < 4; kf++) {
                        const int k0 = kf*16;
                        wmma::fragment<wmma::matrix_a,16,16,16,hf,wmma::row_major> af;
                        wmma::load_matrix_sync(af, sA + m0B*72 + k0, 72);
                        wmma::fragment<wmma::matrix_b,16,16,16,hf,wmma::col_major> bh, bl;
                        wmma::load_matrix_sync(bh, sWBh + kc*64 + k0, WKS);
                        wmma::load_matrix_sync(bl, sBl + k0, 72);
                        wmma::mma_sync(acc0, af, bh, acc0);
                        wmma::mma_sync(acc1, af, bl, acc1);
                    }
                }
            }
            __syncthreads();
            if (wid < 8) {
                #pragma unroll
                for (int e = 0; e < acc0.num_elements; e++)
                    acc0.x[e] += acc1.x[e];
                wmma::store_matrix_sync(cs + m0B*16, acc0, 16, wmma::mem_row_major);
            }
            __syncthreads();

            for (int i = tid; i < 128*16; i += SCANT) {
                int rr = i >> 4, cj = i & 15;
                int row = r0 + rr, c = c0B + cj;
                int idx = row*Hdim + c;
                float ht = tanhf(g_pre_h[((size_t)row*Tdim + t)*Hdim + c] + cs[i]);
                float hs = __ldcg(&g_hs[idx]);
                float zv = __ldcg(&g_z[idx]);
                float hn = (1.0f - zv)*hs + zv*ht;
                if (t == Tdim-1) g_h[idx] = hn;
                float gn = (t+1 < Tdim) ? g_gamma[((size_t)row*Tdim + (t+1))*Hdim + c] : 1.0f;
                float nh = gn*hn;
                g_hs[idx] = nh;
                g_hs_h[idx] = __float2half(nh);
            }
        }
        grid_sync();
    }
}

// ---------------- decoder ---------------------------------------------------
__global__ void k_dec(const float* __restrict__ dW, const float* __restrict__ db,
                      float* __restrict__ out)
{
    __shared__ float hrow[Hdim];
    int b = blockIdx.x;
    for (int i = threadIdx.x; i < Hdim; i += blockDim.x)
        hrow[i] = g_h[b*Hdim + i];
    __syncthreads();
    int o = threadIdx.x;
    float acc = db[o];
    #pragma unroll 8
    for (int k = 0; k < Hdim; k++)
        acc += hrow[k]*dW[k*Odim + o];
    out[b*Odim + o] = acc;
}

// ---------------- launch ----------------------------------------------------
extern "C" void kernel_launch(void* const* d_in, const int* in_sizes, int n_in,
                              void* d_out, int out_size)
{
    const float* x     = (const float*)d_in[0];
    const float* delta = (const float*)d_in[1];
    const float* m     = (const float*)d_in[2];
    const float* W_r   = (const float*)d_in[3];
    const float* U_r   = (const float*)d_in[4];
    const float* V_r   = (const float*)d_in[5];
    const float* b_r   = (const float*)d_in[6];
    const float* W_z   = (const float*)d_in[7];
    const float* U_z   = (const float*)d_in[8];
    const float* V_z   = (const float*)d_in[9];
    const float* b_z   = (const float*)d_in[10];
    const float* W     = (const float*)d_in[11];
    const float* U     = (const float*)d_in[12];
    const float* V     = (const float*)d_in[13];
    const float* b     = (const float*)d_in[14];
    const float* Wgx   = (const float*)d_in[15];
    const float* bgx   = (const float*)d_in[16];
    const float* Wgh   = (const float*)d_in[17];
    const float* bgh   = (const float*)d_in[18];
    const float* decW  = (const float*)d_in[19];
    const float* decb  = (const float*)d_in[20];
    float* out = (float*)d_out;

    static int smem_set = 0;
    if (!smem_set) {
        cudaFuncSetAttribute(k_scan, cudaFuncAttributeMaxDynamicSharedMemorySize, SCAN_SMEM);
        smem_set = 1;
    }

    // launch order: k_scan is launch #4 (ncu capture point)
    k_prep<<<SEG4/256, 256>>>(x, delta, m, Wgx, bgx,
                              W_z, V_z, W_r, V_r, W, V, Wgh, U_z, U_r, U);
    k_pre<<<dim3(Hdim/64, BT/64, 4), 128>>>(b_z, b_r, b, bgh);
    k_init<<<(Bdim*Hdim + 255)/256, 256>>>();
    k_scan<<<NBLK, SCANT, SCAN_SMEM>>>();
    k_dec<<<Bdim, Odim>>>(decW, decb, out);
}

// round 12
// speedup vs baseline: 6.2940x; 1.0743x over previous
#include <cuda_runtime.h>
#include <cuda_bf16.h>
#include <cuda_fp16.h>
#include <mma.h>
#include <math.h>
#include <stdint.h>

using namespace nvcuda;
typedef __nv_bfloat16 bf16;
typedef __half hf;

#define Bdim 256
#define Tdim 256
#define Ddim 128
#define Hdim 1024
#define Odim 64
#define BT (Bdim*Tdim)
#define DK (Ddim*Hdim)
#define NBLK 128
#define SCANT 512

// ---------------- scratch (device globals; allocations forbidden) ----------
// pre_* and gamma are BT-MAJOR: index = ((b*Tdim + t)*Hdim + h)
__device__ float g_pre_z[67108864];
__device__ float g_pre_r[67108864];
__device__ float g_pre_h[67108864];
__device__ float g_gamma[67108864];
__device__ float g_hs[Bdim*Hdim];
__device__ float g_h [Bdim*Hdim];
__device__ float g_z [Bdim*Hdim];

// scan operands: fp16 single-precision-level
__device__ hf g_hs_h[Bdim*Hdim];
__device__ hf g_rh_h[Bdim*Hdim];

// k_pre operands stay bf16 3-product
__device__ bf16 g_x_hi[BT*Ddim],   g_x_lo[BT*Ddim];
__device__ bf16 g_mb [BT*Ddim];
__device__ bf16 g_mib[BT*Ddim];
__device__ bf16 g_Wsm_hi[7*DK], g_Wsm_lo[7*DK];

// transposed scan weights: [n][k], k stride 1024 — fp16 single
__device__ hf g_UzrT[2048*1024];
__device__ hf g_UT[1024*1024];

__device__ unsigned g_bar_cnt = 0;
__device__ unsigned g_bar_gen = 0;

__device__ __forceinline__ void split2(float v, bf16& hi, bf16& lo) {
    hi = __float2bfloat16(v);
    lo = __float2bfloat16(v - __bfloat162float(hi));
}

__device__ __forceinline__ void grid_sync() {
    __threadfence();
    __syncthreads();
    if (threadIdx.x == 0) {
        unsigned my = atomicAdd(&g_bar_gen, 0u);
        if (atomicAdd(&g_bar_cnt, 1u) == NBLK - 1u) {
            atomicExch(&g_bar_cnt, 0u);
            atomicAdd(&g_bar_gen, 1u);
        } else {
            while (atomicAdd(&g_bar_gen, 0u) == my) { }
        }
    }
    __syncthreads();
}

// ---------------- fused prep: xmod + all weight splits ----------------------
#define SEG1 8388608u
#define SEG2 (SEG1 + 917504u)
#define SEG3 (SEG2 + 2097152u)
#define SEG4 (SEG3 + 1048576u)
__global__ void k_prep(const float* __restrict__ x, const float* __restrict__ delta,
                       const float* __restrict__ m, const float* __restrict__ wgx,
                       const float* __restrict__ bgx,
                       const float* __restrict__ Wz, const float* __restrict__ Vz,
                       const float* __restrict__ Wr, const float* __restrict__ Vr,
                       const float* __restrict__ Wh, const float* __restrict__ Vh,
                       const float* __restrict__ Wg,
                       const float* __restrict__ Uz, const float* __restrict__ Ur,
                       const float* __restrict__ U)
{
    unsigned i = blockIdx.x*256u + threadIdx.x;
    if (i < SEG1) {
        int d = i & (Ddim-1);
        float mv = m[i];
        float dec = delta[i]*wgx[d] + bgx[d];
        float xv = (mv > 0.0f) ? (1.0f - dec)*0.001f : x[i];
        split2(xv, g_x_hi[i], g_x_lo[i]);
        g_mb[i]  = __float2bfloat16(mv);
        g_mib[i] = __float2bfloat16(1.0f - mv);
    } else if (i < SEG2) {
        unsigned j2 = i - SEG1;
        int slot = j2 >> 17;
        int j = j2 & (DK-1);
        const float* src = (slot==0)?Wz:(slot==1)?Vz:(slot==2)?Wr:(slot==3)?Vr:(slot==4)?Wh:(slot==5)?Vh:Wg;
        split2(src[j], g_Wsm_hi[j2], g_Wsm_lo[j2]);
    } else if (i < SEG3) {
        unsigned j2 = i - SEG2;
        int n = j2 >> 10, k = j2 & 1023;
        float v = (n < 1024) ? Uz[k*1024 + n] : Ur[k*1024 + (n-1024)];
        g_UzrT[j2] = __float2half(v);
    } else {
        unsigned j2 = i - SEG3;
        int n = j2 >> 10, k = j2 & 1023;
        g_UT[j2] = __float2half(U[k*1024 + n]);
    }
}

__global__ void k_init() {
    int i = blockIdx.x*blockDim.x + threadIdx.x;
    if (i < Bdim*Hdim) {
        g_hs[i] = 0.0f; g_h[i] = 0.0f;
        g_hs_h[i] = __float2half(0.0f);
    }
    if (i == 0) { g_bar_cnt = 0; g_bar_gen = 0; }
}

// ============ precompute GEMMs (unchanged, bf16 3-product) ==================
__global__ void __launch_bounds__(128) k_pre(const float* __restrict__ pbz,
                                             const float* __restrict__ pbr,
                                             const float* __restrict__ pbh,
                                             const float* __restrict__ pbg)
{
    __shared__ __align__(16) char smem_raw[33792];
    bf16* sA0 = (bf16*)smem_raw;
    bf16* sA1 = sA0 + 64*40;
    bf16* sA2 = sA1 + 64*40;
    bf16* sB0 = sA2 + 64*40;
    bf16* sB1 = sB0 + 32*72;
    bf16* sB2 = sB1 + 32*72;
    bf16* sB3 = sB2 + 32*72;
    float* cs = (float*)smem_raw;

    const int which = blockIdx.z;
    const bool dual = (which < 3);
    const int tid = threadIdx.x;
    const int wid = tid >> 5;
    const int wr = wid >> 1, wc = wid & 1;
    const int r0 = blockIdx.y*64, c0 = blockIdx.x*64;

    const bf16 *Wh_p, *Wl_p, *Vh_p = nullptr, *Vl_p = nullptr;
    if (dual) {
        Wh_p = g_Wsm_hi + (size_t)(which*2)*DK;   Wl_p = g_Wsm_lo + (size_t)(which*2)*DK;
        Vh_p = g_Wsm_hi + (size_t)(which*2+1)*DK; Vl_p = g_Wsm_lo + (size_t)(which*2+1)*DK;
    } else {
        Wh_p = g_Wsm_hi + (size_t)6*DK;           Wl_p = g_Wsm_lo + (size_t)6*DK;
    }

    wmma::fragment<wmma::accumulator,16,16,16,float> acc[2][2];
    #pragma unroll
    for (int r=0;r<2;r++)
        #pragma unroll
        for (int c=0;c<2;c++) wmma::fill_fragment(acc[r][c], 0.0f);

    int aRow[2], aOff[2], bRow[2], bOff[2];
    #pragma unroll
    for (int j=0;j<2;j++) {
        int li = tid + 128*j;
        aRow[j] = li >> 2; aOff[j] = (li & 3)*8;
        bRow[j] = li >> 3; bOff[j] = (li & 7)*8;
    }

    for (int kk = 0; kk < Ddim; kk += 32) {
        __syncthreads();
        #pragma unroll
        for (int j=0;j<2;j++) {
            size_t ga = (size_t)(r0 + aRow[j])*Ddim + kk + aOff[j];
            size_t gb = (size_t)(kk + bRow[j])*Hdim + c0 + bOff[j];
            if (dual) {
                *(uint4*)(sA0 + aRow[j]*40 + aOff[j]) = *(const uint4*)(g_x_hi + ga);
                *(uint4*)(sA1 + aRow[j]*40 + aOff[j]) = *(const uint4*)(g_x_lo + ga);
                *(uint4*)(sA2 + aRow[j]*40 + aOff[j]) = *(const uint4*)(g_mib + ga);
                *(uint4*)(sB2 + bRow[j]*72 + bOff[j]) = *(const uint4*)(Vh_p + gb);
                *(uint4*)(sB3 + bRow[j]*72 + bOff[j]) = *(const uint4*)(Vl_p + gb);
            } else {
                *(uint4*)(sA0 + aRow[j]*40 + aOff[j]) = *(const uint4*)(g_mb + ga);
            }
            *(uint4*)(sB0 + bRow[j]*72 + bOff[j]) = *(const uint4*)(Wh_p + gb);
            *(uint4*)(sB1 + bRow[j]*72 + bOff[j]) = *(const uint4*)(Wl_p + gb);
        }
        __syncthreads();
        #pragma unroll
        for (int ks=0; ks<32; ks+=16) {
            wmma::fragment<wmma::matrix_a,16,16,16,bf16,wmma::row_major> a0[2], a1[2], a2[2];
            wmma::fragment<wmma::matrix_b,16,16,16,bf16,wmma::row_major> b0[2], b1[2], b2[2], b3[2];
            #pragma unroll
            for (int r=0;r<2;r++) {
                wmma::load_matrix_sync(a0[r], sA0 + (wr*32+r*16)*40 + ks, 40);
                if (dual) {
                    wmma::load_matrix_sync(a1[r], sA1 + (wr*32+r*16)*40 + ks, 40);
                    wmma::load_matrix_sync(a2[r], sA2 + (wr*32+r*16)*40 + ks, 40);
                }
            }
            #pragma unroll
            for (int c=0;c<2;c++) {
                wmma::load_matrix_sync(b0[c], sB0 + ks*72 + wc*32 + c*16, 72);
                wmma::load_matrix_sync(b1[c], sB1 + ks*72 + wc*32 + c*16, 72);
                if (dual) {
                    wmma::load_matrix_sync(b2[c], sB2 + ks*72 + wc*32 + c*16, 72);
                    wmma::load_matrix_sync(b3[c], sB3 + ks*72 + wc*32 + c*16, 72);
                }
            }
            #pragma unroll
            for (int r=0;r<2;r++)
                #pragma unroll
                for (int c=0;c<2;c++) {
                    wmma::mma_sync(acc[r][c], a0[r], b0[c], acc[r][c]);
                    wmma::mma_sync(acc[r][c], a0[r], b1[c], acc[r][c]);
                    if (dual) {
                        wmma::mma_sync(acc[r][c], a1[r], b0[c], acc[r][c]);
                        wmma::mma_sync(acc[r][c], a2[r], b2[c], acc[r][c]);
                        wmma::mma_sync(acc[r][c], a2[r], b3[c], acc[r][c]);
                    }
                }
        }
    }
    __syncthreads();
    #pragma unroll
    for (int r=0;r<2;r++)
        #pragma unroll
        for (int c=0;c<2;c++)
            wmma::store_matrix_sync(cs + (wr*32+r*16)*64 + wc*32 + c*16, acc[r][c], 64, wmma::mem_row_major);
    __syncthreads();

    const float* bias = (which==0)?pbz : (which==1)?pbr : (which==2)?pbh : pbg;
    float* out = (which==0)?g_pre_z : (which==1)?g_pre_r : (which==2)?g_pre_h : g_gamma;
    for (int i = tid; i < 64*64; i += 128) {
        int rr = i >> 6, cj = i & 63;
        float v = cs[i] + bias[c0 + cj];
        if (which == 3) v = expf(-fmaxf(0.0f, v));
        out[(size_t)(r0+rr)*Hdim + c0 + cj] = v;
    }
}

// ============ persistent fp16 scan — 512 threads, single product ============
#define WKS 1032
#define OFF_WA  0
#define OFF_WB  66048
#define OFF_SA  99072
#define SCAN_SMEM 117504

extern "C" __global__ void __launch_bounds__(SCANT, 1) k_scan()
{
    extern __shared__ __align__(16) char sm[];
    hf* sWA = (hf*)(sm + OFF_WA);
    hf* sWB = (hf*)(sm + OFF_WB);
    hf* sA  = (hf*)(sm + OFF_SA);
    float* cs = (float*)(sm + OFF_SA);

    const int tid = threadIdx.x;
    const int wid = tid >> 5;
    const int blk = blockIdx.x;
    const int mi = blk >> 6, nj = blk & 63;
    const int r0 = mi * 128;
    const int c0A = nj * 32;
    const int c0B = nj * 16;
    const bool isz = (nj < 32);

    // resident weights
    for (int i = tid; i < 4096; i += SCANT) {
        int n = i >> 7, k8 = (i & 127) * 8;
        *(uint4*)(sWA + n*WKS + k8) = *(const uint4*)(g_UzrT + (size_t)(c0A + n)*1024 + k8);
    }
    for (int i = tid; i < 2048; i += SCANT) {
        int n = i >> 7, k8 = (i & 127) * 8;
        *(uint4*)(sWB + n*WKS + k8) = *(const uint4*)(g_UT + (size_t)(c0B + n)*1024 + k8);
    }
    __syncthreads();

    int aRow[2], aOff[2];
    #pragma unroll
    for (int v = 0; v < 2; v++) {
        int li = tid + SCANT*v;
        aRow[v] = li >> 3; aOff[v] = (li & 7)*8;
    }

    const int m0A = (wid >> 1) * 16;
    const int nfA = wid & 1;
    const int m0B = (wid & 7) * 16;

    wmma::fragment<wmma::accumulator,16,16,16,float> acc0;

    for (int t = 0; t < Tdim; t++) {
        // ================= phase A: hs @ [Uz|Ur] slice =================
        {
            uint4 pa[2];
            #pragma unroll
            for (int v = 0; v < 2; v++)
                pa[v] = __ldcg((const uint4*)(g_hs_h + (size_t)(r0 + aRow[v])*1024 + aOff[v]));
            wmma::fill_fragment(acc0, 0.0f);

            for (int kc = 0; kc < 16; kc++) {
                __syncthreads();
                #pragma unroll
                for (int v = 0; v < 2; v++)
                    *(uint4*)(sA + aRow[v]*72 + aOff[v]) = pa[v];
                __syncthreads();
                if (kc < 15) {
                    #pragma unroll
                    for (int v = 0; v < 2; v++)
                        pa[v] = __ldcg((const uint4*)(g_hs_h + (size_t)(r0 + aRow[v])*1024 + (kc+1)*64 + aOff[v]));
                }
                #pragma unroll
                for (int kf = 0; kf < 4; kf++) {
                    const int k0 = kf*16;
                    wmma::fragment<wmma::matrix_a,16,16,16,hf,wmma::row_major> af;
                    wmma::load_matrix_sync(af, sA + m0A*72 + k0, 72);
                    wmma::fragment<wmma::matrix_b,16,16,16,hf,wmma::col_major> bf;
                    wmma::load_matrix_sync(bf, sWA + (nfA*16)*WKS + kc*64 + k0, WKS);
                    wmma::mma_sync(acc0, af, bf, acc0);
                }
            }
            __syncthreads();
            wmma::store_matrix_sync(cs + m0A*32 + nfA*16, acc0, 32, wmma::mem_row_major);
            __syncthreads();

            if (isz) {
                for (int i = tid; i < 128*32; i += SCANT) {
                    int rr = i >> 5, cj = i & 31;
                    int row = r0 + rr, c = c0A + cj;
                    float v = g_pre_z[((size_t)row*Tdim + t)*Hdim + c] + cs[i];
                    g_z[row*Hdim + c] = 1.0f/(1.0f + expf(-v));
                }
            } else {
                for (int i = tid; i < 128*32; i += SCANT) {
                    int rr = i >> 5, cj = i & 31;
                    int row = r0 + rr, c = c0A - 1024 + cj;
                    float v = g_pre_r[((size_t)row*Tdim + t)*Hdim + c] + cs[i];
                    float s = 1.0f/(1.0f + expf(-v));
                    int idx = row*Hdim + c;
                    float rh = s * __ldcg(&g_hs[idx]);
                    g_rh_h[idx] = __float2half(rh);
                }
            }
        }
        grid_sync();

        // ================= phase B: rh @ U slice + state update =========
        {
            uint4 pa[2];
            #pragma unroll
            for (int v = 0; v < 2; v++)
                pa[v] = __ldcg((const uint4*)(g_rh_h + (size_t)(r0 + aRow[v])*1024 + aOff[v]));
            wmma::fill_fragment(acc0, 0.0f);

            for (int kc = 0; kc < 16; kc++) {
                __syncthreads();
                #pragma unroll
                for (int v = 0; v < 2; v++)
                    *(uint4*)(sA + aRow[v]*72 + aOff[v]) = pa[v];
                __syncthreads();
                if (kc < 15) {
                    #pragma unroll
                    for (int v = 0; v < 2; v++)
                        pa[v] = __ldcg((const uint4*)(g_rh_h + (size_t)(r0 + aRow[v])*1024 + (kc+1)*64 + aOff[v]));
                }
                if (wid < 8) {
                    #pragma unroll
                    for (int kf = 0; kf < 4; kf++) {
                        const int k0 = kf*16;
                        wmma::fragment<wmma::matrix_a,16,16,16,hf,wmma::row_major> af;
                        wmma::load_matrix_sync(af, sA + m0B*72 + k0, 72);
                        wmma::fragment<wmma::matrix_b,16,16,16,hf,wmma::col_major> bf;
                        wmma::load_matrix_sync(bf, sWB + kc*64 + k0, WKS);
                        wmma::mma_sync(acc0, af, bf, acc0);
                    }
                }
            }
            __syncthreads();
            if (wid < 8)
                wmma::store_matrix_sync(cs + m0B*16, acc0, 16, wmma::mem_row_major);
            __syncthreads();

            for (int i = tid; i < 128*16; i += SCANT) {
                int rr = i >> 4, cj = i & 15;
                int row = r0 + rr, c = c0B + cj;
                int idx = row*Hdim + c;
                float ht = tanhf(g_pre_h[((size_t)row*Tdim + t)*Hdim + c] + cs[i]);
                float hs = __ldcg(&g_hs[idx]);
                float zv = __ldcg(&g_z[idx]);
                float hn = (1.0f - zv)*hs + zv*ht;
                if (t == Tdim-1) g_h[idx] = hn;
                float gn = (t+1 < Tdim) ? g_gamma[((size_t)row*Tdim + (t+1))*Hdim + c] : 1.0f;
                float nh = gn*hn;
                g_hs[idx] = nh;
                g_hs_h[idx] = __float2half(nh);
            }
        }
        grid_sync();
    }
}

// ---------------- decoder ---------------------------------------------------
__global__ void k_dec(const float* __restrict__ dW, const float* __restrict__ db,
                      float* __restrict__ out)
{
    __shared__ float hrow[Hdim];
    int b = blockIdx.x;
    for (int i = threadIdx.x; i < Hdim; i += blockDim.x)
        hrow[i] = g_h[b*Hdim + i];
    __syncthreads();
    int o = threadIdx.x;
    float acc = db[o];
    #pragma unroll 8
    for (int k = 0; k < Hdim; k++)
        acc += hrow[k]*dW[k*Odim + o];
    out[b*Odim + o] = acc;
}

// ---------------- launch ----------------------------------------------------
extern "C" void kernel_launch(void* const* d_in, const int* in_sizes, int n_in,
                              void* d_out, int out_size)
{
    const float* x     = (const float*)d_in[0];
    const float* delta = (const float*)d_in[1];
    const float* m     = (const float*)d_in[2];
    const float* W_r   = (const float*)d_in[3];
    const float* U_r   = (const float*)d_in[4];
    const float* V_r   = (const float*)d_in[5];
    const float* b_r   = (const float*)d_in[6];
    const float* W_z   = (const float*)d_in[7];
    const float* U_z   = (const float*)d_in[8];
    const float* V_z   = (const float*)d_in[9];
    const float* b_z   = (const float*)d_in[10];
    const float* W     = (const float*)d_in[11];
    const float* U     = (const float*)d_in[12];
    const float* V     = (const float*)d_in[13];
    const float* b     = (const float*)d_in[14];
    const float* Wgx   = (const float*)d_in[15];
    const float* bgx   = (const float*)d_in[16];
    const float* Wgh   = (const float*)d_in[17];
    const float* bgh   = (const float*)d_in[18];
    const float* decW  = (const float*)d_in[19];
    const float* decb  = (const float*)d_in[20];
    float* out = (float*)d_out;

    static int smem_set = 0;
    if (!smem_set) {
        cudaFuncSetAttribute(k_scan, cudaFuncAttributeMaxDynamicSharedMemorySize, SCAN_SMEM);
        smem_set = 1;
    }

    // launch order: k_scan is launch #4 (ncu capture point)
    k_prep<<<SEG4/256, 256>>>(x, delta, m, Wgx, bgx,
                              W_z, V_z, W_r, V_r, W, V, Wgh, U_z, U_r, U);
    k_pre<<<dim3(Hdim/64, BT/64, 4), 128>>>(b_z, b_r, b, bgh);
    k_init<<<(Bdim*Hdim + 255)/256, 256>>>();
    k_scan<<<NBLK, SCANT, SCAN_SMEM>>>();
    k_dec<<<Bdim, Odim>>>(decW, decb, out);
}

// round 13
// speedup vs baseline: 6.7082x; 1.0658x over previous
#include <cuda_runtime.h>
#include <cuda_bf16.h>
#include <cuda_fp16.h>
#include <mma.h>
#include <math.h>
#include <stdint.h>

using namespace nvcuda;
typedef __nv_bfloat16 bf16;
typedef __half hf;

#define Bdim 256
#define Tdim 256
#define Ddim 128
#define Hdim 1024
#define Odim 64
#define BT (Bdim*Tdim)
#define DK (Ddim*Hdim)
#define NBLK 128
#define SCANT 512

// ---------------- scratch (device globals; allocations forbidden) ----------
// pre_* and gamma are T-MAJOR: index = ((t*Bdim + b)*Hdim + h)
__device__ float g_pre_z[67108864];
__device__ float g_pre_r[67108864];
__device__ float g_pre_h[67108864];
__device__ float g_gamma[67108864];
__device__ float g_hs[Bdim*Hdim];
__device__ float g_h [Bdim*Hdim];
__device__ float g_z [Bdim*Hdim];

// scan operands: fp16 single-precision-level
__device__ hf g_hs_h[Bdim*Hdim];
__device__ hf g_rh_h[Bdim*Hdim];

// k_pre operands stay bf16 3-product
__device__ bf16 g_x_hi[BT*Ddim],   g_x_lo[BT*Ddim];
__device__ bf16 g_mb [BT*Ddim];
__device__ bf16 g_mib[BT*Ddim];
__device__ bf16 g_Wsm_hi[7*DK], g_Wsm_lo[7*DK];

// transposed scan weights: [n][k], k stride 1024 — fp16 single
__device__ hf g_UzrT[2048*1024];
__device__ hf g_UT[1024*1024];

__device__ unsigned g_bar_cnt = 0;
__device__ unsigned g_bar_gen = 0;

__device__ __forceinline__ void split2(float v, bf16& hi, bf16& lo) {
    hi = __float2bfloat16(v);
    lo = __float2bfloat16(v - __bfloat162float(hi));
}

__device__ __forceinline__ void grid_sync() {
    __threadfence();
    __syncthreads();
    if (threadIdx.x == 0) {
        unsigned my = atomicAdd(&g_bar_gen, 0u);
        if (atomicAdd(&g_bar_cnt, 1u) == NBLK - 1u) {
            atomicExch(&g_bar_cnt, 0u);
            atomicAdd(&g_bar_gen, 1u);
        } else {
            while (atomicAdd(&g_bar_gen, 0u) == my) { }
        }
    }
    __syncthreads();
}

// ---------------- fused prep: xmod + all weight splits ----------------------
#define SEG1 8388608u
#define SEG2 (SEG1 + 917504u)
#define SEG3 (SEG2 + 2097152u)
#define SEG4 (SEG3 + 1048576u)
__global__ void k_prep(const float* __restrict__ x, const float* __restrict__ delta,
                       const float* __restrict__ m, const float* __restrict__ wgx,
                       const float* __restrict__ bgx,
                       const float* __restrict__ Wz, const float* __restrict__ Vz,
                       const float* __restrict__ Wr, const float* __restrict__ Vr,
                       const float* __restrict__ Wh, const float* __restrict__ Vh,
                       const float* __restrict__ Wg,
                       const float* __restrict__ Uz, const float* __restrict__ Ur,
                       const float* __restrict__ U)
{
    unsigned i = blockIdx.x*256u + threadIdx.x;
    if (i < SEG1) {
        int d = i & (Ddim-1);
        float mv = m[i];
        float dec = delta[i]*wgx[d] + bgx[d];
        float xv = (mv > 0.0f) ? (1.0f - dec)*0.001f : x[i];
        split2(xv, g_x_hi[i], g_x_lo[i]);
        g_mb[i]  = __float2bfloat16(mv);
        g_mib[i] = __float2bfloat16(1.0f - mv);
    } else if (i < SEG2) {
        unsigned j2 = i - SEG1;
        int slot = j2 >> 17;
        int j = j2 & (DK-1);
        const float* src = (slot==0)?Wz:(slot==1)?Vz:(slot==2)?Wr:(slot==3)?Vr:(slot==4)?Wh:(slot==5)?Vh:Wg;
        split2(src[j], g_Wsm_hi[j2], g_Wsm_lo[j2]);
    } else if (i < SEG3) {
        unsigned j2 = i - SEG2;
        int n = j2 >> 10, k = j2 & 1023;
        float v = (n < 1024) ? Uz[k*1024 + n] : Ur[k*1024 + (n-1024)];
        g_UzrT[j2] = __float2half(v);
    } else {
        unsigned j2 = i - SEG3;
        int n = j2 >> 10, k = j2 & 1023;
        g_UT[j2] = __float2half(U[k*1024 + n]);
    }
}

__global__ void k_init() {
    int i = blockIdx.x*blockDim.x + threadIdx.x;
    if (i < Bdim*Hdim) {
        g_hs[i] = 0.0f; g_h[i] = 0.0f;
        g_hs_h[i] = __float2half(0.0f);
    }
    if (i == 0) { g_bar_cnt = 0; g_bar_gen = 0; }
}

// ============ precompute GEMMs (bf16 3-product; t-major outputs) ============
__global__ void __launch_bounds__(128) k_pre(const float* __restrict__ pbz,
                                             const float* __restrict__ pbr,
                                             const float* __restrict__ pbh,
                                             const float* __restrict__ pbg)
{
    __shared__ __align__(16) char smem_raw[33792];
    bf16* sA0 = (bf16*)smem_raw;
    bf16* sA1 = sA0 + 64*40;
    bf16* sA2 = sA1 + 64*40;
    bf16* sB0 = sA2 + 64*40;
    bf16* sB1 = sB0 + 32*72;
    bf16* sB2 = sB1 + 32*72;
    bf16* sB3 = sB2 + 32*72;
    float* cs = (float*)smem_raw;

    const int which = blockIdx.z;
    const bool dual = (which < 3);
    const int tid = threadIdx.x;
    const int wid = tid >> 5;
    const int wr = wid >> 1, wc = wid & 1;
    const int r0 = blockIdx.y*64, c0 = blockIdx.x*64;

    const bf16 *Wh_p, *Wl_p, *Vh_p = nullptr, *Vl_p = nullptr;
    if (dual) {
        Wh_p = g_Wsm_hi + (size_t)(which*2)*DK;   Wl_p = g_Wsm_lo + (size_t)(which*2)*DK;
        Vh_p = g_Wsm_hi + (size_t)(which*2+1)*DK; Vl_p = g_Wsm_lo + (size_t)(which*2+1)*DK;
    } else {
        Wh_p = g_Wsm_hi + (size_t)6*DK;           Wl_p = g_Wsm_lo + (size_t)6*DK;
    }

    wmma::fragment<wmma::accumulator,16,16,16,float> acc[2][2];
    #pragma unroll
    for (int r=0;r<2;r++)
        #pragma unroll
        for (int c=0;c<2;c++) wmma::fill_fragment(acc[r][c], 0.0f);

    int aRow[2], aOff[2], bRow[2], bOff[2];
    #pragma unroll
    for (int j=0;j<2;j++) {
        int li = tid + 128*j;
        aRow[j] = li >> 2; aOff[j] = (li & 3)*8;
        bRow[j] = li >> 3; bOff[j] = (li & 7)*8;
    }

    for (int kk = 0; kk < Ddim; kk += 32) {
        __syncthreads();
        #pragma unroll
        for (int j=0;j<2;j++) {
            size_t ga = (size_t)(r0 + aRow[j])*Ddim + kk + aOff[j];
            size_t gb = (size_t)(kk + bRow[j])*Hdim + c0 + bOff[j];
            if (dual) {
                *(uint4*)(sA0 + aRow[j]*40 + aOff[j]) = *(const uint4*)(g_x_hi + ga);
                *(uint4*)(sA1 + aRow[j]*40 + aOff[j]) = *(const uint4*)(g_x_lo + ga);
                *(uint4*)(sA2 + aRow[j]*40 + aOff[j]) = *(const uint4*)(g_mib + ga);
                *(uint4*)(sB2 + bRow[j]*72 + bOff[j]) = *(const uint4*)(Vh_p + gb);
                *(uint4*)(sB3 + bRow[j]*72 + bOff[j]) = *(const uint4*)(Vl_p + gb);
            } else {
                *(uint4*)(sA0 + aRow[j]*40 + aOff[j]) = *(const uint4*)(g_mb + ga);
            }
            *(uint4*)(sB0 + bRow[j]*72 + bOff[j]) = *(const uint4*)(Wh_p + gb);
            *(uint4*)(sB1 + bRow[j]*72 + bOff[j]) = *(const uint4*)(Wl_p + gb);
        }
        __syncthreads();
        #pragma unroll
        for (int ks=0; ks<32; ks+=16) {
            wmma::fragment<wmma::matrix_a,16,16,16,bf16,wmma::row_major> a0[2], a1[2], a2[2];
            wmma::fragment<wmma::matrix_b,16,16,16,bf16,wmma::row_major> b0[2], b1[2], b2[2], b3[2];
            #pragma unroll
            for (int r=0;r<2;r++) {
                wmma::load_matrix_sync(a0[r], sA0 + (wr*32+r*16)*40 + ks, 40);
                if (dual) {
                    wmma::load_matrix_sync(a1[r], sA1 + (wr*32+r*16)*40 + ks, 40);
                    wmma::load_matrix_sync(a2[r], sA2 + (wr*32+r*16)*40 + ks, 40);
                }
            }
            #pragma unroll
            for (int c=0;c<2;c++) {
                wmma::load_matrix_sync(b0[c], sB0 + ks*72 + wc*32 + c*16, 72);
                wmma::load_matrix_sync(b1[c], sB1 + ks*72 + wc*32 + c*16, 72);
                if (dual) {
                    wmma::load_matrix_sync(b2[c], sB2 + ks*72 + wc*32 + c*16, 72);
                    wmma::load_matrix_sync(b3[c], sB3 + ks*72 + wc*32 + c*16, 72);
                }
            }
            #pragma unroll
            for (int r=0;r<2;r++)
                #pragma unroll
                for (int c=0;c<2;c++) {
                    wmma::mma_sync(acc[r][c], a0[r], b0[c], acc[r][c]);
                    wmma::mma_sync(acc[r][c], a0[r], b1[c], acc[r][c]);
                    if (dual) {
                        wmma::mma_sync(acc[r][c], a1[r], b0[c], acc[r][c]);
                        wmma::mma_sync(acc[r][c], a2[r], b2[c], acc[r][c]);
                        wmma::mma_sync(acc[r][c], a2[r], b3[c], acc[r][c]);
                    }
                }
        }
    }
    __syncthreads();
    #pragma unroll
    for (int r=0;r<2;r++)
        #pragma unroll
        for (int c=0;c<2;c++)
            wmma::store_matrix_sync(cs + (wr*32+r*16)*64 + wc*32 + c*16, acc[r][c], 64, wmma::mem_row_major);
    __syncthreads();

    const float* bias = (which==0)?pbz : (which==1)?pbr : (which==2)?pbh : pbg;
    float* out = (which==0)?g_pre_z : (which==1)?g_pre_r : (which==2)?g_pre_h : g_gamma;
    for (int i = tid; i < 64*64; i += 128) {
        int rr = i >> 6, cj = i & 63;
        float v = cs[i] + bias[c0 + cj];
        if (which == 3) v = expf(-fmaxf(0.0f, v));
        int row_bt = r0 + rr;
        int bb = row_bt >> 8;          // batch  (bt = b*256 + t)
        int tt = row_bt & 255;         // time
        out[((size_t)tt*Bdim + bb)*Hdim + c0 + cj] = v;   // t-major
    }
}

// ============ persistent fp16 scan — 512 threads, BK=128 ====================
#define WKS 1032
#define AKS 136
#define OFF_WA  0
#define OFF_WB  66048
#define OFF_SA  99072
#define SCAN_SMEM (99072 + 128*AKS*2)   /* 133888 */

extern "C" __global__ void __launch_bounds__(SCANT, 1) k_scan()
{
    extern __shared__ __align__(16) char sm[];
    hf* sWA = (hf*)(sm + OFF_WA);
    hf* sWB = (hf*)(sm + OFF_WB);
    hf* sA  = (hf*)(sm + OFF_SA);
    float* cs = (float*)(sm + OFF_SA);

    const int tid = threadIdx.x;
    const int wid = tid >> 5;
    const int blk = blockIdx.x;
    const int mi = blk >> 6, nj = blk & 63;
    const int r0 = mi * 128;
    const int c0A = nj * 32;
    const int c0B = nj * 16;
    const bool isz = (nj < 32);

    // resident weights
    for (int i = tid; i < 4096; i += SCANT) {
        int n = i >> 7, k8 = (i & 127) * 8;
        *(uint4*)(sWA + n*WKS + k8) = *(const uint4*)(g_UzrT + (size_t)(c0A + n)*1024 + k8);
    }
    for (int i = tid; i < 2048; i += SCANT) {
        int n = i >> 7, k8 = (i & 127) * 8;
        *(uint4*)(sWB + n*WKS + k8) = *(const uint4*)(g_UT + (size_t)(c0B + n)*1024 + k8);
    }
    __syncthreads();

    // A staging: 128 rows x 128 k (hf) = 2048 uint4; 4 per thread
    int aRow[4], aOff[4];
    #pragma unroll
    for (int v = 0; v < 4; v++) {
        int li = tid + SCANT*v;
        aRow[v] = li >> 4; aOff[v] = (li & 15)*8;
    }

    const int m0A = (wid >> 1) * 16;
    const int nfA = wid & 1;
    const int m0B = (wid & 7) * 16;

    wmma::fragment<wmma::accumulator,16,16,16,float> acc0;

    for (int t = 0; t < Tdim; t++) {
        // ================= phase A: hs @ [Uz|Ur] slice =================
        {
            uint4 pa[4];
            #pragma unroll
            for (int v = 0; v < 4; v++)
                pa[v] = __ldcg((const uint4*)(g_hs_h + (size_t)(r0 + aRow[v])*1024 + aOff[v]));
            wmma::fill_fragment(acc0, 0.0f);

            for (int kc = 0; kc < 8; kc++) {
                __syncthreads();
                #pragma unroll
                for (int v = 0; v < 4; v++)
                    *(uint4*)(sA + aRow[v]*AKS + aOff[v]) = pa[v];
                __syncthreads();
                if (kc < 7) {
                    #pragma unroll
                    for (int v = 0; v < 4; v++)
                        pa[v] = __ldcg((const uint4*)(g_hs_h + (size_t)(r0 + aRow[v])*1024 + (kc+1)*128 + aOff[v]));
                }
                #pragma unroll
                for (int kf = 0; kf < 8; kf++) {
                    const int k0 = kf*16;
                    wmma::fragment<wmma::matrix_a,16,16,16,hf,wmma::row_major> af;
                    wmma::load_matrix_sync(af, sA + m0A*AKS + k0, AKS);
                    wmma::fragment<wmma::matrix_b,16,16,16,hf,wmma::col_major> bf;
                    wmma::load_matrix_sync(bf, sWA + (nfA*16)*WKS + kc*128 + k0, WKS);
                    wmma::mma_sync(acc0, af, bf, acc0);
                }
            }
            __syncthreads();
            wmma::store_matrix_sync(cs + m0A*32 + nfA*16, acc0, 32, wmma::mem_row_major);
            __syncthreads();

            if (isz) {
                for (int i = tid; i < 128*32; i += SCANT) {
                    int rr = i >> 5, cj = i & 31;
                    int row = r0 + rr, c = c0A + cj;
                    float v = g_pre_z[((size_t)t*Bdim + row)*Hdim + c] + cs[i];
                    g_z[row*Hdim + c] = 1.0f/(1.0f + expf(-v));
                }
            } else {
                for (int i = tid; i < 128*32; i += SCANT) {
                    int rr = i >> 5, cj = i & 31;
                    int row = r0 + rr, c = c0A - 1024 + cj;
                    float v = g_pre_r[((size_t)t*Bdim + row)*Hdim + c] + cs[i];
                    float s = 1.0f/(1.0f + expf(-v));
                    int idx = row*Hdim + c;
                    float rh = s * __ldcg(&g_hs[idx]);
                    g_rh_h[idx] = __float2half(rh);
                }
            }
        }
        grid_sync();

        // ================= phase B: rh @ U slice + state update =========
        {
            uint4 pa[4];
            #pragma unroll
            for (int v = 0; v < 4; v++)
                pa[v] = __ldcg((const uint4*)(g_rh_h + (size_t)(r0 + aRow[v])*1024 + aOff[v]));
            wmma::fill_fragment(acc0, 0.0f);

            for (int kc = 0; kc < 8; kc++) {
                __syncthreads();
                #pragma unroll
                for (int v = 0; v < 4; v++)
                    *(uint4*)(sA + aRow[v]*AKS + aOff[v]) = pa[v];
                __syncthreads();
                if (kc < 7) {
                    #pragma unroll
                    for (int v = 0; v < 4; v++)
                        pa[v] = __ldcg((const uint4*)(g_rh_h + (size_t)(r0 + aRow[v])*1024 + (kc+1)*128 + aOff[v]));
                }
                if (wid < 8) {
                    #pragma unroll
                    for (int kf = 0; kf < 8; kf++) {
                        const int k0 = kf*16;
                        wmma::fragment<wmma::matrix_a,16,16,16,hf,wmma::row_major> af;
                        wmma::load_matrix_sync(af, sA + m0B*AKS + k0, AKS);
                        wmma::fragment<wmma::matrix_b,16,16,16,hf,wmma::col_major> bf;
                        wmma::load_matrix_sync(bf, sWB + kc*128 + k0, WKS);
                        wmma::mma_sync(acc0, af, bf, acc0);
                    }
                }
            }
            __syncthreads();
            if (wid < 8)
                wmma::store_matrix_sync(cs + m0B*16, acc0, 16, wmma::mem_row_major);
            __syncthreads();

            for (int i = tid; i < 128*16; i += SCANT) {
                int rr = i >> 4, cj = i & 15;
                int row = r0 + rr, c = c0B + cj;
                int idx = row*Hdim + c;
                float ht = tanhf(g_pre_h[((size_t)t*Bdim + row)*Hdim + c] + cs[i]);
                float hs = __ldcg(&g_hs[idx]);
                float zv = __ldcg(&g_z[idx]);
                float hn = (1.0f - zv)*hs + zv*ht;
                if (t == Tdim-1) g_h[idx] = hn;
                float gn = (t+1 < Tdim) ? g_gamma[((size_t)(t+1)*Bdim + row)*Hdim + c] : 1.0f;
                float nh = gn*hn;
                g_hs[idx] = nh;
                g_hs_h[idx] = __float2half(nh);
            }
        }
        grid_sync();
    }
}

// ---------------- decoder ---------------------------------------------------
__global__ void k_dec(const float* __restrict__ dW, const float* __restrict__ db,
                      float* __restrict__ out)
{
    __shared__ float hrow[Hdim];
    int b = blockIdx.x;
    for (int i = threadIdx.x; i < Hdim; i += blockDim.x)
        hrow[i] = g_h[b*Hdim + i];
    __syncthreads();
    int o = threadIdx.x;
    float acc = db[o];
    #pragma unroll 8
    for (int k = 0; k < Hdim; k++)
        acc += hrow[k]*dW[k*Odim + o];
    out[b*Odim + o] = acc;
}

// ---------------- launch ----------------------------------------------------
extern "C" void kernel_launch(void* const* d_in, const int* in_sizes, int n_in,
                              void* d_out, int out_size)
{
    const float* x     = (const float*)d_in[0];
    const float* delta = (const float*)d_in[1];
    const float* m     = (const float*)d_in[2];
    const float* W_r   = (const float*)d_in[3];
    const float* U_r   = (const float*)d_in[4];
    const float* V_r   = (const float*)d_in[5];
    const float* b_r   = (const float*)d_in[6];
    const float* W_z   = (const float*)d_in[7];
    const float* U_z   = (const float*)d_in[8];
    const float* V_z   = (const float*)d_in[9];
    const float* b_z   = (const float*)d_in[10];
    const float* W     = (const float*)d_in[11];
    const float* U     = (const float*)d_in[12];
    const float* V     = (const float*)d_in[13];
    const float* b     = (const float*)d_in[14];
    const float* Wgx   = (const float*)d_in[15];
    const float* bgx   = (const float*)d_in[16];
    const float* Wgh   = (const float*)d_in[17];
    const float* bgh   = (const float*)d_in[18];
    const float* decW  = (const float*)d_in[19];
    const float* decb  = (const float*)d_in[20];
    float* out = (float*)d_out;

    static int smem_set = 0;
    if (!smem_set) {
        cudaFuncSetAttribute(k_scan, cudaFuncAttributeMaxDynamicSharedMemorySize, SCAN_SMEM);
        smem_set = 1;
    }

    // launch order: k_scan is launch #4 (ncu capture point)
    k_prep<<<SEG4/256, 256>>>(x, delta, m, Wgx, bgx,
                              W_z, V_z, W_r, V_r, W, V, Wgh, U_z, U_r, U);
    k_pre<<<dim3(Hdim/64, BT/64, 4), 128>>>(b_z, b_r, b, bgh);
    k_init<<<(Bdim*Hdim + 255)/256, 256>>>();
    k_scan<<<NBLK, SCANT, SCAN_SMEM>>>();
    k_dec<<<Bdim, Odim>>>(decW, decb, out);
}

// round 14
// speedup vs baseline: 6.9685x; 1.0388x over previous
#include <cuda_runtime.h>
#include <cuda_bf16.h>
#include <cuda_fp16.h>
#include <mma.h>
#include <math.h>
#include <stdint.h>

using namespace nvcuda;
typedef __nv_bfloat16 bf16;
typedef __half hf;

#define Bdim 256
#define Tdim 256
#define Ddim 128
#define Hdim 1024
#define Odim 64
#define BT (Bdim*Tdim)
#define DK (Ddim*Hdim)
#define NBLK 128
#define SCANT 512

// ---------------- scratch (device globals; allocations forbidden) ----------
// pre_* and gamma are T-MAJOR: index = ((t*Bdim + b)*Hdim + h)
__device__ float g_pre_z[67108864];
__device__ float g_pre_r[67108864];
__device__ float g_pre_h[67108864];
__device__ float g_gamma[67108864];
__device__ float g_hs[Bdim*Hdim];
__device__ float g_h [Bdim*Hdim];
__device__ float g_z [Bdim*Hdim];

// scan operands: fp16 single-precision-level
__device__ hf g_hs_h[Bdim*Hdim];
__device__ hf g_rh_h[Bdim*Hdim];

// k_pre operands stay bf16 3-product
__device__ bf16 g_x_hi[BT*Ddim],   g_x_lo[BT*Ddim];
__device__ bf16 g_mb [BT*Ddim];
__device__ bf16 g_mib[BT*Ddim];
__device__ bf16 g_Wsm_hi[7*DK], g_Wsm_lo[7*DK];

// transposed scan weights: [n][k], k stride 1024 — fp16 single
__device__ hf g_UzrT[2048*1024];
__device__ hf g_UT[1024*1024];

__device__ unsigned g_bar_cnt = 0;
__device__ unsigned g_bar_gen = 0;

__device__ __forceinline__ void split2(float v, bf16& hi, bf16& lo) {
    hi = __float2bfloat16(v);
    lo = __float2bfloat16(v - __bfloat162float(hi));
}

__device__ __forceinline__ void grid_sync() {
    __threadfence();
    __syncthreads();
    if (threadIdx.x == 0) {
        unsigned my = atomicAdd(&g_bar_gen, 0u);
        if (atomicAdd(&g_bar_cnt, 1u) == NBLK - 1u) {
            atomicExch(&g_bar_cnt, 0u);
            atomicAdd(&g_bar_gen, 1u);
        } else {
            while (atomicAdd(&g_bar_gen, 0u) == my) { }
        }
    }
    __syncthreads();
}

// ---------------- fused prep: xmod + all weight splits ----------------------
#define SEG1 8388608u
#define SEG2 (SEG1 + 917504u)
#define SEG3 (SEG2 + 2097152u)
#define SEG4 (SEG3 + 1048576u)
__global__ void k_prep(const float* __restrict__ x, const float* __restrict__ delta,
                       const float* __restrict__ m, const float* __restrict__ wgx,
                       const float* __restrict__ bgx,
                       const float* __restrict__ Wz, const float* __restrict__ Vz,
                       const float* __restrict__ Wr, const float* __restrict__ Vr,
                       const float* __restrict__ Wh, const float* __restrict__ Vh,
                       const float* __restrict__ Wg,
                       const float* __restrict__ Uz, const float* __restrict__ Ur,
                       const float* __restrict__ U)
{
    unsigned i = blockIdx.x*256u + threadIdx.x;
    if (i < SEG1) {
        int d = i & (Ddim-1);
        float mv = m[i];
        float dec = delta[i]*wgx[d] + bgx[d];
        float xv = (mv > 0.0f) ? (1.0f - dec)*0.001f : x[i];
        split2(xv, g_x_hi[i], g_x_lo[i]);
        g_mb[i]  = __float2bfloat16(mv);
        g_mib[i] = __float2bfloat16(1.0f - mv);
    } else if (i < SEG2) {
        unsigned j2 = i - SEG1;
        int slot = j2 >> 17;
        int j = j2 & (DK-1);
        const float* src = (slot==0)?Wz:(slot==1)?Vz:(slot==2)?Wr:(slot==3)?Vr:(slot==4)?Wh:(slot==5)?Vh:Wg;
        split2(src[j], g_Wsm_hi[j2], g_Wsm_lo[j2]);
    } else if (i < SEG3) {
        unsigned j2 = i - SEG2;
        int n = j2 >> 10, k = j2 & 1023;
        float v = (n < 1024) ? Uz[k*1024 + n] : Ur[k*1024 + (n-1024)];
        g_UzrT[j2] = __float2half(v);
    } else {
        unsigned j2 = i - SEG3;
        int n = j2 >> 10, k = j2 & 1023;
        g_UT[j2] = __float2half(U[k*1024 + n]);
    }
}

__global__ void k_init() {
    int i = blockIdx.x*blockDim.x + threadIdx.x;
    if (i < Bdim*Hdim) {
        g_hs[i] = 0.0f; g_h[i] = 0.0f;
        g_hs_h[i] = __float2half(0.0f);
    }
    if (i == 0) { g_bar_cnt = 0; g_bar_gen = 0; }
}

// ============ precompute GEMMs (bf16 3-product; t-major outputs) ============
__global__ void __launch_bounds__(128) k_pre(const float* __restrict__ pbz,
                                             const float* __restrict__ pbr,
                                             const float* __restrict__ pbh,
                                             const float* __restrict__ pbg)
{
    __shared__ __align__(16) char smem_raw[33792];
    bf16* sA0 = (bf16*)smem_raw;
    bf16* sA1 = sA0 + 64*40;
    bf16* sA2 = sA1 + 64*40;
    bf16* sB0 = sA2 + 64*40;
    bf16* sB1 = sB0 + 32*72;
    bf16* sB2 = sB1 + 32*72;
    bf16* sB3 = sB2 + 32*72;
    float* cs = (float*)smem_raw;

    const int which = blockIdx.z;
    const bool dual = (which < 3);
    const int tid = threadIdx.x;
    const int wid = tid >> 5;
    const int wr = wid >> 1, wc = wid & 1;
    const int r0 = blockIdx.y*64, c0 = blockIdx.x*64;

    const bf16 *Wh_p, *Wl_p, *Vh_p = nullptr, *Vl_p = nullptr;
    if (dual) {
        Wh_p = g_Wsm_hi + (size_t)(which*2)*DK;   Wl_p = g_Wsm_lo + (size_t)(which*2)*DK;
        Vh_p = g_Wsm_hi + (size_t)(which*2+1)*DK; Vl_p = g_Wsm_lo + (size_t)(which*2+1)*DK;
    } else {
        Wh_p = g_Wsm_hi + (size_t)6*DK;           Wl_p = g_Wsm_lo + (size_t)6*DK;
    }

    wmma::fragment<wmma::accumulator,16,16,16,float> acc[2][2];
    #pragma unroll
    for (int r=0;r<2;r++)
        #pragma unroll
        for (int c=0;c<2;c++) wmma::fill_fragment(acc[r][c], 0.0f);

    int aRow[2], aOff[2], bRow[2], bOff[2];
    #pragma unroll
    for (int j=0;j<2;j++) {
        int li = tid + 128*j;
        aRow[j] = li >> 2; aOff[j] = (li & 3)*8;
        bRow[j] = li >> 3; bOff[j] = (li & 7)*8;
    }

    for (int kk = 0; kk < Ddim; kk += 32) {
        __syncthreads();
        #pragma unroll
        for (int j=0;j<2;j++) {
            size_t ga = (size_t)(r0 + aRow[j])*Ddim + kk + aOff[j];
            size_t gb = (size_t)(kk + bRow[j])*Hdim + c0 + bOff[j];
            if (dual) {
                *(uint4*)(sA0 + aRow[j]*40 + aOff[j]) = *(const uint4*)(g_x_hi + ga);
                *(uint4*)(sA1 + aRow[j]*40 + aOff[j]) = *(const uint4*)(g_x_lo + ga);
                *(uint4*)(sA2 + aRow[j]*40 + aOff[j]) = *(const uint4*)(g_mib + ga);
                *(uint4*)(sB2 + bRow[j]*72 + bOff[j]) = *(const uint4*)(Vh_p + gb);
                *(uint4*)(sB3 + bRow[j]*72 + bOff[j]) = *(const uint4*)(Vl_p + gb);
            } else {
                *(uint4*)(sA0 + aRow[j]*40 + aOff[j]) = *(const uint4*)(g_mb + ga);
            }
            *(uint4*)(sB0 + bRow[j]*72 + bOff[j]) = *(const uint4*)(Wh_p + gb);
            *(uint4*)(sB1 + bRow[j]*72 + bOff[j]) = *(const uint4*)(Wl_p + gb);
        }
        __syncthreads();
        #pragma unroll
        for (int ks=0; ks<32; ks+=16) {
            wmma::fragment<wmma::matrix_a,16,16,16,bf16,wmma::row_major> a0[2], a1[2], a2[2];
            wmma::fragment<wmma::matrix_b,16,16,16,bf16,wmma::row_major> b0[2], b1[2], b2[2], b3[2];
            #pragma unroll
            for (int r=0;r<2;r++) {
                wmma::load_matrix_sync(a0[r], sA0 + (wr*32+r*16)*40 + ks, 40);
                if (dual) {
                    wmma::load_matrix_sync(a1[r], sA1 + (wr*32+r*16)*40 + ks, 40);
                    wmma::load_matrix_sync(a2[r], sA2 + (wr*32+r*16)*40 + ks, 40);
                }
            }
            #pragma unroll
            for (int c=0;c<2;c++) {
                wmma::load_matrix_sync(b0[c], sB0 + ks*72 + wc*32 + c*16, 72);
                wmma::load_matrix_sync(b1[c], sB1 + ks*72 + wc*32 + c*16, 72);
                if (dual) {
                    wmma::load_matrix_sync(b2[c], sB2 + ks*72 + wc*32 + c*16, 72);
                    wmma::load_matrix_sync(b3[c], sB3 + ks*72 + wc*32 + c*16, 72);
                }
            }
            #pragma unroll
            for (int r=0;r<2;r++)
                #pragma unroll
                for (int c=0;c<2;c++) {
                    wmma::mma_sync(acc[r][c], a0[r], b0[c], acc[r][c]);
                    wmma::mma_sync(acc[r][c], a0[r], b1[c], acc[r][c]);
                    if (dual) {
                        wmma::mma_sync(acc[r][c], a1[r], b0[c], acc[r][c]);
                        wmma::mma_sync(acc[r][c], a2[r], b2[c], acc[r][c]);
                        wmma::mma_sync(acc[r][c], a2[r], b3[c], acc[r][c]);
                    }
                }
        }
    }
    __syncthreads();
    #pragma unroll
    for (int r=0;r<2;r++)
        #pragma unroll
        for (int c=0;c<2;c++)
            wmma::store_matrix_sync(cs + (wr*32+r*16)*64 + wc*32 + c*16, acc[r][c], 64, wmma::mem_row_major);
    __syncthreads();

    const float* bias = (which==0)?pbz : (which==1)?pbr : (which==2)?pbh : pbg;
    float* out = (which==0)?g_pre_z : (which==1)?g_pre_r : (which==2)?g_pre_h : g_gamma;
    for (int i = tid; i < 64*64; i += 128) {
        int rr = i >> 6, cj = i & 63;
        float v = cs[i] + bias[c0 + cj];
        if (which == 3) v = expf(-fmaxf(0.0f, v));
        int row_bt = r0 + rr;
        int bb = row_bt >> 8;
        int tt = row_bt & 255;
        out[((size_t)tt*Bdim + bb)*Hdim + c0 + cj] = v;   // t-major
    }
}

// ============ persistent fp16 scan — 512 threads, BK=128, double-buffered ===
#define WKS 1032
#define AKS 136
#define OFF_WA  0
#define OFF_WB  66048
#define OFF_SA0 99072
#define OFF_SA1 (99072 + 128*AKS*2)          /* 133888 */
#define SCAN_SMEM (OFF_SA1 + 128*AKS*2)      /* 168704 */

extern "C" __global__ void __launch_bounds__(SCANT, 1) k_scan()
{
    extern __shared__ __align__(16) char sm[];
    hf* sWA = (hf*)(sm + OFF_WA);
    hf* sWB = (hf*)(sm + OFF_WB);
    hf* sAB[2] = { (hf*)(sm + OFF_SA0), (hf*)(sm + OFF_SA1) };
    float* cs = (float*)(sm + OFF_SA0);

    const int tid = threadIdx.x;
    const int wid = tid >> 5;
    const int blk = blockIdx.x;
    const int mi = blk >> 6, nj = blk & 63;
    const int r0 = mi * 128;
    const int c0A = nj * 32;
    const int c0B = nj * 16;
    const bool isz = (nj < 32);

    // resident weights
    for (int i = tid; i < 4096; i += SCANT) {
        int n = i >> 7, k8 = (i & 127) * 8;
        *(uint4*)(sWA + n*WKS + k8) = *(const uint4*)(g_UzrT + (size_t)(c0A + n)*1024 + k8);
    }
    for (int i = tid; i < 2048; i += SCANT) {
        int n = i >> 7, k8 = (i & 127) * 8;
        *(uint4*)(sWB + n*WKS + k8) = *(const uint4*)(g_UT + (size_t)(c0B + n)*1024 + k8);
    }
    __syncthreads();

    // A staging map: 128 rows x 128 k (hf) = 2048 uint4; 4 per thread
    int aRow[4], aOff[4];
    #pragma unroll
    for (int v = 0; v < 4; v++) {
        int li = tid + SCANT*v;
        aRow[v] = li >> 4; aOff[v] = (li & 15)*8;
    }

    const int m0A = (wid >> 1) * 16;
    const int nfA = wid & 1;
    const int m0B = (wid & 7) * 16;

    wmma::fragment<wmma::accumulator,16,16,16,float> acc0;

    for (int t = 0; t < Tdim; t++) {
        // ================= phase A: hs @ [Uz|Ur] slice =================
        {
            uint4 pa[4];
            #pragma unroll
            for (int v = 0; v < 4; v++)
                pa[v] = __ldcg((const uint4*)(g_hs_h + (size_t)(r0 + aRow[v])*1024 + aOff[v]));
            wmma::fill_fragment(acc0, 0.0f);
            #pragma unroll
            for (int v = 0; v < 4; v++)
                *(uint4*)(sAB[0] + aRow[v]*AKS + aOff[v]) = pa[v];
            __syncthreads();

            for (int kc = 0; kc < 8; kc++) {
                if (kc < 7) {
                    #pragma unroll
                    for (int v = 0; v < 4; v++)
                        pa[v] = __ldcg((const uint4*)(g_hs_h + (size_t)(r0 + aRow[v])*1024 + (kc+1)*128 + aOff[v]));
                }
                const hf* sA = sAB[kc & 1];
                #pragma unroll
                for (int kf = 0; kf < 8; kf++) {
                    const int k0 = kf*16;
                    wmma::fragment<wmma::matrix_a,16,16,16,hf,wmma::row_major> af;
                    wmma::load_matrix_sync(af, sA + m0A*AKS + k0, AKS);
                    wmma::fragment<wmma::matrix_b,16,16,16,hf,wmma::col_major> bf;
                    wmma::load_matrix_sync(bf, sWA + (nfA*16)*WKS + kc*128 + k0, WKS);
                    wmma::mma_sync(acc0, af, bf, acc0);
                }
                if (kc < 7) {
                    hf* sN = sAB[(kc + 1) & 1];
                    #pragma unroll
                    for (int v = 0; v < 4; v++)
                        *(uint4*)(sN + aRow[v]*AKS + aOff[v]) = pa[v];
                }
                __syncthreads();
            }
            wmma::store_matrix_sync(cs + m0A*32 + nfA*16, acc0, 32, wmma::mem_row_major);
            __syncthreads();

            if (isz) {
                for (int i = tid; i < 128*32; i += SCANT) {
                    int rr = i >> 5, cj = i & 31;
                    int row = r0 + rr, c = c0A + cj;
                    float v = g_pre_z[((size_t)t*Bdim + row)*Hdim + c] + cs[i];
                    g_z[row*Hdim + c] = 1.0f/(1.0f + expf(-v));
                }
            } else {
                for (int i = tid; i < 128*32; i += SCANT) {
                    int rr = i >> 5, cj = i & 31;
                    int row = r0 + rr, c = c0A - 1024 + cj;
                    float v = g_pre_r[((size_t)t*Bdim + row)*Hdim + c] + cs[i];
                    float s = 1.0f/(1.0f + expf(-v));
                    int idx = row*Hdim + c;
                    float rh = s * __ldcg(&g_hs[idx]);
                    g_rh_h[idx] = __float2half(rh);
                }
            }
        }
        grid_sync();

        // ================= phase B: rh @ U slice + state update =========
        {
            uint4 pa[4];
            #pragma unroll
            for (int v = 0; v < 4; v++)
                pa[v] = __ldcg((const uint4*)(g_rh_h + (size_t)(r0 + aRow[v])*1024 + aOff[v]));
            wmma::fill_fragment(acc0, 0.0f);
            #pragma unroll
            for (int v = 0; v < 4; v++)
                *(uint4*)(sAB[0] + aRow[v]*AKS + aOff[v]) = pa[v];
            __syncthreads();

            for (int kc = 0; kc < 8; kc++) {
                if (kc < 7) {
                    #pragma unroll
                    for (int v = 0; v < 4; v++)
                        pa[v] = __ldcg((const uint4*)(g_rh_h + (size_t)(r0 + aRow[v])*1024 + (kc+1)*128 + aOff[v]));
                }
                if (wid < 8) {
                    const hf* sA = sAB[kc & 1];
                    #pragma unroll
                    for (int kf = 0; kf < 8; kf++) {
                        const int k0 = kf*16;
                        wmma::fragment<wmma::matrix_a,16,16,16,hf,wmma::row_major> af;
                        wmma::load_matrix_sync(af, sA + m0B*AKS + k0, AKS);
                        wmma::fragment<wmma::matrix_b,16,16,16,hf,wmma::col_major> bf;
                        wmma::load_matrix_sync(bf, sWB + kc*128 + k0, WKS);
                        wmma::mma_sync(acc0, af, bf, acc0);
                    }
                }
                if (kc < 7) {
                    hf* sN = sAB[(kc + 1) & 1];
                    #pragma unroll
                    for (int v = 0; v < 4; v++)
                        *(uint4*)(sN + aRow[v]*AKS + aOff[v]) = pa[v];
                }
                __syncthreads();
            }
            if (wid < 8)
                wmma::store_matrix_sync(cs + m0B*16, acc0, 16, wmma::mem_row_major);
            __syncthreads();

            for (int i = tid; i < 128*16; i += SCANT) {
                int rr = i >> 4, cj = i & 15;
                int row = r0 + rr, c = c0B + cj;
                int idx = row*Hdim + c;
                float ht = tanhf(g_pre_h[((size_t)t*Bdim + row)*Hdim + c] + cs[i]);
                float hs = __ldcg(&g_hs[idx]);
                float zv = __ldcg(&g_z[idx]);
                float hn = (1.0f - zv)*hs + zv*ht;
                if (t == Tdim-1) g_h[idx] = hn;
                float gn = (t+1 < Tdim) ? g_gamma[((size_t)(t+1)*Bdim + row)*Hdim + c] : 1.0f;
                float nh = gn*hn;
                g_hs[idx] = nh;
                g_hs_h[idx] = __float2half(nh);
            }
        }
        grid_sync();
    }
}

// ---------------- decoder ---------------------------------------------------
__global__ void k_dec(const float* __restrict__ dW, const float* __restrict__ db,
                      float* __restrict__ out)
{
    __shared__ float hrow[Hdim];
    int b = blockIdx.x;
    for (int i = threadIdx.x; i < Hdim; i += blockDim.x)
        hrow[i] = g_h[b*Hdim + i];
    __syncthreads();
    int o = threadIdx.x;
    float acc = db[o];
    #pragma unroll 8
    for (int k = 0; k < Hdim; k++)
        acc += hrow[k]*dW[k*Odim + o];
    out[b*Odim + o] = acc;
}

// ---------------- launch ----------------------------------------------------
extern "C" void kernel_launch(void* const* d_in, const int* in_sizes, int n_in,
                              void* d_out, int out_size)
{
    const float* x     = (const float*)d_in[0];
    const float* delta = (const float*)d_in[1];
    const float* m     = (const float*)d_in[2];
    const float* W_r   = (const float*)d_in[3];
    const float* U_r   = (const float*)d_in[4];
    const float* V_r   = (const float*)d_in[5];
    const float* b_r   = (const float*)d_in[6];
    const float* W_z   = (const float*)d_in[7];
    const float* U_z   = (const float*)d_in[8];
    const float* V_z   = (const float*)d_in[9];
    const float* b_z   = (const float*)d_in[10];
    const float* W     = (const float*)d_in[11];
    const float* U     = (const float*)d_in[12];
    const float* V     = (const float*)d_in[13];
    const float* b     = (const float*)d_in[14];
    const float* Wgx   = (const float*)d_in[15];
    const float* bgx   = (const float*)d_in[16];
    const float* Wgh   = (const float*)d_in[17];
    const float* bgh   = (const float*)d_in[18];
    const float* decW  = (const float*)d_in[19];
    const float* decb  = (const float*)d_in[20];
    float* out = (float*)d_out;

    static int smem_set = 0;
    if (!smem_set) {
        cudaFuncSetAttribute(k_scan, cudaFuncAttributeMaxDynamicSharedMemorySize, SCAN_SMEM);
        smem_set = 1;
    }

    // launch order: k_scan is launch #4 (ncu capture point)
    k_prep<<<SEG4/256, 256>>>(x, delta, m, Wgx, bgx,
                              W_z, V_z, W_r, V_r, W, V, Wgh, U_z, U_r, U);
    k_pre<<<dim3(Hdim/64, BT/64, 4), 128>>>(b_z, b_r, b, bgh);
    k_init<<<(Bdim*Hdim + 255)/256, 256>>>();
    k_scan<<<NBLK, SCANT, SCAN_SMEM>>>();
    k_dec<<<Bdim, Odim>>>(decW, decb, out);
}